// round 2
// baseline (speedup 1.0000x reference)
#include <cuda_runtime.h>
#include <cuda_bf16.h>

#define S    2048
#define HID  2048
#define H    16
#define NOPE 128
#define ROPE 64
#define QD   192   // NOPE+ROPE
#define KVR  512
#define D    576   // KVR+ROPE
#define VH   128
#define SCALE 0.07216878364870323f  // (NOPE+ROPE)^-0.5
#define EPS  1e-6f

// ---------------- scratch (device globals; no allocations allowed) -----------
__device__ float g_q[(long long)S * H * QD];       // 25 MB   x @ w_q
__device__ float g_kv[(long long)S * D];           // 4.7 MB  x @ w_kv_a
__device__ float g_qfull[(long long)H * S * D];    // 75.5 MB per-head [S,576]
__device__ float g_kfull[(long long)S * D];        // 4.7 MB  [latent | roped k_pe]
__device__ float g_p[(long long)H * S * S];        // 256 MB  attention probs
__device__ float g_ao[(long long)H * S * KVR];     // 64 MB   attn @ latent
__device__ float g_ov[(long long)S * H * VH];      // 16 MB   [S, H*VH]

// ---------------- generic tiled SGEMM ---------------------------------------
// C[M,N] = alpha * A[M,K] @ (TRANSB ? B[N,K]^T : B[K,N]) ; all row-major.
// Requires: M % 128 == 0, N % 64 == 0, K % 16 == 0 (true for every call here).
// causal_mode: 0 = none
//              1 = skip blocks entirely above the diagonal (scores GEMM)
//              2 = truncate K loop at rowbase+BM (P rows are zero beyond s)
template<bool TRANSB>
__global__ void __launch_bounds__(256)
sgemm_kernel(const float* __restrict__ A, const float* __restrict__ B,
             float* __restrict__ C,
             int M, int N, int K, int lda, int ldb, int ldc,
             long long sA, long long sB, long long sC,
             float alpha, int causal_mode)
{
    const int BM = 128, BN = 64, BK = 16;
    __shared__ float As[BK][BM + 4];
    __shared__ float Bs[BK][BN + 4];

    const int rowbase = blockIdx.y * BM;
    const int colbase = blockIdx.x * BN;
    if (causal_mode == 1 && colbase >= rowbase + BM) return;  // fully masked tile
    int kmax = K;
    if (causal_mode == 2) kmax = min(K, rowbase + BM);

    A += blockIdx.z * sA;
    B += blockIdx.z * sB;
    C += blockIdx.z * sC;

    const int tid = threadIdx.x;
    const int ty = tid >> 4, tx = tid & 15;

    float acc[8][4];
#pragma unroll
    for (int i = 0; i < 8; i++)
#pragma unroll
        for (int j = 0; j < 4; j++) acc[i][j] = 0.f;

    for (int k0 = 0; k0 < kmax; k0 += BK) {
        // ---- load A tile (128 x 16), store transposed into As[k][m]
#pragma unroll
        for (int r = 0; r < 2; r++) {
            int idx = tid + r * 256;           // 512 float4 total
            int row = idx >> 2;
            int c4  = idx & 3;
            float4 v = *(const float4*)(A + (long long)(rowbase + row) * lda + k0 + c4 * 4);
            As[c4 * 4 + 0][row] = v.x;
            As[c4 * 4 + 1][row] = v.y;
            As[c4 * 4 + 2][row] = v.z;
            As[c4 * 4 + 3][row] = v.w;
        }
        // ---- load B tile (16 x 64) into Bs[k][n]
        if (!TRANSB) {
            int row = tid >> 4;                // 256 float4 total
            int c4  = tid & 15;
            float4 v = *(const float4*)(B + (long long)(k0 + row) * ldb + colbase + c4 * 4);
            *(float4*)&Bs[row][c4 * 4] = v;
        } else {
            int n  = tid >> 2;
            int c4 = tid & 3;
            float4 v = *(const float4*)(B + (long long)(colbase + n) * ldb + k0 + c4 * 4);
            Bs[c4 * 4 + 0][n] = v.x;
            Bs[c4 * 4 + 1][n] = v.y;
            Bs[c4 * 4 + 2][n] = v.z;
            Bs[c4 * 4 + 3][n] = v.w;
        }
        __syncthreads();

#pragma unroll
        for (int k = 0; k < BK; k++) {
            float a[8], b[4];
            *(float4*)&a[0] = *(const float4*)&As[k][ty * 8];
            *(float4*)&a[4] = *(const float4*)&As[k][ty * 8 + 4];
            *(float4*)&b[0] = *(const float4*)&Bs[k][tx * 4];
#pragma unroll
            for (int i = 0; i < 8; i++)
#pragma unroll
                for (int j = 0; j < 4; j++) acc[i][j] += a[i] * b[j];
        }
        __syncthreads();
    }

#pragma unroll
    for (int i = 0; i < 8; i++) {
        long long row = rowbase + ty * 8 + i;
        float4 v = make_float4(acc[i][0] * alpha, acc[i][1] * alpha,
                               acc[i][2] * alpha, acc[i][3] * alpha);
        *(float4*)(C + row * ldc + colbase + tx * 4) = v;
    }
}

// ---------------- rmsnorm(latent) + RoPE(k_pe, q_pe per head) ----------------
__global__ void __launch_bounds__(256)
prep_kernel(const float* __restrict__ cosp, const float* __restrict__ sinp,
            const float* __restrict__ normw)
{
    const int s = blockIdx.x;
    const int tid = threadIdx.x;
    const float* kv = g_kv + (long long)s * D;
    float* kf = g_kfull + (long long)s * D;

    // rms over latent (first 512)
    float ss = 0.f;
    for (int i = tid; i < KVR; i += 256) { float v = kv[i]; ss += v * v; }
    __shared__ float red[32];
#pragma unroll
    for (int o = 16; o > 0; o >>= 1) ss += __shfl_xor_sync(0xffffffffu, ss, o);
    if ((tid & 31) == 0) red[tid >> 5] = ss;
    __syncthreads();
    if (tid < 32) {
        float v = (tid < 8) ? red[tid] : 0.f;
#pragma unroll
        for (int o = 16; o > 0; o >>= 1) v += __shfl_xor_sync(0xffffffffu, v, o);
        if (tid == 0) red[0] = v;
    }
    __syncthreads();
    const float r = rsqrtf(red[0] / (float)KVR + EPS);

    for (int i = tid; i < KVR; i += 256) kf[i] = kv[i] * r * normw[i];

    const float* cs = cosp + (long long)s * ROPE;
    const float* sn = sinp + (long long)s * ROPE;

    // k_pe rope
    for (int i = tid; i < ROPE; i += 256) {
        float v = kv[KVR + i];
        float rot = (i < 32) ? -kv[KVR + i + 32] : kv[KVR + i - 32];
        kf[KVR + i] = v * cs[i] + rot * sn[i];
    }
    // q_pe rope, all heads
    for (int idx = tid; idx < H * ROPE; idx += 256) {
        int h = idx >> 6, i = idx & 63;
        const float* qp = g_q + (long long)s * (H * QD) + h * QD + NOPE;
        float v = qp[i];
        float rot = (i < 32) ? -qp[i + 32] : qp[i - 32];
        g_qfull[(long long)h * S * D + (long long)s * D + KVR + i] = v * cs[i] + rot * sn[i];
    }
}

// ---------------- causal row softmax ----------------------------------------
__global__ void __launch_bounds__(256)
softmax_kernel()
{
    const int s = blockIdx.x, h = blockIdx.y;
    float* row = g_p + ((long long)h * S + s) * S;
    __shared__ float sh[S];
    __shared__ float red[33];
    const int n = s + 1;
    const int tid = threadIdx.x;

    float mx = -3.0e38f;
    for (int t = tid; t < n; t += 256) { float v = row[t]; sh[t] = v; mx = fmaxf(mx, v); }
#pragma unroll
    for (int o = 16; o > 0; o >>= 1) mx = fmaxf(mx, __shfl_xor_sync(0xffffffffu, mx, o));
    if ((tid & 31) == 0) red[tid >> 5] = mx;
    __syncthreads();
    if (tid < 32) {
        float v = (tid < 8) ? red[tid] : -3.0e38f;
#pragma unroll
        for (int o = 16; o > 0; o >>= 1) v = fmaxf(v, __shfl_xor_sync(0xffffffffu, v, o));
        if (tid == 0) red[32] = v;
    }
    __syncthreads();
    mx = red[32];

    float sum = 0.f;
    for (int t = tid; t < n; t += 256) { float e = expf(sh[t] - mx); sh[t] = e; sum += e; }
#pragma unroll
    for (int o = 16; o > 0; o >>= 1) sum += __shfl_xor_sync(0xffffffffu, sum, o);
    if ((tid & 31) == 0) red[tid >> 5] = sum;
    __syncthreads();
    if (tid < 32) {
        float v = (tid < 8) ? red[tid] : 0.f;
#pragma unroll
        for (int o = 16; o > 0; o >>= 1) v += __shfl_xor_sync(0xffffffffu, v, o);
        if (tid == 0) red[32] = v;
    }
    __syncthreads();
    const float inv = 1.0f / red[32];

    for (int t = tid; t < n; t += 256) row[t] = sh[t] * inv;
    for (int t = n + tid; t < S; t += 256) row[t] = 0.f;   // zero masked region
}

// ---------------- launch ------------------------------------------------------
extern "C" void kernel_launch(void* const* d_in, const int* in_sizes, int n_in,
                              void* d_out, int out_size)
{
    (void)in_sizes; (void)n_in; (void)out_size;
    const float* x      = (const float*)d_in[0];
    const float* cosp   = (const float*)d_in[1];
    const float* sinp   = (const float*)d_in[2];
    const float* w_q    = (const float*)d_in[3];
    const float* w_kv_a = (const float*)d_in[4];
    const float* normw  = (const float*)d_in[5];
    const float* kc     = (const float*)d_in[6];
    const float* vc     = (const float*)d_in[7];
    const float* w_o    = (const float*)d_in[8];
    float* out = (float*)d_out;

    float *q, *kv, *qf, *kf, *p, *ao, *ov;
    cudaGetSymbolAddress((void**)&q,  g_q);
    cudaGetSymbolAddress((void**)&kv, g_kv);
    cudaGetSymbolAddress((void**)&qf, g_qfull);
    cudaGetSymbolAddress((void**)&kf, g_kfull);
    cudaGetSymbolAddress((void**)&p,  g_p);
    cudaGetSymbolAddress((void**)&ao, g_ao);
    cudaGetSymbolAddress((void**)&ov, g_ov);

    dim3 blk(256);

    // 1) q = x @ w_q   [2048 x 3072]
    sgemm_kernel<false><<<dim3(3072 / 64, S / 128, 1), blk>>>(
        x, w_q, q, S, H * QD, HID, HID, H * QD, H * QD, 0, 0, 0, 1.0f, 0);

    // 2) kv = x @ w_kv_a   [2048 x 576]
    sgemm_kernel<false><<<dim3(D / 64, S / 128, 1), blk>>>(
        x, w_kv_a, kv, S, D, HID, HID, D, D, 0, 0, 0, 1.0f, 0);

    // 3) rmsnorm + rope -> g_kfull, g_qfull[:, 512:576]
    prep_kernel<<<S, blk>>>(cosp, sinp, normw);

    // 4) q_nope @ kc  -> g_qfull[:, :512]  (batched over heads)
    sgemm_kernel<false><<<dim3(KVR / 64, S / 128, H), blk>>>(
        q, kc, qf, S, KVR, NOPE, H * QD, KVR, D,
        (long long)QD, (long long)NOPE * KVR, (long long)S * D, 1.0f, 0);

    // 5) scores = SCALE * q_full @ k_full^T  (causal block skip)
    sgemm_kernel<true><<<dim3(S / 64, S / 128, H), blk>>>(
        qf, kf, p, S, S, D, D, D, S,
        (long long)S * D, 0LL, (long long)S * S, SCALE, 1);

    // 6) causal softmax
    softmax_kernel<<<dim3(S, H), blk>>>();

    // 7) attn @ latent  (K-truncated at the diagonal)
    sgemm_kernel<false><<<dim3(KVR / 64, S / 128, H), blk>>>(
        p, kf, ao, S, KVR, S, S, D, KVR,
        (long long)S * S, 0LL, (long long)S * KVR, 1.0f, 2);

    // 8) out @ vc -> g_ov [S, H*VH]
    sgemm_kernel<false><<<dim3(VH / 64, S / 128, H), blk>>>(
        ao, vc, ov, S, VH, KVR, KVR, VH, H * VH,
        (long long)S * KVR, (long long)KVR * VH, (long long)VH, 1.0f, 0);

    // 9) final: g_ov @ w_o -> out
    sgemm_kernel<false><<<dim3(HID / 64, S / 128, 1), blk>>>(
        ov, w_o, out, S, HID, H * VH, H * VH, HID, HID, 0, 0, 0, 1.0f, 0);
}

// round 5
// speedup vs baseline: 1.9695x; 1.9695x over previous
#include <cuda_runtime.h>
#include <cuda_bf16.h>
#include <cstdint>
#include <cstring>

#define S    2048
#define HID  2048
#define H    16
#define NOPE 128
#define ROPE 64
#define QD   192   // NOPE+ROPE
#define KVR  512
#define D    576   // KVR+ROPE
#define VH   128
#define SCALE 0.07216878364870323f  // (NOPE+ROPE)^-0.5
#define EPS  1e-6f

// ---------------- scratch (device globals; no allocations allowed) -----------
__device__ float g_q[(long long)S * H * QD];
__device__ float g_kv[(long long)S * D];
__device__ float g_qfull[(long long)H * S * D];
__device__ float g_kfull[(long long)S * D];
__device__ float g_p[(long long)H * S * S];
__device__ float g_ao[(long long)H * S * KVR];
__device__ float g_ov[(long long)S * H * VH];
// transposed (K-major) B operands
__device__ float g_wqT[(long long)(H * QD) * HID];
__device__ float g_wkvaT[(long long)D * HID];
__device__ float g_kcT[(long long)H * KVR * NOPE];
__device__ float g_vcT[(long long)H * VH * KVR];
__device__ float g_woT[(long long)HID * (H * VH)];
__device__ float g_latT[(long long)KVR * S];

// ---------------- helpers -----------------------------------------------------
// pack two fp32 into bf16x2 (hi parts) and return residual bf16x2 (lo parts)
__device__ __forceinline__ void split_pair(float x, float y, uint32_t& hb, uint32_t& lb) {
    __nv_bfloat162 h = __floats2bfloat162_rn(x, y);   // .x=lo half from x, .y=hi half from y
    memcpy(&hb, &h, 4);
    float rx = x - __uint_as_float(hb << 16);
    float ry = y - __uint_as_float(hb & 0xffff0000u);
    __nv_bfloat162 l = __floats2bfloat162_rn(rx, ry);
    memcpy(&lb, &l, 4);
}

#define MMA_BF16(d, a, b) \
    asm volatile("mma.sync.aligned.m16n8k16.row.col.f32.bf16.bf16.f32 " \
        "{%0,%1,%2,%3}, {%4,%5,%6,%7}, {%8,%9}, {%0,%1,%2,%3};" \
        : "+f"((d)[0]), "+f"((d)[1]), "+f"((d)[2]), "+f"((d)[3]) \
        : "r"((a)[0]), "r"((a)[1]), "r"((a)[2]), "r"((a)[3]), \
          "r"((b)[0]), "r"((b)[1]))

// ---------------- split-bf16 mma.sync GEMM ------------------------------------
// C[M,N] = alpha * A[M,K] @ B[N,K]^T  (A [M,K] K-major, B [N,K] K-major, fp32)
// Block tile 128 x NT x 32. 8 warps = 2(m) x 4(n); warp tile 64 x NT/4.
// 2-way bf16 split, 3 HMMA products per fragment pair (hh + hl + lh).
// causal_mode: 0 none; 1 skip tiles colbase>=rowbase+128; 2 kmax=rowbase+128.
template<int NT>
__global__ void __launch_bounds__(256)
mma_gemm(const float* __restrict__ A, const float* __restrict__ B, float* __restrict__ C,
         int K, int lda, int ldb, int ldc,
         long long sA, long long sB, long long sC, float alpha, int causal_mode)
{
    constexpr int WTN   = NT / 4;       // warp tile n: 32 or 16
    constexpr int NFRAG = WTN / 8;      // 4 or 2
    constexpr int MFRAG = 4;            // 64/16
    constexpr int ASZ = 128 * 17;       // u32 elems (bf16x2), row stride 17
    constexpr int BSZ = NT * 17;
    constexpr int BUF = 2 * ASZ + 2 * BSZ;   // Ah Al Bh Bl
    constexpr int ACNT = 4;             // float4 gmem loads per thread (A)
    constexpr int BCNT = NT / 32;       // float4 gmem loads per thread (B)

    const int rowbase = blockIdx.y * 128;
    const int colbase = blockIdx.x * NT;
    if (causal_mode == 1 && colbase >= rowbase + 128) return;
    const int kmax = (causal_mode == 2) ? min(K, rowbase + 128) : K;
    const int nk = kmax >> 5;

    A += blockIdx.z * sA; B += blockIdx.z * sB; C += blockIdx.z * sC;

    extern __shared__ uint32_t sm[];
    const int tid = threadIdx.x;
    const int wid = tid >> 5, lane = tid & 31;
    const int wm = wid >> 2, wn = wid & 3;
    const int lr = lane >> 2, lc = lane & 3;

    float acc[MFRAG][NFRAG][4];
#pragma unroll
    for (int i = 0; i < MFRAG; i++)
#pragma unroll
        for (int j = 0; j < NFRAG; j++)
#pragma unroll
            for (int q = 0; q < 4; q++) acc[i][j][q] = 0.f;

    // ---- prologue: gmem -> smem buf 0
    {
        uint32_t* Ah = sm;           uint32_t* Al = Ah + ASZ;
        uint32_t* Bh = Al + ASZ;     uint32_t* Bl = Bh + BSZ;
#pragma unroll
        for (int i = 0; i < ACNT; i++) {
            int idx = tid + i * 256, r = idx >> 3, c4 = idx & 7;
            float4 v = *(const float4*)(A + (long long)(rowbase + r) * lda + c4 * 4);
            uint32_t h0, l0, h1, l1;
            split_pair(v.x, v.y, h0, l0); split_pair(v.z, v.w, h1, l1);
            Ah[r * 17 + c4 * 2] = h0; Ah[r * 17 + c4 * 2 + 1] = h1;
            Al[r * 17 + c4 * 2] = l0; Al[r * 17 + c4 * 2 + 1] = l1;
        }
#pragma unroll
        for (int i = 0; i < BCNT; i++) {
            int idx = tid + i * 256, r = idx >> 3, c4 = idx & 7;
            float4 v = *(const float4*)(B + (long long)(colbase + r) * ldb + c4 * 4);
            uint32_t h0, l0, h1, l1;
            split_pair(v.x, v.y, h0, l0); split_pair(v.z, v.w, h1, l1);
            Bh[r * 17 + c4 * 2] = h0; Bh[r * 17 + c4 * 2 + 1] = h1;
            Bl[r * 17 + c4 * 2] = l0; Bl[r * 17 + c4 * 2 + 1] = l1;
        }
    }
    __syncthreads();

    float4 ra[ACNT], rb[BCNT];
    for (int kt = 0; kt < nk; kt++) {
        // ---- prefetch next k-tile into registers
        if (kt + 1 < nk) {
            int k0 = (kt + 1) << 5;
#pragma unroll
            for (int i = 0; i < ACNT; i++) {
                int idx = tid + i * 256, r = idx >> 3, c4 = idx & 7;
                ra[i] = *(const float4*)(A + (long long)(rowbase + r) * lda + k0 + c4 * 4);
            }
#pragma unroll
            for (int i = 0; i < BCNT; i++) {
                int idx = tid + i * 256, r = idx >> 3, c4 = idx & 7;
                rb[i] = *(const float4*)(B + (long long)(colbase + r) * ldb + k0 + c4 * 4);
            }
        }
        // ---- compute on current buffer
        {
            const uint32_t* Ah = sm + (kt & 1) * BUF;
            const uint32_t* Al = Ah + ASZ;
            const uint32_t* Bh = Al + ASZ;
            const uint32_t* Bl = Bh + BSZ;
#pragma unroll
            for (int ks = 0; ks < 2; ks++) {
                const int ko = ks * 8;
                uint32_t ah[MFRAG][4], al[MFRAG][4];
#pragma unroll
                for (int mf = 0; mf < MFRAG; mf++) {
                    int r0 = wm * 64 + mf * 16 + lr;
                    int i0 = r0 * 17 + ko + lc;
                    int i1 = i0 + 8 * 17;
                    ah[mf][0] = Ah[i0]; ah[mf][1] = Ah[i1];
                    ah[mf][2] = Ah[i0 + 4]; ah[mf][3] = Ah[i1 + 4];
                    al[mf][0] = Al[i0]; al[mf][1] = Al[i1];
                    al[mf][2] = Al[i0 + 4]; al[mf][3] = Al[i1 + 4];
                }
                uint32_t bh[NFRAG][2], bl[NFRAG][2];
#pragma unroll
                for (int nf = 0; nf < NFRAG; nf++) {
                    int n0 = wn * WTN + nf * 8 + lr;
                    int j0 = n0 * 17 + ko + lc;
                    bh[nf][0] = Bh[j0]; bh[nf][1] = Bh[j0 + 4];
                    bl[nf][0] = Bl[j0]; bl[nf][1] = Bl[j0 + 4];
                }
#pragma unroll
                for (int mf = 0; mf < MFRAG; mf++)
#pragma unroll
                    for (int nf = 0; nf < NFRAG; nf++) {
                        MMA_BF16(acc[mf][nf], ah[mf], bh[nf]);
                        MMA_BF16(acc[mf][nf], ah[mf], bl[nf]);
                        MMA_BF16(acc[mf][nf], al[mf], bh[nf]);
                    }
            }
        }
        __syncthreads();
        // ---- store prefetched regs into the other buffer
        if (kt + 1 < nk) {
            uint32_t* Ah = sm + ((kt + 1) & 1) * BUF;
            uint32_t* Al = Ah + ASZ;
            uint32_t* Bh = Al + ASZ;
            uint32_t* Bl = Bh + BSZ;
#pragma unroll
            for (int i = 0; i < ACNT; i++) {
                int idx = tid + i * 256, r = idx >> 3, c4 = idx & 7;
                uint32_t h0, l0, h1, l1;
                split_pair(ra[i].x, ra[i].y, h0, l0); split_pair(ra[i].z, ra[i].w, h1, l1);
                Ah[r * 17 + c4 * 2] = h0; Ah[r * 17 + c4 * 2 + 1] = h1;
                Al[r * 17 + c4 * 2] = l0; Al[r * 17 + c4 * 2 + 1] = l1;
            }
#pragma unroll
            for (int i = 0; i < BCNT; i++) {
                int idx = tid + i * 256, r = idx >> 3, c4 = idx & 7;
                uint32_t h0, l0, h1, l1;
                split_pair(rb[i].x, rb[i].y, h0, l0); split_pair(rb[i].z, rb[i].w, h1, l1);
                Bh[r * 17 + c4 * 2] = h0; Bh[r * 17 + c4 * 2 + 1] = h1;
                Bl[r * 17 + c4 * 2] = l0; Bl[r * 17 + c4 * 2 + 1] = l1;
            }
            __syncthreads();
        }
    }

    // ---- epilogue
#pragma unroll
    for (int mf = 0; mf < MFRAG; mf++) {
        int r0 = rowbase + wm * 64 + mf * 16 + lr;
#pragma unroll
        for (int nf = 0; nf < NFRAG; nf++) {
            int c0 = colbase + wn * WTN + nf * 8 + lc * 2;
            float2 v0 = make_float2(acc[mf][nf][0] * alpha, acc[mf][nf][1] * alpha);
            float2 v1 = make_float2(acc[mf][nf][2] * alpha, acc[mf][nf][3] * alpha);
            *(float2*)(C + (long long)r0 * ldc + c0) = v0;
            *(float2*)(C + (long long)(r0 + 8) * ldc + c0) = v1;
        }
    }
}

// ---------------- fp32 transpose (tiled, batched) ----------------------------
__global__ void __launch_bounds__(256)
transpose_kernel(const float* __restrict__ in, float* __restrict__ out,
                 int ldin, int ldout, long long sIn, long long sOut)
{
    __shared__ float t[32][33];
    const float* ip = in + blockIdx.z * sIn;
    float* op = out + blockIdx.z * sOut;
    const int c0 = blockIdx.x * 32, r0 = blockIdx.y * 32;
#pragma unroll
    for (int i = 0; i < 4; i++) {
        int r = threadIdx.y + i * 8;
        t[r][threadIdx.x] = ip[(long long)(r0 + r) * ldin + c0 + threadIdx.x];
    }
    __syncthreads();
#pragma unroll
    for (int i = 0; i < 4; i++) {
        int c = threadIdx.y + i * 8;
        op[(long long)(c0 + c) * ldout + r0 + threadIdx.x] = t[threadIdx.x][c];
    }
}

// ---------------- rmsnorm(latent) + RoPE(k_pe, q_pe per head) ----------------
__global__ void __launch_bounds__(256)
prep_kernel(const float* __restrict__ cosp, const float* __restrict__ sinp,
            const float* __restrict__ normw)
{
    const int s = blockIdx.x;
    const int tid = threadIdx.x;
    const float* kv = g_kv + (long long)s * D;
    float* kf = g_kfull + (long long)s * D;

    float ss = 0.f;
    for (int i = tid; i < KVR; i += 256) { float v = kv[i]; ss += v * v; }
    __shared__ float red[32];
#pragma unroll
    for (int o = 16; o > 0; o >>= 1) ss += __shfl_xor_sync(0xffffffffu, ss, o);
    if ((tid & 31) == 0) red[tid >> 5] = ss;
    __syncthreads();
    if (tid < 32) {
        float v = (tid < 8) ? red[tid] : 0.f;
#pragma unroll
        for (int o = 16; o > 0; o >>= 1) v += __shfl_xor_sync(0xffffffffu, v, o);
        if (tid == 0) red[0] = v;
    }
    __syncthreads();
    const float r = rsqrtf(red[0] / (float)KVR + EPS);

    for (int i = tid; i < KVR; i += 256) kf[i] = kv[i] * r * normw[i];

    const float* cs = cosp + (long long)s * ROPE;
    const float* sn = sinp + (long long)s * ROPE;

    for (int i = tid; i < ROPE; i += 256) {
        float v = kv[KVR + i];
        float rot = (i < 32) ? -kv[KVR + i + 32] : kv[KVR + i - 32];
        kf[KVR + i] = v * cs[i] + rot * sn[i];
    }
    for (int idx = tid; idx < H * ROPE; idx += 256) {
        int h = idx >> 6, i = idx & 63;
        const float* qp = g_q + (long long)s * (H * QD) + h * QD + NOPE;
        float v = qp[i];
        float rot = (i < 32) ? -qp[i + 32] : qp[i - 32];
        g_qfull[(long long)h * S * D + (long long)s * D + KVR + i] = v * cs[i] + rot * sn[i];
    }
}

// ---------------- causal row softmax ----------------------------------------
__global__ void __launch_bounds__(256)
softmax_kernel()
{
    const int s = blockIdx.x, h = blockIdx.y;
    float* row = g_p + ((long long)h * S + s) * S;
    __shared__ float sh[S];
    __shared__ float red[33];
    const int n = s + 1;
    const int tid = threadIdx.x;

    float mx = -3.0e38f;
    for (int t = tid; t < n; t += 256) { float v = row[t]; sh[t] = v; mx = fmaxf(mx, v); }
#pragma unroll
    for (int o = 16; o > 0; o >>= 1) mx = fmaxf(mx, __shfl_xor_sync(0xffffffffu, mx, o));
    if ((tid & 31) == 0) red[tid >> 5] = mx;
    __syncthreads();
    if (tid < 32) {
        float v = (tid < 8) ? red[tid] : -3.0e38f;
#pragma unroll
        for (int o = 16; o > 0; o >>= 1) v = fmaxf(v, __shfl_xor_sync(0xffffffffu, v, o));
        if (tid == 0) red[32] = v;
    }
    __syncthreads();
    mx = red[32];

    float sum = 0.f;
    for (int t = tid; t < n; t += 256) { float e = expf(sh[t] - mx); sh[t] = e; sum += e; }
#pragma unroll
    for (int o = 16; o > 0; o >>= 1) sum += __shfl_xor_sync(0xffffffffu, sum, o);
    if ((tid & 31) == 0) red[tid >> 5] = sum;
    __syncthreads();
    if (tid < 32) {
        float v = (tid < 8) ? red[tid] : 0.f;
#pragma unroll
        for (int o = 16; o > 0; o >>= 1) v += __shfl_xor_sync(0xffffffffu, v, o);
        if (tid == 0) red[32] = v;
    }
    __syncthreads();
    const float inv = 1.0f / red[32];

    for (int t = tid; t < n; t += 256) row[t] = sh[t] * inv;
    for (int t = n + tid; t < S; t += 256) row[t] = 0.f;
}

// ---------------- launch ------------------------------------------------------
extern "C" void kernel_launch(void* const* d_in, const int* in_sizes, int n_in,
                              void* d_out, int out_size)
{
    (void)in_sizes; (void)n_in; (void)out_size;
    const float* x      = (const float*)d_in[0];
    const float* cosp   = (const float*)d_in[1];
    const float* sinp   = (const float*)d_in[2];
    const float* w_q    = (const float*)d_in[3];
    const float* w_kv_a = (const float*)d_in[4];
    const float* normw  = (const float*)d_in[5];
    const float* kc     = (const float*)d_in[6];
    const float* vc     = (const float*)d_in[7];
    const float* w_o    = (const float*)d_in[8];
    float* out = (float*)d_out;

    float *q, *kv, *qf, *kf, *p, *ao, *ov;
    float *wqT, *wkvaT, *kcT, *vcT, *woT, *latT;
    cudaGetSymbolAddress((void**)&q,  g_q);
    cudaGetSymbolAddress((void**)&kv, g_kv);
    cudaGetSymbolAddress((void**)&qf, g_qfull);
    cudaGetSymbolAddress((void**)&kf, g_kfull);
    cudaGetSymbolAddress((void**)&p,  g_p);
    cudaGetSymbolAddress((void**)&ao, g_ao);
    cudaGetSymbolAddress((void**)&ov, g_ov);
    cudaGetSymbolAddress((void**)&wqT,   g_wqT);
    cudaGetSymbolAddress((void**)&wkvaT, g_wkvaT);
    cudaGetSymbolAddress((void**)&kcT,   g_kcT);
    cudaGetSymbolAddress((void**)&vcT,   g_vcT);
    cudaGetSymbolAddress((void**)&woT,   g_woT);
    cudaGetSymbolAddress((void**)&latT,  g_latT);

    // dynamic smem sizes (u32 elems * 4 bytes * 2 buffers)
    const int SMEM128 = 2 * (2 * 128 * 17 + 2 * 128 * 17) * 4;  // 69632
    const int SMEM64  = 2 * (2 * 128 * 17 + 2 * 64 * 17) * 4;   // 52224
    cudaFuncSetAttribute(mma_gemm<128>, cudaFuncAttributeMaxDynamicSharedMemorySize, SMEM128);
    cudaFuncSetAttribute(mma_gemm<64>,  cudaFuncAttributeMaxDynamicSharedMemorySize, SMEM64);

    dim3 tb(32, 8);

    // ---- transpose weights to K-major [N,K] layouts
    transpose_kernel<<<dim3((H * QD) / 32, HID / 32, 1), tb>>>(w_q, wqT, H * QD, HID, 0, 0);
    transpose_kernel<<<dim3(D / 32, HID / 32, 1), tb>>>(w_kv_a, wkvaT, D, HID, 0, 0);
    transpose_kernel<<<dim3(KVR / 32, NOPE / 32, H), tb>>>(kc, kcT, KVR, NOPE,
        (long long)NOPE * KVR, (long long)NOPE * KVR);
    transpose_kernel<<<dim3(VH / 32, KVR / 32, H), tb>>>(vc, vcT, VH, KVR,
        (long long)KVR * VH, (long long)KVR * VH);
    transpose_kernel<<<dim3(HID / 32, (H * VH) / 32, 1), tb>>>(w_o, woT, HID, H * VH, 0, 0);

    // 1) q = x @ w_q          [2048, 3072]
    mma_gemm<128><<<dim3((H * QD) / 128, S / 128, 1), 256, SMEM128>>>(
        x, wqT, q, HID, HID, HID, H * QD, 0, 0, 0, 1.0f, 0);

    // 2) kv = x @ w_kv_a      [2048, 576]
    mma_gemm<64><<<dim3(D / 64, S / 128, 1), 256, SMEM64>>>(
        x, wkvaT, kv, HID, HID, HID, D, 0, 0, 0, 1.0f, 0);

    // 3) rmsnorm + rope
    prep_kernel<<<S, 256>>>(cosp, sinp, normw);

    // 3b) latent^T  [512, 2048]
    transpose_kernel<<<dim3(KVR / 32, S / 32, 1), tb>>>(kf, latT, D, S, 0, 0);

    // 4) q_nope @ kc -> g_qfull[:, :512]   (per head)
    mma_gemm<128><<<dim3(KVR / 128, S / 128, H), 256, SMEM128>>>(
        q, kcT, qf, NOPE, H * QD, NOPE, D,
        (long long)QD, (long long)KVR * NOPE, (long long)S * D, 1.0f, 0);

    // 5) scores = SCALE * q_full @ k_full^T  (causal tile skip)
    mma_gemm<128><<<dim3(S / 128, S / 128, H), 256, SMEM128>>>(
        qf, kf, p, D, D, D, S,
        (long long)S * D, 0LL, (long long)S * S, SCALE, 1);

    // 6) causal softmax
    softmax_kernel<<<dim3(S, H), 256>>>();

    // 7) attn @ latent  (K truncated at diagonal)
    mma_gemm<128><<<dim3(KVR / 128, S / 128, H), 256, SMEM128>>>(
        p, latT, ao, S, S, S, KVR,
        (long long)S * S, 0LL, (long long)S * KVR, 1.0f, 2);

    // 8) out @ vc -> g_ov [S, H*VH]
    mma_gemm<128><<<dim3(VH / 128, S / 128, H), 256, SMEM128>>>(
        ao, vcT, ov, KVR, KVR, KVR, H * VH,
        (long long)S * KVR, (long long)VH * KVR, (long long)VH, 1.0f, 0);

    // 9) final: g_ov @ w_o -> out
    mma_gemm<128><<<dim3(HID / 128, S / 128, 1), 256, SMEM128>>>(
        ov, woT, out, H * VH, H * VH, H * VH, HID, 0, 0, 0, 1.0f, 0);
}

// round 7
// speedup vs baseline: 2.0428x; 1.0373x over previous
#include <cuda_runtime.h>
#include <cuda_bf16.h>
#include <cstdint>
#include <cstring>

#define S    2048
#define HID  2048
#define H    16
#define NOPE 128
#define ROPE 64
#define QD   192   // NOPE+ROPE
#define KVR  512
#define D    576   // KVR+ROPE
#define VH   128
#define SCALE 0.07216878364870323f
#define EPS  1e-6f

typedef __nv_bfloat16  bf16;
typedef __nv_bfloat162 bf162;

// ---------------- scratch (device globals) ------------------------------------
__device__ float g_q[(long long)S * H * QD];        // fp32 (prep reads q_pe)
__device__ float g_kv[(long long)S * D];
__device__ float g_kfull[(long long)S * D];
__device__ float g_p[(long long)H * S * S];         // scores fp32
// split bf16 operand arrays (hi/lo)
__device__ bf16 g_xh[(long long)S * HID],      g_xl[(long long)S * HID];
__device__ bf16 g_qh[(long long)S * H * QD],   g_ql[(long long)S * H * QD];
__device__ bf16 g_qfh[(long long)H * S * D],   g_qfl[(long long)H * S * D];
__device__ bf16 g_kfh[(long long)S * D],       g_kfl[(long long)S * D];
__device__ bf16 g_ph[(long long)H * S * S],    g_pl[(long long)H * S * S];
__device__ bf16 g_aoh[(long long)H * S * KVR], g_aol[(long long)H * S * KVR];
__device__ bf16 g_ovh[(long long)S * H * VH],  g_ovl[(long long)S * H * VH];
__device__ bf16 g_wqTh[(long long)(H * QD) * HID], g_wqTl[(long long)(H * QD) * HID];
__device__ bf16 g_wkvaTh[(long long)D * HID],      g_wkvaTl[(long long)D * HID];
__device__ bf16 g_kcTh[(long long)H * KVR * NOPE], g_kcTl[(long long)H * KVR * NOPE];
__device__ bf16 g_vcTh[(long long)H * VH * KVR],   g_vcTl[(long long)H * VH * KVR];
__device__ bf16 g_woTh[(long long)HID * (H * VH)], g_woTl[(long long)HID * (H * VH)];
__device__ bf16 g_latTh[(long long)KVR * S],       g_latTl[(long long)KVR * S];

// ---------------- helpers -----------------------------------------------------
__device__ __forceinline__ uint32_t smem_u32(const void* p) {
    uint32_t a;
    asm("{ .reg .u64 t; cvta.to.shared.u64 t, %1; cvt.u32.u64 %0, t; }" : "=r"(a) : "l"(p));
    return a;
}
__device__ __forceinline__ void split2(float x, float y, bf162& h, bf162& l) {
    h = __floats2bfloat162_rn(x, y);
    l = __floats2bfloat162_rn(x - __bfloat162float(h.x), y - __bfloat162float(h.y));
}

#define CP_ASYNC16(dst, src) \
    asm volatile("cp.async.cg.shared.global [%0], [%1], 16;" :: "r"(dst), "l"(src))
#define CP_COMMIT() asm volatile("cp.async.commit_group;" ::: "memory")
#define CP_WAIT(n)  asm volatile("cp.async.wait_group %0;" :: "n"(n) : "memory")

#define LDMX4(r0, r1, r2, r3, addr) \
    asm volatile("ldmatrix.sync.aligned.m8n8.x4.shared.b16 {%0,%1,%2,%3}, [%4];" \
        : "=r"(r0), "=r"(r1), "=r"(r2), "=r"(r3) : "r"(addr))

#define MMA_BF16(d, a, b0v, b1v) \
    asm volatile("mma.sync.aligned.m16n8k16.row.col.f32.bf16.bf16.f32 " \
        "{%0,%1,%2,%3}, {%4,%5,%6,%7}, {%8,%9}, {%0,%1,%2,%3};" \
        : "+f"((d)[0]), "+f"((d)[1]), "+f"((d)[2]), "+f"((d)[3]) \
        : "r"((a)[0]), "r"((a)[1]), "r"((a)[2]), "r"((a)[3]), "r"(b0v), "r"(b1v))

// ---------------- split-bf16 mma.sync GEMM (pre-split operands) ----------------
// C[M,N] = alpha * A[M,K] @ B[N,K]^T. A,B given as bf16 hi/lo pairs, K-major.
// Block tile 128 x NT x 32; 8 warps = 2(m) x 4(n).
// EPI: 0 = fp32 C; 1 = split bf16 (Ch,Cl); 2 = both.
// causal_mode: 0 none; 1 skip colbase>=rowbase+128; 2 kmax=rowbase+128.
template<int NT, int EPI>
__global__ void __launch_bounds__(256)
mma_gemm(const bf16* __restrict__ Agh, const bf16* __restrict__ Agl,
         const bf16* __restrict__ Bgh, const bf16* __restrict__ Bgl,
         float* __restrict__ C, bf16* __restrict__ Ch, bf16* __restrict__ Cl,
         int K, int lda, int ldb, int ldc,
         long long sA, long long sB, long long sC, float alpha, int causal_mode)
{
    constexpr int WTN = NT / 4, NFRAG = WTN / 8, MFRAG = 4;
    constexpr int OFF_AL = 10240, OFF_BH = 20480, OFF_BL = 20480 + NT * 80;
    constexpr int BUFB = 20480 + 2 * NT * 80;
    constexpr int BC = (NT * 4) / 256;      // B chunk loads per thread per array

    const int rowbase = blockIdx.y * 128;
    const int colbase = blockIdx.x * NT;
    if (causal_mode == 1 && colbase >= rowbase + 128) return;
    const int kmax = (causal_mode == 2) ? min(K, rowbase + 128) : K;
    const int nk = kmax >> 5;

    Agh += blockIdx.z * sA; Agl += blockIdx.z * sA;
    Bgh += blockIdx.z * sB; Bgl += blockIdx.z * sB;

    extern __shared__ char smem[];
    const uint32_t sb = smem_u32(smem);
    const int tid = threadIdx.x, wid = tid >> 5, lane = tid & 31;
    const int wm = wid >> 2, wn = wid & 3;
    const int lr = lane >> 2, lc = lane & 3;

    float acc[MFRAG][NFRAG][4];
#pragma unroll
    for (int i = 0; i < MFRAG; i++)
#pragma unroll
        for (int j = 0; j < NFRAG; j++)
#pragma unroll
            for (int q = 0; q < 4; q++) acc[i][j][q] = 0.f;

    auto issue_tile = [&](int kt, int buf) {
        const uint32_t base = sb + buf * BUFB;
        const int k0 = kt << 5;
#pragma unroll
        for (int i = 0; i < 2; i++) {              // A: 512 chunks per array
            int idx = tid + i * 256, r = idx >> 2, c = idx & 3;
            long long g = (long long)(rowbase + r) * lda + k0 + c * 8;
            uint32_t so = (uint32_t)(r * 80 + c * 16);
            CP_ASYNC16(base + so, Agh + g);
            CP_ASYNC16(base + OFF_AL + so, Agl + g);
        }
#pragma unroll
        for (int i = 0; i < BC; i++) {             // B: NT*4 chunks per array
            int idx = tid + i * 256, r = idx >> 2, c = idx & 3;
            long long g = (long long)(colbase + r) * ldb + k0 + c * 8;
            uint32_t so = (uint32_t)(r * 80 + c * 16);
            CP_ASYNC16(base + OFF_BH + so, Bgh + g);
            CP_ASYNC16(base + OFF_BL + so, Bgl + g);
        }
        CP_COMMIT();
    };

    issue_tile(0, 0);

    for (int kt = 0; kt < nk; kt++) {
        if (kt + 1 < nk) { issue_tile(kt + 1, (kt + 1) & 1); CP_WAIT(1); }
        else             { CP_WAIT(0); }
        __syncthreads();

        const uint32_t base = sb + (kt & 1) * BUFB;
        // B fragments, both k-halves: [nf][b0@ks0, b1@ks0, b0@ks1, b1@ks1]
        uint32_t bh[NFRAG][4], bl[NFRAG][4];
#pragma unroll
        for (int nf = 0; nf < NFRAG; nf++) {
            int n = wn * WTN + nf * 8 + (lane & 7);
            uint32_t ad = base + OFF_BH + n * 80 + (lane >> 3) * 16;
            LDMX4(bh[nf][0], bh[nf][1], bh[nf][2], bh[nf][3], ad);
            LDMX4(bl[nf][0], bl[nf][1], bl[nf][2], bl[nf][3], ad + (OFF_BL - OFF_BH));
        }
#pragma unroll
        for (int ks = 0; ks < 2; ks++) {
#pragma unroll
            for (int mf = 0; mf < MFRAG; mf++) {
                int r = wm * 64 + mf * 16 + (lane & 15);
                uint32_t ad = base + r * 80 + (lane >> 4) * 16 + ks * 32;
                uint32_t ah[4], al[4];
                LDMX4(ah[0], ah[1], ah[2], ah[3], ad);
                LDMX4(al[0], al[1], al[2], al[3], ad + OFF_AL);
#pragma unroll
                for (int nf = 0; nf < NFRAG; nf++) {
                    MMA_BF16(acc[mf][nf], ah, bh[nf][2 * ks], bh[nf][2 * ks + 1]);
                    MMA_BF16(acc[mf][nf], ah, bl[nf][2 * ks], bl[nf][2 * ks + 1]);
                    MMA_BF16(acc[mf][nf], al, bh[nf][2 * ks], bh[nf][2 * ks + 1]);
                }
            }
        }
        __syncthreads();
    }

    // ---- epilogue
#pragma unroll
    for (int mf = 0; mf < MFRAG; mf++) {
        int r0 = rowbase + wm * 64 + mf * 16 + lr;
#pragma unroll
        for (int nf = 0; nf < NFRAG; nf++) {
            int c0 = colbase + wn * WTN + nf * 8 + lc * 2;
            float v00 = acc[mf][nf][0] * alpha, v01 = acc[mf][nf][1] * alpha;
            float v10 = acc[mf][nf][2] * alpha, v11 = acc[mf][nf][3] * alpha;
            long long o0 = (long long)r0 * ldc + c0 + blockIdx.z * sC;
            long long o1 = (long long)(r0 + 8) * ldc + c0 + blockIdx.z * sC;
            if (EPI == 0 || EPI == 2) {
                *(float2*)(C + o0) = make_float2(v00, v01);
                *(float2*)(C + o1) = make_float2(v10, v11);
            }
            if (EPI >= 1) {
                bf162 h0, l0, h1, l1;
                split2(v00, v01, h0, l0); split2(v10, v11, h1, l1);
                *(bf162*)(Ch + o0) = h0; *(bf162*)(Cl + o0) = l0;
                *(bf162*)(Ch + o1) = h1; *(bf162*)(Cl + o1) = l1;
            }
        }
    }
}

// ---------------- fp32 -> split bf16 (elementwise) -----------------------------
__global__ void __launch_bounds__(256)
split_kernel(const float* __restrict__ in, bf16* __restrict__ oh, bf16* __restrict__ ol,
             long long n)
{
    long long i = ((long long)blockIdx.x * 256 + threadIdx.x) * 4;
    if (i >= n) return;
    float4 v = *(const float4*)(in + i);
    bf162 h0, l0, h1, l1;
    split2(v.x, v.y, h0, l0); split2(v.z, v.w, h1, l1);
    *(bf162*)(oh + i) = h0; *(bf162*)(oh + i + 2) = h1;
    *(bf162*)(ol + i) = l0; *(bf162*)(ol + i + 2) = l1;
}

// ---------------- fp32 transpose -> split bf16 ---------------------------------
__global__ void __launch_bounds__(256)
transpose_split_kernel(const float* __restrict__ in, bf16* __restrict__ oh,
                       bf16* __restrict__ ol, int ldin, int ldout,
                       long long sIn, long long sOut)
{
    __shared__ float t[32][33];
    const float* ip = in + blockIdx.z * sIn;
    const int c0 = blockIdx.x * 32, r0 = blockIdx.y * 32;
#pragma unroll
    for (int i = 0; i < 4; i++) {
        int r = threadIdx.y + i * 8;
        t[r][threadIdx.x] = ip[(long long)(r0 + r) * ldin + c0 + threadIdx.x];
    }
    __syncthreads();
#pragma unroll
    for (int i = 0; i < 4; i++) {
        int c = threadIdx.y + i * 8;
        float v = t[threadIdx.x][c];
        bf16 h = __float2bfloat16(v);
        bf16 l = __float2bfloat16(v - __bfloat162float(h));
        long long o = blockIdx.z * sOut + (long long)(c0 + c) * ldout + r0 + threadIdx.x;
        oh[o] = h; ol[o] = l;
    }
}

// ---------------- rmsnorm(latent) + RoPE ---------------------------------------
__global__ void __launch_bounds__(256)
prep_kernel(const float* __restrict__ cosp, const float* __restrict__ sinp,
            const float* __restrict__ normw)
{
    const int s = blockIdx.x;
    const int tid = threadIdx.x;
    const float* kv = g_kv + (long long)s * D;
    float* kf = g_kfull + (long long)s * D;

    float ss = 0.f;
    for (int i = tid; i < KVR; i += 256) { float v = kv[i]; ss += v * v; }
    __shared__ float red[32];
#pragma unroll
    for (int o = 16; o > 0; o >>= 1) ss += __shfl_xor_sync(0xffffffffu, ss, o);
    if ((tid & 31) == 0) red[tid >> 5] = ss;
    __syncthreads();
    if (tid < 32) {
        float v = (tid < 8) ? red[tid] : 0.f;
#pragma unroll
        for (int o = 16; o > 0; o >>= 1) v += __shfl_xor_sync(0xffffffffu, v, o);
        if (tid == 0) red[0] = v;
    }
    __syncthreads();
    const float r = rsqrtf(red[0] / (float)KVR + EPS);

    for (int i = tid; i < KVR; i += 256) {
        float v = kv[i] * r * normw[i];
        kf[i] = v;
        bf16 h = __float2bfloat16(v);
        g_kfh[(long long)s * D + i] = h;
        g_kfl[(long long)s * D + i] = __float2bfloat16(v - __bfloat162float(h));
    }

    const float* cs = cosp + (long long)s * ROPE;
    const float* sn = sinp + (long long)s * ROPE;

    for (int i = tid; i < ROPE; i += 256) {
        float v = kv[KVR + i];
        float rot = (i < 32) ? -kv[KVR + i + 32] : kv[KVR + i - 32];
        float w = v * cs[i] + rot * sn[i];
        kf[KVR + i] = w;
        bf16 h = __float2bfloat16(w);
        g_kfh[(long long)s * D + KVR + i] = h;
        g_kfl[(long long)s * D + KVR + i] = __float2bfloat16(w - __bfloat162float(h));
    }
    for (int idx = tid; idx < H * ROPE; idx += 256) {
        int h = idx >> 6, i = idx & 63;
        const float* qp = g_q + (long long)s * (H * QD) + h * QD + NOPE;
        float v = qp[i];
        float rot = (i < 32) ? -qp[i + 32] : qp[i - 32];
        float w = v * cs[i] + rot * sn[i];
        long long o = (long long)h * S * D + (long long)s * D + KVR + i;
        bf16 hb = __float2bfloat16(w);
        g_qfh[o] = hb;
        g_qfl[o] = __float2bfloat16(w - __bfloat162float(hb));
    }
}

// ---------------- causal row softmax (fp32 in -> split bf16 out) ---------------
__global__ void __launch_bounds__(256)
softmax_kernel()
{
    const int s = blockIdx.x, h = blockIdx.y;
    const float* row = g_p + ((long long)h * S + s) * S;
    bf16* ph = g_ph + ((long long)h * S + s) * S;
    bf16* pl = g_pl + ((long long)h * S + s) * S;
    __shared__ float sh[S];
    __shared__ float red[33];
    const int n = s + 1;
    const int tid = threadIdx.x;

    float mx = -3.0e38f;
    for (int t = tid; t < n; t += 256) { float v = row[t]; sh[t] = v; mx = fmaxf(mx, v); }
#pragma unroll
    for (int o = 16; o > 0; o >>= 1) mx = fmaxf(mx, __shfl_xor_sync(0xffffffffu, mx, o));
    if ((tid & 31) == 0) red[tid >> 5] = mx;
    __syncthreads();
    if (tid < 32) {
        float v = (tid < 8) ? red[tid] : -3.0e38f;
#pragma unroll
        for (int o = 16; o > 0; o >>= 1) v = fmaxf(v, __shfl_xor_sync(0xffffffffu, v, o));
        if (tid == 0) red[32] = v;
    }
    __syncthreads();
    mx = red[32];

    float sum = 0.f;
    for (int t = tid; t < n; t += 256) { float e = expf(sh[t] - mx); sh[t] = e; sum += e; }
#pragma unroll
    for (int o = 16; o > 0; o >>= 1) sum += __shfl_xor_sync(0xffffffffu, sum, o);
    if ((tid & 31) == 0) red[tid >> 5] = sum;
    __syncthreads();
    if (tid < 32) {
        float v = (tid < 8) ? red[tid] : 0.f;
#pragma unroll
        for (int o = 16; o > 0; o >>= 1) v += __shfl_xor_sync(0xffffffffu, v, o);
        if (tid == 0) red[32] = v;
    }
    __syncthreads();
    const float inv = 1.0f / red[32];

    for (int t = tid; t < n; t += 256) {
        float v = sh[t] * inv;
        bf16 hb = __float2bfloat16(v);
        ph[t] = hb;
        pl[t] = __float2bfloat16(v - __bfloat162float(hb));
    }
    const bf16 z = __float2bfloat16(0.f);
    for (int t = n + tid; t < S; t += 256) { ph[t] = z; pl[t] = z; }
}

// ---------------- launch --------------------------------------------------------
extern "C" void kernel_launch(void* const* d_in, const int* in_sizes, int n_in,
                              void* d_out, int out_size)
{
    (void)in_sizes; (void)n_in; (void)out_size;
    const float* x      = (const float*)d_in[0];
    const float* cosp   = (const float*)d_in[1];
    const float* sinp   = (const float*)d_in[2];
    const float* w_q    = (const float*)d_in[3];
    const float* w_kv_a = (const float*)d_in[4];
    const float* normw  = (const float*)d_in[5];
    const float* kc     = (const float*)d_in[6];
    const float* vc     = (const float*)d_in[7];
    const float* w_o    = (const float*)d_in[8];
    float* out = (float*)d_out;

    float *q, *kv, *kf, *p;
    bf16 *xh, *xl, *qh, *ql, *qfh, *qfl, *kfh, *kfl, *ph, *pl, *aoh, *aol, *ovh, *ovl;
    bf16 *wqTh, *wqTl, *wkvaTh, *wkvaTl, *kcTh, *kcTl, *vcTh, *vcTl, *woTh, *woTl, *latTh, *latTl;
    cudaGetSymbolAddress((void**)&q,  g_q);
    cudaGetSymbolAddress((void**)&kv, g_kv);
    cudaGetSymbolAddress((void**)&kf, g_kfull);
    cudaGetSymbolAddress((void**)&p,  g_p);
    cudaGetSymbolAddress((void**)&xh, g_xh);   cudaGetSymbolAddress((void**)&xl, g_xl);
    cudaGetSymbolAddress((void**)&qh, g_qh);   cudaGetSymbolAddress((void**)&ql, g_ql);
    cudaGetSymbolAddress((void**)&qfh, g_qfh); cudaGetSymbolAddress((void**)&qfl, g_qfl);
    cudaGetSymbolAddress((void**)&kfh, g_kfh); cudaGetSymbolAddress((void**)&kfl, g_kfl);
    cudaGetSymbolAddress((void**)&ph, g_ph);   cudaGetSymbolAddress((void**)&pl, g_pl);
    cudaGetSymbolAddress((void**)&aoh, g_aoh); cudaGetSymbolAddress((void**)&aol, g_aol);
    cudaGetSymbolAddress((void**)&ovh, g_ovh); cudaGetSymbolAddress((void**)&ovl, g_ovl);
    cudaGetSymbolAddress((void**)&wqTh, g_wqTh);     cudaGetSymbolAddress((void**)&wqTl, g_wqTl);
    cudaGetSymbolAddress((void**)&wkvaTh, g_wkvaTh); cudaGetSymbolAddress((void**)&wkvaTl, g_wkvaTl);
    cudaGetSymbolAddress((void**)&kcTh, g_kcTh);     cudaGetSymbolAddress((void**)&kcTl, g_kcTl);
    cudaGetSymbolAddress((void**)&vcTh, g_vcTh);     cudaGetSymbolAddress((void**)&vcTl, g_vcTl);
    cudaGetSymbolAddress((void**)&woTh, g_woTh);     cudaGetSymbolAddress((void**)&woTl, g_woTl);
    cudaGetSymbolAddress((void**)&latTh, g_latTh);   cudaGetSymbolAddress((void**)&latTl, g_latTl);

    const int SMEM128 = 2 * (20480 + 2 * 128 * 80);  // 81920
    const int SMEM64  = 2 * (20480 + 2 * 64 * 80);   // 61440
    cudaFuncSetAttribute(mma_gemm<128, 0>, cudaFuncAttributeMaxDynamicSharedMemorySize, SMEM128);
    cudaFuncSetAttribute(mma_gemm<128, 1>, cudaFuncAttributeMaxDynamicSharedMemorySize, SMEM128);
    cudaFuncSetAttribute(mma_gemm<128, 2>, cudaFuncAttributeMaxDynamicSharedMemorySize, SMEM128);
    cudaFuncSetAttribute(mma_gemm<64, 0>,  cudaFuncAttributeMaxDynamicSharedMemorySize, SMEM64);

    dim3 tb(32, 8);

    // 0) split x; transpose+split weights
    split_kernel<<<(S * HID) / 1024, 256>>>(x, xh, xl, (long long)S * HID);
    transpose_split_kernel<<<dim3((H * QD) / 32, HID / 32, 1), tb>>>(w_q, wqTh, wqTl, H * QD, HID, 0, 0);
    transpose_split_kernel<<<dim3(D / 32, HID / 32, 1), tb>>>(w_kv_a, wkvaTh, wkvaTl, D, HID, 0, 0);
    transpose_split_kernel<<<dim3(KVR / 32, NOPE / 32, H), tb>>>(kc, kcTh, kcTl, KVR, NOPE,
        (long long)NOPE * KVR, (long long)NOPE * KVR);
    transpose_split_kernel<<<dim3(VH / 32, KVR / 32, H), tb>>>(vc, vcTh, vcTl, VH, KVR,
        (long long)KVR * VH, (long long)KVR * VH);
    transpose_split_kernel<<<dim3(HID / 32, (H * VH) / 32, 1), tb>>>(w_o, woTh, woTl, HID, H * VH, 0, 0);

    // 1) q = x @ w_q  (fp32 for prep + split for stage 4)
    mma_gemm<128, 2><<<dim3((H * QD) / 128, S / 128, 1), 256, SMEM128>>>(
        xh, xl, wqTh, wqTl, q, qh, ql, HID, HID, HID, H * QD, 0, 0, 0, 1.0f, 0);

    // 2) kv = x @ w_kv_a  (fp32 only)
    mma_gemm<64, 0><<<dim3(D / 64, S / 128, 1), 256, SMEM64>>>(
        xh, xl, wkvaTh, wkvaTl, kv, nullptr, nullptr, HID, HID, HID, D, 0, 0, 0, 1.0f, 0);

    // 3) rmsnorm + rope (writes kfull fp32+split, qfull rope split)
    prep_kernel<<<S, 256>>>(cosp, sinp, normw);

    // 3b) latent^T split  [KVR, S]
    transpose_split_kernel<<<dim3(KVR / 32, S / 32, 1), tb>>>(kf, latTh, latTl, D, S, 0, 0);

    // 4) q_nope @ kc -> qfull[:, :512] split (per head)
    mma_gemm<128, 1><<<dim3(KVR / 128, S / 128, H), 256, SMEM128>>>(
        qh, ql, kcTh, kcTl, nullptr, qfh, qfl, NOPE, H * QD, NOPE, D,
        (long long)QD, (long long)KVR * NOPE, (long long)S * D, 1.0f, 0);

    // 5) scores = SCALE * qfull @ kfull^T  (causal tile skip, fp32)
    mma_gemm<128, 0><<<dim3(S / 128, S / 128, H), 256, SMEM128>>>(
        qfh, qfl, kfh, kfl, p, nullptr, nullptr, D, D, D, S,
        (long long)S * D, 0LL, (long long)S * S, SCALE, 1);

    // 6) softmax -> P split
    softmax_kernel<<<dim3(S, H), 256>>>();

    // 7) ao = P @ latent  (K truncated at diagonal, split out)
    mma_gemm<128, 1><<<dim3(KVR / 128, S / 128, H), 256, SMEM128>>>(
        ph, pl, latTh, latTl, nullptr, aoh, aol, S, S, S, KVR,
        (long long)S * S, 0LL, (long long)S * KVR, 1.0f, 2);

    // 8) ov = ao @ vc  (split out, per head)
    mma_gemm<128, 1><<<dim3(VH / 128, S / 128, H), 256, SMEM128>>>(
        aoh, aol, vcTh, vcTl, nullptr, ovh, ovl, KVR, KVR, KVR, H * VH,
        (long long)S * KVR, (long long)VH * KVR, (long long)VH, 1.0f, 0);

    // 9) out = ov @ w_o  (fp32 final)
    mma_gemm<128, 0><<<dim3(HID / 128, S / 128, 1), 256, SMEM128>>>(
        ovh, ovl, woTh, woTl, out, nullptr, nullptr, H * VH, H * VH, H * VH, HID,
        0, 0, 0, 1.0f, 0);
}

// round 10
// speedup vs baseline: 2.3838x; 1.1669x over previous
#include <cuda_runtime.h>
#include <cuda_bf16.h>
#include <cuda_fp16.h>
#include <cstdint>
#include <cstring>

#define S    2048
#define HID  2048
#define H    16
#define NOPE 128
#define ROPE 64
#define QD   192   // NOPE+ROPE
#define KVR  512
#define D    576   // KVR+ROPE
#define VH   128
#define SCALE 0.07216878364870323f
#define EPS  1e-6f

typedef unsigned short u16;

// ---------------- scratch (device globals) ------------------------------------
__device__ float g_q[(long long)S * H * QD];        // fp32 (prep reads q_pe)
__device__ float g_kv[(long long)S * D];
__device__ float g_kfull[(long long)S * D];
__device__ float g_p[(long long)H * S * S];         // scores fp32
// bf16 split pairs (3-term stages 1,2,4,5)
__device__ u16 g_xh[(long long)S * HID],      g_xl[(long long)S * HID];
__device__ u16 g_qh[(long long)S * H * QD],   g_ql[(long long)S * H * QD];
__device__ u16 g_qfh[(long long)H * S * D],   g_qfl[(long long)H * S * D];
__device__ u16 g_kfh[(long long)S * D],       g_kfl[(long long)S * D];
__device__ u16 g_wqTh[(long long)(H * QD) * HID], g_wqTl[(long long)(H * QD) * HID];
__device__ u16 g_wkvaTh[(long long)D * HID],      g_wkvaTl[(long long)D * HID];
__device__ u16 g_kcTh[(long long)H * KVR * NOPE], g_kcTl[(long long)H * KVR * NOPE];
// fp16 (2-term stages 7,8,9): A split, B single
__device__ u16 g_ph16[(long long)H * S * S],  g_pl16[(long long)H * S * S];
__device__ u16 g_aoh16[(long long)H * S * KVR], g_aol16[(long long)H * S * KVR];
__device__ u16 g_ovh16[(long long)S * H * VH],  g_ovl16[(long long)S * H * VH];
__device__ u16 g_latT16[(long long)KVR * S];
__device__ u16 g_vcT16[(long long)H * VH * KVR];
__device__ u16 g_woT16[(long long)HID * (H * VH)];

// ---------------- helpers -----------------------------------------------------
__device__ __forceinline__ uint32_t smem_u32(const void* p) {
    uint32_t a;
    asm("{ .reg .u64 t; cvta.to.shared.u64 t, %1; cvt.u32.u64 %0, t; }" : "=r"(a) : "l"(p));
    return a;
}
__device__ __forceinline__ u16 bf16_bits(float v) {
    __nv_bfloat16 b = __float2bfloat16(v); u16 u; memcpy(&u, &b, 2); return u;
}
__device__ __forceinline__ float bf16_val(u16 u) {
    __nv_bfloat16 b; memcpy(&b, &u, 2); return __bfloat162float(b);
}
__device__ __forceinline__ u16 h16_bits(float v) {
    __half b = __float2half_rn(v); u16 u; memcpy(&u, &b, 2); return u;
}
__device__ __forceinline__ float h16_val(u16 u) {
    __half b; memcpy(&b, &u, 2); return __half2float(b);
}
__device__ __forceinline__ void split_bf_pack(float x, float y, uint32_t& h, uint32_t& l) {
    __nv_bfloat162 hv = __floats2bfloat162_rn(x, y);
    __nv_bfloat162 lv = __floats2bfloat162_rn(x - __bfloat162float(hv.x),
                                              y - __bfloat162float(hv.y));
    memcpy(&h, &hv, 4); memcpy(&l, &lv, 4);
}
__device__ __forceinline__ void split_h_pack(float x, float y, uint32_t& h, uint32_t& l) {
    __half2 hv = __floats2half2_rn(x, y);
    __half2 lv = __floats2half2_rn(x - __half2float(__low2half(hv)),
                                   y - __half2float(__high2half(hv)));
    memcpy(&h, &hv, 4); memcpy(&l, &lv, 4);
}

#define CP_ASYNC16(dst, src) \
    asm volatile("cp.async.cg.shared.global [%0], [%1], 16;" :: "r"(dst), "l"(src))
#define CP_COMMIT() asm volatile("cp.async.commit_group;" ::: "memory")
#define CP_WAIT(n)  asm volatile("cp.async.wait_group %0;" :: "n"(n) : "memory")

#define LDMX4(r0, r1, r2, r3, addr) \
    asm volatile("ldmatrix.sync.aligned.m8n8.x4.shared.b16 {%0,%1,%2,%3}, [%4];" \
        : "=r"(r0), "=r"(r1), "=r"(r2), "=r"(r3) : "r"(addr))

#define MMA_BF16(d, a, b0v, b1v) \
    asm volatile("mma.sync.aligned.m16n8k16.row.col.f32.bf16.bf16.f32 " \
        "{%0,%1,%2,%3}, {%4,%5,%6,%7}, {%8,%9}, {%0,%1,%2,%3};" \
        : "+f"((d)[0]), "+f"((d)[1]), "+f"((d)[2]), "+f"((d)[3]) \
        : "r"((a)[0]), "r"((a)[1]), "r"((a)[2]), "r"((a)[3]), "r"(b0v), "r"(b1v))

#define MMA_F16(d, a, b0v, b1v) \
    asm volatile("mma.sync.aligned.m16n8k16.row.col.f32.f16.f16.f32 " \
        "{%0,%1,%2,%3}, {%4,%5,%6,%7}, {%8,%9}, {%0,%1,%2,%3};" \
        : "+f"((d)[0]), "+f"((d)[1]), "+f"((d)[2]), "+f"((d)[3]) \
        : "r"((a)[0]), "r"((a)[1]), "r"((a)[2]), "r"((a)[3]), "r"(b0v), "r"(b1v))

// ---------------- split mma.sync GEMM ------------------------------------------
// C[M,N] = alpha * A[M,K] @ B[N,K]^T. All 16-bit operands K-major.
// MODE 0: bf16, A split + B split, 3 MMAs (hh+hl+lh).
// MODE 1: fp16, A split + B single, 2 MMAs ((ah+al)·b).
// EPI: 0=fp32 C; 1=bf16 split (Ch,Cl); 2=fp32+bf16 split; 3=fp16 split.
// causal_mode: 0 none; 1 skip colbase>=rowbase+128; 2 kmax=rowbase+128.
template<int NT, int MODE, int EPI>
__global__ void __launch_bounds__(256)
mma_gemm(const u16* __restrict__ Agh, const u16* __restrict__ Agl,
         const u16* __restrict__ Bgh, const u16* __restrict__ Bgl,
         float* __restrict__ C, u16* __restrict__ Ch, u16* __restrict__ Cl,
         int K, int lda, int ldb, int ldc,
         long long sA, long long sB, long long sC, float alpha, int causal_mode)
{
    constexpr int WTN = NT / 4, NFRAG = WTN / 8, MFRAG = 4;
    constexpr int OFF_AL = 10240, OFF_BH = 20480;
    constexpr int OFF_BL = 20480 + NT * 80;
    constexpr int BUFB = (MODE == 0) ? (20480 + 2 * NT * 80) : (20480 + NT * 80);
    constexpr int BC = (NT * 4) / 256;

    const int rowbase = blockIdx.y * 128;
    const int colbase = blockIdx.x * NT;
    if (causal_mode == 1 && colbase >= rowbase + 128) return;
    const int kmax = (causal_mode == 2) ? min(K, rowbase + 128) : K;
    const int nk = kmax >> 5;

    Agh += blockIdx.z * sA; Agl += blockIdx.z * sA;
    Bgh += blockIdx.z * sB;
    if (MODE == 0) Bgl += blockIdx.z * sB;

    extern __shared__ char smem[];
    const uint32_t sb = smem_u32(smem);
    const int tid = threadIdx.x, wid = tid >> 5, lane = tid & 31;
    const int wm = wid >> 2, wn = wid & 3;
    const int lr = lane >> 2, lc = lane & 3;

    float acc[MFRAG][NFRAG][4];
#pragma unroll
    for (int i = 0; i < MFRAG; i++)
#pragma unroll
        for (int j = 0; j < NFRAG; j++)
#pragma unroll
            for (int q = 0; q < 4; q++) acc[i][j][q] = 0.f;

    auto issue_tile = [&](int kt, int buf) {
        const uint32_t base = sb + buf * BUFB;
        const int k0 = kt << 5;
#pragma unroll
        for (int i = 0; i < 2; i++) {
            int idx = tid + i * 256, r = idx >> 2, c = idx & 3;
            long long g = (long long)(rowbase + r) * lda + k0 + c * 8;
            uint32_t so = (uint32_t)(r * 80 + c * 16);
            CP_ASYNC16(base + so, Agh + g);
            CP_ASYNC16(base + OFF_AL + so, Agl + g);
        }
#pragma unroll
        for (int i = 0; i < BC; i++) {
            int idx = tid + i * 256, r = idx >> 2, c = idx & 3;
            long long g = (long long)(colbase + r) * ldb + k0 + c * 8;
            uint32_t so = (uint32_t)(r * 80 + c * 16);
            CP_ASYNC16(base + OFF_BH + so, Bgh + g);
            if (MODE == 0) CP_ASYNC16(base + OFF_BL + so, Bgl + g);
        }
        CP_COMMIT();
    };

    issue_tile(0, 0);

    for (int kt = 0; kt < nk; kt++) {
        CP_WAIT(0);
        __syncthreads();
        if (kt + 1 < nk) issue_tile(kt + 1, (kt + 1) & 1);   // overlaps with compute

        const uint32_t base = sb + (kt & 1) * BUFB;
        uint32_t bh[NFRAG][4], bl[NFRAG][4];
#pragma unroll
        for (int nf = 0; nf < NFRAG; nf++) {
            int n = wn * WTN + nf * 8 + (lane & 7);
            uint32_t ad = base + OFF_BH + n * 80 + (lane >> 3) * 16;
            LDMX4(bh[nf][0], bh[nf][1], bh[nf][2], bh[nf][3], ad);
            if (MODE == 0)
                LDMX4(bl[nf][0], bl[nf][1], bl[nf][2], bl[nf][3], ad + (OFF_BL - OFF_BH));
        }
#pragma unroll
        for (int ks = 0; ks < 2; ks++) {
#pragma unroll
            for (int mf = 0; mf < MFRAG; mf++) {
                int r = wm * 64 + mf * 16 + (lane & 15);
                uint32_t ad = base + r * 80 + (lane >> 4) * 16 + ks * 32;
                uint32_t ah[4], al[4];
                LDMX4(ah[0], ah[1], ah[2], ah[3], ad);
                LDMX4(al[0], al[1], al[2], al[3], ad + OFF_AL);
#pragma unroll
                for (int nf = 0; nf < NFRAG; nf++) {
                    if (MODE == 0) {
                        MMA_BF16(acc[mf][nf], ah, bh[nf][2 * ks], bh[nf][2 * ks + 1]);
                        MMA_BF16(acc[mf][nf], ah, bl[nf][2 * ks], bl[nf][2 * ks + 1]);
                        MMA_BF16(acc[mf][nf], al, bh[nf][2 * ks], bh[nf][2 * ks + 1]);
                    } else {
                        MMA_F16(acc[mf][nf], ah, bh[nf][2 * ks], bh[nf][2 * ks + 1]);
                        MMA_F16(acc[mf][nf], al, bh[nf][2 * ks], bh[nf][2 * ks + 1]);
                    }
                }
            }
        }
    }

    // ---- epilogue
#pragma unroll
    for (int mf = 0; mf < MFRAG; mf++) {
        int r0 = rowbase + wm * 64 + mf * 16 + lr;
#pragma unroll
        for (int nf = 0; nf < NFRAG; nf++) {
            int c0 = colbase + wn * WTN + nf * 8 + lc * 2;
            float v00 = acc[mf][nf][0] * alpha, v01 = acc[mf][nf][1] * alpha;
            float v10 = acc[mf][nf][2] * alpha, v11 = acc[mf][nf][3] * alpha;
            long long o0 = (long long)r0 * ldc + c0 + blockIdx.z * sC;
            long long o1 = (long long)(r0 + 8) * ldc + c0 + blockIdx.z * sC;
            if (EPI == 0 || EPI == 2) {
                *(float2*)(C + o0) = make_float2(v00, v01);
                *(float2*)(C + o1) = make_float2(v10, v11);
            }
            if (EPI == 1 || EPI == 2) {
                uint32_t h0, l0, h1, l1;
                split_bf_pack(v00, v01, h0, l0); split_bf_pack(v10, v11, h1, l1);
                *(uint32_t*)(Ch + o0) = h0; *(uint32_t*)(Cl + o0) = l0;
                *(uint32_t*)(Ch + o1) = h1; *(uint32_t*)(Cl + o1) = l1;
            }
            if (EPI == 3) {
                uint32_t h0, l0, h1, l1;
                split_h_pack(v00, v01, h0, l0); split_h_pack(v10, v11, h1, l1);
                *(uint32_t*)(Ch + o0) = h0; *(uint32_t*)(Cl + o0) = l0;
                *(uint32_t*)(Ch + o1) = h1; *(uint32_t*)(Cl + o1) = l1;
            }
        }
    }
}

// ---------------- fp32 -> bf16 split (elementwise) -----------------------------
__global__ void __launch_bounds__(256)
split_kernel(const float* __restrict__ in, u16* __restrict__ oh, u16* __restrict__ ol,
             long long n)
{
    long long i = ((long long)blockIdx.x * 256 + threadIdx.x) * 4;
    if (i >= n) return;
    float4 v = *(const float4*)(in + i);
    uint32_t h0, l0, h1, l1;
    split_bf_pack(v.x, v.y, h0, l0); split_bf_pack(v.z, v.w, h1, l1);
    *(uint32_t*)(oh + i) = h0; *(uint32_t*)(oh + i + 2) = h1;
    *(uint32_t*)(ol + i) = l0; *(uint32_t*)(ol + i + 2) = l1;
}

// ---------------- fp32 transpose -> bf16 split ---------------------------------
__global__ void __launch_bounds__(256)
transpose_split_kernel(const float* __restrict__ in, u16* __restrict__ oh,
                       u16* __restrict__ ol, int ldin, int ldout,
                       long long sIn, long long sOut)
{
    __shared__ float t[32][33];
    const float* ip = in + blockIdx.z * sIn;
    const int c0 = blockIdx.x * 32, r0 = blockIdx.y * 32;
#pragma unroll
    for (int i = 0; i < 4; i++) {
        int r = threadIdx.y + i * 8;
        t[r][threadIdx.x] = ip[(long long)(r0 + r) * ldin + c0 + threadIdx.x];
    }
    __syncthreads();
#pragma unroll
    for (int i = 0; i < 4; i++) {
        int c = threadIdx.y + i * 8;
        float v = t[threadIdx.x][c];
        long long o = blockIdx.z * sOut + (long long)(c0 + c) * ldout + r0 + threadIdx.x;
        u16 h = bf16_bits(v);
        oh[o] = h; ol[o] = bf16_bits(v - bf16_val(h));
    }
}

// ---------------- fp32 transpose -> fp16 single --------------------------------
__global__ void __launch_bounds__(256)
transpose_half_kernel(const float* __restrict__ in, u16* __restrict__ out,
                      int ldin, int ldout, long long sIn, long long sOut)
{
    __shared__ float t[32][33];
    const float* ip = in + blockIdx.z * sIn;
    const int c0 = blockIdx.x * 32, r0 = blockIdx.y * 32;
#pragma unroll
    for (int i = 0; i < 4; i++) {
        int r = threadIdx.y + i * 8;
        t[r][threadIdx.x] = ip[(long long)(r0 + r) * ldin + c0 + threadIdx.x];
    }
    __syncthreads();
#pragma unroll
    for (int i = 0; i < 4; i++) {
        int c = threadIdx.y + i * 8;
        long long o = blockIdx.z * sOut + (long long)(c0 + c) * ldout + r0 + threadIdx.x;
        out[o] = h16_bits(t[threadIdx.x][c]);
    }
}

// ---------------- rmsnorm(latent) + RoPE ---------------------------------------
__global__ void __launch_bounds__(256)
prep_kernel(const float* __restrict__ cosp, const float* __restrict__ sinp,
            const float* __restrict__ normw)
{
    const int s = blockIdx.x;
    const int tid = threadIdx.x;
    const float* kv = g_kv + (long long)s * D;
    float* kf = g_kfull + (long long)s * D;

    float ss = 0.f;
    for (int i = tid; i < KVR; i += 256) { float v = kv[i]; ss += v * v; }
    __shared__ float red[32];
#pragma unroll
    for (int o = 16; o > 0; o >>= 1) ss += __shfl_xor_sync(0xffffffffu, ss, o);
    if ((tid & 31) == 0) red[tid >> 5] = ss;
    __syncthreads();
    if (tid < 32) {
        float v = (tid < 8) ? red[tid] : 0.f;
#pragma unroll
        for (int o = 16; o > 0; o >>= 1) v += __shfl_xor_sync(0xffffffffu, v, o);
        if (tid == 0) red[0] = v;
    }
    __syncthreads();
    const float r = rsqrtf(red[0] / (float)KVR + EPS);

    for (int i = tid; i < KVR; i += 256) {
        float v = kv[i] * r * normw[i];
        kf[i] = v;
        u16 h = bf16_bits(v);
        g_kfh[(long long)s * D + i] = h;
        g_kfl[(long long)s * D + i] = bf16_bits(v - bf16_val(h));
    }

    const float* cs = cosp + (long long)s * ROPE;
    const float* sn = sinp + (long long)s * ROPE;

    for (int i = tid; i < ROPE; i += 256) {
        float v = kv[KVR + i];
        float rot = (i < 32) ? -kv[KVR + i + 32] : kv[KVR + i - 32];
        float w = v * cs[i] + rot * sn[i];
        kf[KVR + i] = w;
        u16 h = bf16_bits(w);
        g_kfh[(long long)s * D + KVR + i] = h;
        g_kfl[(long long)s * D + KVR + i] = bf16_bits(w - bf16_val(h));
    }
    for (int idx = tid; idx < H * ROPE; idx += 256) {
        int h = idx >> 6, i = idx & 63;
        const float* qp = g_q + (long long)s * (H * QD) + h * QD + NOPE;
        float v = qp[i];
        float rot = (i < 32) ? -qp[i + 32] : qp[i - 32];
        float w = v * cs[i] + rot * sn[i];
        long long o = (long long)h * S * D + (long long)s * D + KVR + i;
        u16 hb = bf16_bits(w);
        g_qfh[o] = hb;
        g_qfl[o] = bf16_bits(w - bf16_val(hb));
    }
}

// ---------------- causal row softmax (fp32 in -> fp16 split out) ---------------
__global__ void __launch_bounds__(256)
softmax_kernel()
{
    const int s = blockIdx.x, h = blockIdx.y;
    const float* row = g_p + ((long long)h * S + s) * S;
    u16* ph = g_ph16 + ((long long)h * S + s) * S;
    u16* pl = g_pl16 + ((long long)h * S + s) * S;
    __shared__ float sh[S];
    __shared__ float red[33];
    const int n = s + 1;
    const int tid = threadIdx.x;

    float mx = -3.0e38f;
    for (int t = tid; t < n; t += 256) { float v = row[t]; sh[t] = v; mx = fmaxf(mx, v); }
#pragma unroll
    for (int o = 16; o > 0; o >>= 1) mx = fmaxf(mx, __shfl_xor_sync(0xffffffffu, mx, o));
    if ((tid & 31) == 0) red[tid >> 5] = mx;
    __syncthreads();
    if (tid < 32) {
        float v = (tid < 8) ? red[tid] : -3.0e38f;
#pragma unroll
        for (int o = 16; o > 0; o >>= 1) v = fmaxf(v, __shfl_xor_sync(0xffffffffu, v, o));
        if (tid == 0) red[32] = v;
    }
    __syncthreads();
    mx = red[32];

    float sum = 0.f;
    for (int t = tid; t < n; t += 256) { float e = expf(sh[t] - mx); sh[t] = e; sum += e; }
#pragma unroll
    for (int o = 16; o > 0; o >>= 1) sum += __shfl_xor_sync(0xffffffffu, sum, o);
    if ((tid & 31) == 0) red[tid >> 5] = sum;
    __syncthreads();
    if (tid < 32) {
        float v = (tid < 8) ? red[tid] : 0.f;
#pragma unroll
        for (int o = 16; o > 0; o >>= 1) v += __shfl_xor_sync(0xffffffffu, v, o);
        if (tid == 0) red[32] = v;
    }
    __syncthreads();
    const float inv = 1.0f / red[32];

    for (int t = tid; t < n; t += 256) {
        float v = sh[t] * inv;
        u16 hb = h16_bits(v);
        ph[t] = hb;
        pl[t] = h16_bits(v - h16_val(hb));
    }
    for (int t = n + tid; t < S; t += 256) { ph[t] = 0; pl[t] = 0; }
}

// ---------------- launch --------------------------------------------------------
extern "C" void kernel_launch(void* const* d_in, const int* in_sizes, int n_in,
                              void* d_out, int out_size)
{
    (void)in_sizes; (void)n_in; (void)out_size;
    const float* x      = (const float*)d_in[0];
    const float* cosp   = (const float*)d_in[1];
    const float* sinp   = (const float*)d_in[2];
    const float* w_q    = (const float*)d_in[3];
    const float* w_kv_a = (const float*)d_in[4];
    const float* normw  = (const float*)d_in[5];
    const float* kc     = (const float*)d_in[6];
    const float* vc     = (const float*)d_in[7];
    const float* w_o    = (const float*)d_in[8];
    float* out = (float*)d_out;

    float *q, *kv, *kf, *p;
    u16 *xh, *xl, *qh, *ql, *qfh, *qfl, *kfh, *kfl;
    u16 *wqTh, *wqTl, *wkvaTh, *wkvaTl, *kcTh, *kcTl;
    u16 *ph16, *pl16, *aoh16, *aol16, *ovh16, *ovl16, *latT16, *vcT16, *woT16;
    cudaGetSymbolAddress((void**)&q,  g_q);
    cudaGetSymbolAddress((void**)&kv, g_kv);
    cudaGetSymbolAddress((void**)&kf, g_kfull);
    cudaGetSymbolAddress((void**)&p,  g_p);
    cudaGetSymbolAddress((void**)&xh, g_xh);   cudaGetSymbolAddress((void**)&xl, g_xl);
    cudaGetSymbolAddress((void**)&qh, g_qh);   cudaGetSymbolAddress((void**)&ql, g_ql);
    cudaGetSymbolAddress((void**)&qfh, g_qfh); cudaGetSymbolAddress((void**)&qfl, g_qfl);
    cudaGetSymbolAddress((void**)&kfh, g_kfh); cudaGetSymbolAddress((void**)&kfl, g_kfl);
    cudaGetSymbolAddress((void**)&wqTh, g_wqTh);     cudaGetSymbolAddress((void**)&wqTl, g_wqTl);
    cudaGetSymbolAddress((void**)&wkvaTh, g_wkvaTh); cudaGetSymbolAddress((void**)&wkvaTl, g_wkvaTl);
    cudaGetSymbolAddress((void**)&kcTh, g_kcTh);     cudaGetSymbolAddress((void**)&kcTl, g_kcTl);
    cudaGetSymbolAddress((void**)&ph16, g_ph16);     cudaGetSymbolAddress((void**)&pl16, g_pl16);
    cudaGetSymbolAddress((void**)&aoh16, g_aoh16);   cudaGetSymbolAddress((void**)&aol16, g_aol16);
    cudaGetSymbolAddress((void**)&ovh16, g_ovh16);   cudaGetSymbolAddress((void**)&ovl16, g_ovl16);
    cudaGetSymbolAddress((void**)&latT16, g_latT16);
    cudaGetSymbolAddress((void**)&vcT16, g_vcT16);
    cudaGetSymbolAddress((void**)&woT16, g_woT16);

    const int SM_M0_128 = 2 * (20480 + 2 * 128 * 80);  // 81920
    const int SM_M0_64  = 2 * (20480 + 2 * 64 * 80);   // 61440
    const int SM_M1_128 = 2 * (20480 + 128 * 80);      // 61440
    cudaFuncSetAttribute(mma_gemm<128, 0, 0>, cudaFuncAttributeMaxDynamicSharedMemorySize, SM_M0_128);
    cudaFuncSetAttribute(mma_gemm<128, 0, 1>, cudaFuncAttributeMaxDynamicSharedMemorySize, SM_M0_128);
    cudaFuncSetAttribute(mma_gemm<128, 0, 2>, cudaFuncAttributeMaxDynamicSharedMemorySize, SM_M0_128);
    cudaFuncSetAttribute(mma_gemm<64, 0, 0>,  cudaFuncAttributeMaxDynamicSharedMemorySize, SM_M0_64);
    cudaFuncSetAttribute(mma_gemm<128, 1, 0>, cudaFuncAttributeMaxDynamicSharedMemorySize, SM_M1_128);
    cudaFuncSetAttribute(mma_gemm<128, 1, 3>, cudaFuncAttributeMaxDynamicSharedMemorySize, SM_M1_128);

    dim3 tb(32, 8);

    // [0] split x
    split_kernel<<<(S * HID) / 1024, 256>>>(x, xh, xl, (long long)S * HID);
    // [1..3] bf16 split transposes
    transpose_split_kernel<<<dim3((H * QD) / 32, HID / 32, 1), tb>>>(w_q, wqTh, wqTl, H * QD, HID, 0, 0);
    transpose_split_kernel<<<dim3(D / 32, HID / 32, 1), tb>>>(w_kv_a, wkvaTh, wkvaTl, D, HID, 0, 0);
    transpose_split_kernel<<<dim3(KVR / 32, NOPE / 32, H), tb>>>(kc, kcTh, kcTl, KVR, NOPE,
        (long long)NOPE * KVR, (long long)NOPE * KVR);
    // [4] vc^T fp16
    transpose_half_kernel<<<dim3(VH / 32, KVR / 32, H), tb>>>(vc, vcT16, VH, KVR,
        (long long)KVR * VH, (long long)KVR * VH);

    // [5] q = x @ w_q  (profiled by ncu -s 5)
    mma_gemm<128, 0, 2><<<dim3((H * QD) / 128, S / 128, 1), 256, SM_M0_128>>>(
        xh, xl, wqTh, wqTl, q, qh, ql, HID, HID, HID, H * QD, 0, 0, 0, 1.0f, 0);

    // [6] w_o^T fp16
    transpose_half_kernel<<<dim3(HID / 32, (H * VH) / 32, 1), tb>>>(w_o, woT16, HID, H * VH, 0, 0);

    // [7] kv = x @ w_kv_a
    mma_gemm<64, 0, 0><<<dim3(D / 64, S / 128, 1), 256, SM_M0_64>>>(
        xh, xl, wkvaTh, wkvaTl, kv, nullptr, nullptr, HID, HID, HID, D, 0, 0, 0, 1.0f, 0);

    // [8] rmsnorm + rope
    prep_kernel<<<S, 256>>>(cosp, sinp, normw);

    // [9] latent^T fp16 [KVR, S]
    transpose_half_kernel<<<dim3(KVR / 32, S / 32, 1), tb>>>(kf, latT16, D, S, 0, 0);

    // [10] q_nope @ kc -> qfull[:, :512] bf16 split (per head)
    mma_gemm<128, 0, 1><<<dim3(KVR / 128, S / 128, H), 256, SM_M0_128>>>(
        qh, ql, kcTh, kcTl, nullptr, qfh, qfl, NOPE, H * QD, NOPE, D,
        (long long)QD, (long long)KVR * NOPE, (long long)S * D, 1.0f, 0);

    // [11] scores = SCALE * qfull @ kfull^T  (causal tile skip, fp32)
    mma_gemm<128, 0, 0><<<dim3(S / 128, S / 128, H), 256, SM_M0_128>>>(
        qfh, qfl, kfh, kfl, p, nullptr, nullptr, D, D, D, S,
        (long long)S * D, 0LL, (long long)S * S, SCALE, 1);

    // [12] softmax -> P fp16 split
    softmax_kernel<<<dim3(S, H), 256>>>();

    // [13] ao = P @ latent  (fp16 2-term, K truncated)
    mma_gemm<128, 1, 3><<<dim3(KVR / 128, S / 128, H), 256, SM_M1_128>>>(
        ph16, pl16, latT16, nullptr, nullptr, aoh16, aol16, S, S, S, KVR,
        (long long)S * S, 0LL, (long long)S * KVR, 1.0f, 2);

    // [14] ov = ao @ vc  (fp16 2-term, per head)
    mma_gemm<128, 1, 3><<<dim3(VH / 128, S / 128, H), 256, SM_M1_128>>>(
        aoh16, aol16, vcT16, nullptr, nullptr, ovh16, ovl16, KVR, KVR, KVR, H * VH,
        (long long)S * KVR, (long long)VH * KVR, (long long)VH, 1.0f, 0);

    // [15] out = ov @ w_o  (fp16 2-term, fp32 out)
    mma_gemm<128, 1, 0><<<dim3(HID / 128, S / 128, 1), 256, SM_M1_128>>>(
        ovh16, ovl16, woT16, nullptr, out, nullptr, nullptr, H * VH, H * VH, H * VH, HID,
        0, 0, 0, 1.0f, 0);
}

// round 11
// speedup vs baseline: 3.0990x; 1.3000x over previous
#include <cuda_runtime.h>
#include <cuda_fp16.h>
#include <cstdint>
#include <cstring>

#define S    2048
#define HID  2048
#define H    16
#define NOPE 128
#define ROPE 64
#define QD   192   // NOPE+ROPE
#define KVR  512
#define D    576   // KVR+ROPE
#define VH   128
#define SCALE 0.07216878364870323f
#define EPS  1e-6f

typedef unsigned short u16;

// ---------------- scratch (device globals) ------------------------------------
__device__ float g_q[(long long)S * H * QD];        // fp32 (prep reads q_pe)
__device__ float g_kv[(long long)S * D];
__device__ float g_kfull[(long long)S * D];
__device__ float g_p[(long long)H * S * S];         // scores fp32
// fp16 split pairs (A operands)
__device__ u16 g_xh[(long long)S * HID],      g_xl[(long long)S * HID];
__device__ u16 g_qh[(long long)S * H * QD],   g_ql[(long long)S * H * QD];
__device__ u16 g_qfh[(long long)H * S * D],   g_qfl[(long long)H * S * D];
__device__ u16 g_ph[(long long)H * S * S],    g_pl[(long long)H * S * S];
__device__ u16 g_aoh[(long long)H * S * KVR], g_aol[(long long)H * S * KVR];
__device__ u16 g_ovh[(long long)S * H * VH],  g_ovl[(long long)S * H * VH];
// fp16 single (B operands, K-major)
__device__ u16 g_wqT16[(long long)(H * QD) * HID];
__device__ u16 g_wkvaT16[(long long)D * HID];
__device__ u16 g_kcT16[(long long)H * KVR * NOPE];
__device__ u16 g_kf16[(long long)S * D];
__device__ u16 g_latT16[(long long)KVR * S];
__device__ u16 g_vcT16[(long long)H * VH * KVR];
__device__ u16 g_woT16[(long long)HID * (H * VH)];

// ---------------- helpers -----------------------------------------------------
__device__ __forceinline__ uint32_t smem_u32(const void* p) {
    uint32_t a;
    asm("{ .reg .u64 t; cvta.to.shared.u64 t, %1; cvt.u32.u64 %0, t; }" : "=r"(a) : "l"(p));
    return a;
}
__device__ __forceinline__ u16 h16_bits(float v) {
    __half b = __float2half_rn(v); u16 u; memcpy(&u, &b, 2); return u;
}
__device__ __forceinline__ float h16_val(u16 u) {
    __half b; memcpy(&b, &u, 2); return __half2float(b);
}
__device__ __forceinline__ void split_h_pack(float x, float y, uint32_t& h, uint32_t& l) {
    __half2 hv = __floats2half2_rn(x, y);
    __half2 lv = __floats2half2_rn(x - __half2float(__low2half(hv)),
                                   y - __half2float(__high2half(hv)));
    memcpy(&h, &hv, 4); memcpy(&l, &lv, 4);
}

#define CP_ASYNC16(dst, src) \
    asm volatile("cp.async.cg.shared.global [%0], [%1], 16;" :: "r"(dst), "l"(src))
#define CP_COMMIT() asm volatile("cp.async.commit_group;" ::: "memory")
#define CP_WAIT(n)  asm volatile("cp.async.wait_group %0;" :: "n"(n) : "memory")

#define LDMX4(r0, r1, r2, r3, addr) \
    asm volatile("ldmatrix.sync.aligned.m8n8.x4.shared.b16 {%0,%1,%2,%3}, [%4];" \
        : "=r"(r0), "=r"(r1), "=r"(r2), "=r"(r3) : "r"(addr))

#define MMA_F16(d, a, b0v, b1v) \
    asm volatile("mma.sync.aligned.m16n8k16.row.col.f32.f16.f16.f32 " \
        "{%0,%1,%2,%3}, {%4,%5,%6,%7}, {%8,%9}, {%0,%1,%2,%3};" \
        : "+f"((d)[0]), "+f"((d)[1]), "+f"((d)[2]), "+f"((d)[3]) \
        : "r"((a)[0]), "r"((a)[1]), "r"((a)[2]), "r"((a)[3]), "r"(b0v), "r"(b1v))

// ---------------- fp16 2-term mma.sync GEMM ------------------------------------
// C[M,N] = alpha * A[M,K] @ B[N,K]^T. A = fp16 hi/lo pair, B = fp16 single, K-major.
// Block tile 128 x NT x 32; 8 warps = 2(m) x 4(n). 2 MMAs per frag pair.
// EPI: 0 = fp32 C; 1 = fp16 split (Ch,Cl); 2 = fp32 + fp16 split.
// causal_mode: 0 none; 1 skip colbase>=rowbase+128; 2 kmax=rowbase+128.
template<int NT, int EPI>
__global__ void __launch_bounds__(256)
mma_gemm(const u16* __restrict__ Agh, const u16* __restrict__ Agl,
         const u16* __restrict__ Bg,
         float* __restrict__ C, u16* __restrict__ Ch, u16* __restrict__ Cl,
         int K, int lda, int ldb, int ldc,
         long long sA, long long sB, long long sC, float alpha, int causal_mode)
{
    constexpr int WTN = NT / 4, NFRAG = WTN / 8, MFRAG = 4;
    constexpr int OFF_AL = 10240, OFF_B = 20480;
    constexpr int BUFB = 20480 + NT * 80;
    constexpr int BC = (NT * 4) / 256;

    const int rowbase = blockIdx.y * 128;
    const int colbase = blockIdx.x * NT;
    if (causal_mode == 1 && colbase >= rowbase + 128) return;
    const int kmax = (causal_mode == 2) ? min(K, rowbase + 128) : K;
    const int nk = kmax >> 5;

    Agh += blockIdx.z * sA; Agl += blockIdx.z * sA;
    Bg += blockIdx.z * sB;

    extern __shared__ char smem[];
    const uint32_t sb = smem_u32(smem);
    const int tid = threadIdx.x, wid = tid >> 5, lane = tid & 31;
    const int wm = wid >> 2, wn = wid & 3;
    const int lr = lane >> 2, lc = lane & 3;

    float acc[MFRAG][NFRAG][4];
#pragma unroll
    for (int i = 0; i < MFRAG; i++)
#pragma unroll
        for (int j = 0; j < NFRAG; j++)
#pragma unroll
            for (int q = 0; q < 4; q++) acc[i][j][q] = 0.f;

    auto issue_tile = [&](int kt, int buf) {
        const uint32_t base = sb + buf * BUFB;
        const int k0 = kt << 5;
#pragma unroll
        for (int i = 0; i < 2; i++) {
            int idx = tid + i * 256, r = idx >> 2, c = idx & 3;
            long long g = (long long)(rowbase + r) * lda + k0 + c * 8;
            uint32_t so = (uint32_t)(r * 80 + c * 16);
            CP_ASYNC16(base + so, Agh + g);
            CP_ASYNC16(base + OFF_AL + so, Agl + g);
        }
#pragma unroll
        for (int i = 0; i < BC; i++) {
            int idx = tid + i * 256, r = idx >> 2, c = idx & 3;
            long long g = (long long)(colbase + r) * ldb + k0 + c * 8;
            uint32_t so = (uint32_t)(r * 80 + c * 16);
            CP_ASYNC16(base + OFF_B + so, Bg + g);
        }
        CP_COMMIT();
    };

    issue_tile(0, 0);

    for (int kt = 0; kt < nk; kt++) {
        CP_WAIT(0);
        __syncthreads();
        if (kt + 1 < nk) issue_tile(kt + 1, (kt + 1) & 1);   // overlaps with compute

        const uint32_t base = sb + (kt & 1) * BUFB;
        uint32_t bh[NFRAG][4];
#pragma unroll
        for (int nf = 0; nf < NFRAG; nf++) {
            int n = wn * WTN + nf * 8 + (lane & 7);
            uint32_t ad = base + OFF_B + n * 80 + (lane >> 3) * 16;
            LDMX4(bh[nf][0], bh[nf][1], bh[nf][2], bh[nf][3], ad);
        }
#pragma unroll
        for (int ks = 0; ks < 2; ks++) {
#pragma unroll
            for (int mf = 0; mf < MFRAG; mf++) {
                int r = wm * 64 + mf * 16 + (lane & 15);
                uint32_t ad = base + r * 80 + (lane >> 4) * 16 + ks * 32;
                uint32_t ah[4], al[4];
                LDMX4(ah[0], ah[1], ah[2], ah[3], ad);
                LDMX4(al[0], al[1], al[2], al[3], ad + OFF_AL);
#pragma unroll
                for (int nf = 0; nf < NFRAG; nf++) {
                    MMA_F16(acc[mf][nf], ah, bh[nf][2 * ks], bh[nf][2 * ks + 1]);
                    MMA_F16(acc[mf][nf], al, bh[nf][2 * ks], bh[nf][2 * ks + 1]);
                }
            }
        }
    }

    // ---- epilogue
#pragma unroll
    for (int mf = 0; mf < MFRAG; mf++) {
        int r0 = rowbase + wm * 64 + mf * 16 + lr;
#pragma unroll
        for (int nf = 0; nf < NFRAG; nf++) {
            int c0 = colbase + wn * WTN + nf * 8 + lc * 2;
            float v00 = acc[mf][nf][0] * alpha, v01 = acc[mf][nf][1] * alpha;
            float v10 = acc[mf][nf][2] * alpha, v11 = acc[mf][nf][3] * alpha;
            long long o0 = (long long)r0 * ldc + c0 + blockIdx.z * sC;
            long long o1 = (long long)(r0 + 8) * ldc + c0 + blockIdx.z * sC;
            if (EPI == 0 || EPI == 2) {
                *(float2*)(C + o0) = make_float2(v00, v01);
                *(float2*)(C + o1) = make_float2(v10, v11);
            }
            if (EPI == 1 || EPI == 2) {
                uint32_t h0, l0, h1, l1;
                split_h_pack(v00, v01, h0, l0); split_h_pack(v10, v11, h1, l1);
                *(uint32_t*)(Ch + o0) = h0; *(uint32_t*)(Cl + o0) = l0;
                *(uint32_t*)(Ch + o1) = h1; *(uint32_t*)(Cl + o1) = l1;
            }
        }
    }
}

// ---------------- fp32 -> fp16 split (elementwise) -----------------------------
__global__ void __launch_bounds__(256)
split_kernel(const float* __restrict__ in, u16* __restrict__ oh, u16* __restrict__ ol,
             long long n)
{
    long long i = ((long long)blockIdx.x * 256 + threadIdx.x) * 4;
    if (i >= n) return;
    float4 v = *(const float4*)(in + i);
    uint32_t h0, l0, h1, l1;
    split_h_pack(v.x, v.y, h0, l0); split_h_pack(v.z, v.w, h1, l1);
    *(uint32_t*)(oh + i) = h0; *(uint32_t*)(oh + i + 2) = h1;
    *(uint32_t*)(ol + i) = l0; *(uint32_t*)(ol + i + 2) = l1;
}

// ---------------- fp32 transpose -> fp16 single --------------------------------
__global__ void __launch_bounds__(256)
transpose_half_kernel(const float* __restrict__ in, u16* __restrict__ out,
                      int ldin, int ldout, long long sIn, long long sOut)
{
    __shared__ float t[32][33];
    const float* ip = in + blockIdx.z * sIn;
    const int c0 = blockIdx.x * 32, r0 = blockIdx.y * 32;
#pragma unroll
    for (int i = 0; i < 4; i++) {
        int r = threadIdx.y + i * 8;
        t[r][threadIdx.x] = ip[(long long)(r0 + r) * ldin + c0 + threadIdx.x];
    }
    __syncthreads();
#pragma unroll
    for (int i = 0; i < 4; i++) {
        int c = threadIdx.y + i * 8;
        long long o = blockIdx.z * sOut + (long long)(c0 + c) * ldout + r0 + threadIdx.x;
        out[o] = h16_bits(t[threadIdx.x][c]);
    }
}

// ---------------- rmsnorm(latent) + RoPE ---------------------------------------
__global__ void __launch_bounds__(256)
prep_kernel(const float* __restrict__ cosp, const float* __restrict__ sinp,
            const float* __restrict__ normw)
{
    const int s = blockIdx.x;
    const int tid = threadIdx.x;
    const float* kv = g_kv + (long long)s * D;
    float* kf = g_kfull + (long long)s * D;

    float ss = 0.f;
    for (int i = tid; i < KVR; i += 256) { float v = kv[i]; ss += v * v; }
    __shared__ float red[32];
#pragma unroll
    for (int o = 16; o > 0; o >>= 1) ss += __shfl_xor_sync(0xffffffffu, ss, o);
    if ((tid & 31) == 0) red[tid >> 5] = ss;
    __syncthreads();
    if (tid < 32) {
        float v = (tid < 8) ? red[tid] : 0.f;
#pragma unroll
        for (int o = 16; o > 0; o >>= 1) v += __shfl_xor_sync(0xffffffffu, v, o);
        if (tid == 0) red[0] = v;
    }
    __syncthreads();
    const float r = rsqrtf(red[0] / (float)KVR + EPS);

    for (int i = tid; i < KVR; i += 256) {
        float v = kv[i] * r * normw[i];
        kf[i] = v;
        g_kf16[(long long)s * D + i] = h16_bits(v);
    }

    const float* cs = cosp + (long long)s * ROPE;
    const float* sn = sinp + (long long)s * ROPE;

    for (int i = tid; i < ROPE; i += 256) {
        float v = kv[KVR + i];
        float rot = (i < 32) ? -kv[KVR + i + 32] : kv[KVR + i - 32];
        float w = v * cs[i] + rot * sn[i];
        kf[KVR + i] = w;
        g_kf16[(long long)s * D + KVR + i] = h16_bits(w);
    }
    for (int idx = tid; idx < H * ROPE; idx += 256) {
        int h = idx >> 6, i = idx & 63;
        const float* qp = g_q + (long long)s * (H * QD) + h * QD + NOPE;
        float v = qp[i];
        float rot = (i < 32) ? -qp[i + 32] : qp[i - 32];
        float w = v * cs[i] + rot * sn[i];
        long long o = (long long)h * S * D + (long long)s * D + KVR + i;
        u16 hb = h16_bits(w);
        g_qfh[o] = hb;
        g_qfl[o] = h16_bits(w - h16_val(hb));
    }
}

// ---------------- causal row softmax (fp32 in -> fp16 split out) ---------------
// Zero-fill only up to the 128-aligned tile boundary (stage 7 truncates K there).
__global__ void __launch_bounds__(256)
softmax_kernel()
{
    const int s = blockIdx.x, h = blockIdx.y;
    const float* row = g_p + ((long long)h * S + s) * S;
    u16* ph = g_ph + ((long long)h * S + s) * S;
    u16* pl = g_pl + ((long long)h * S + s) * S;
    __shared__ float sh[S];
    __shared__ float red[33];
    const int n = s + 1;
    const int nz = ((s >> 7) + 1) << 7;   // round_up(n,128)
    const int tid = threadIdx.x;

    float mx = -3.0e38f;
    for (int t = tid; t < n; t += 256) { float v = row[t]; sh[t] = v; mx = fmaxf(mx, v); }
#pragma unroll
    for (int o = 16; o > 0; o >>= 1) mx = fmaxf(mx, __shfl_xor_sync(0xffffffffu, mx, o));
    if ((tid & 31) == 0) red[tid >> 5] = mx;
    __syncthreads();
    if (tid < 32) {
        float v = (tid < 8) ? red[tid] : -3.0e38f;
#pragma unroll
        for (int o = 16; o > 0; o >>= 1) v = fmaxf(v, __shfl_xor_sync(0xffffffffu, v, o));
        if (tid == 0) red[32] = v;
    }
    __syncthreads();
    mx = red[32];

    float sum = 0.f;
    for (int t = tid; t < n; t += 256) { float e = expf(sh[t] - mx); sh[t] = e; sum += e; }
#pragma unroll
    for (int o = 16; o > 0; o >>= 1) sum += __shfl_xor_sync(0xffffffffu, sum, o);
    if ((tid & 31) == 0) red[tid >> 5] = sum;
    __syncthreads();
    if (tid < 32) {
        float v = (tid < 8) ? red[tid] : 0.f;
#pragma unroll
        for (int o = 16; o > 0; o >>= 1) v += __shfl_xor_sync(0xffffffffu, v, o);
        if (tid == 0) red[32] = v;
    }
    __syncthreads();
    const float inv = 1.0f / red[32];

    for (int t = tid; t < n; t += 256) {
        float v = sh[t] * inv;
        u16 hb = h16_bits(v);
        ph[t] = hb;
        pl[t] = h16_bits(v - h16_val(hb));
    }
    for (int t = n + tid; t < nz; t += 256) { ph[t] = 0; pl[t] = 0; }
}

// ---------------- launch --------------------------------------------------------
extern "C" void kernel_launch(void* const* d_in, const int* in_sizes, int n_in,
                              void* d_out, int out_size)
{
    (void)in_sizes; (void)n_in; (void)out_size;
    const float* x      = (const float*)d_in[0];
    const float* cosp   = (const float*)d_in[1];
    const float* sinp   = (const float*)d_in[2];
    const float* w_q    = (const float*)d_in[3];
    const float* w_kv_a = (const float*)d_in[4];
    const float* normw  = (const float*)d_in[5];
    const float* kc     = (const float*)d_in[6];
    const float* vc     = (const float*)d_in[7];
    const float* w_o    = (const float*)d_in[8];
    float* out = (float*)d_out;

    float *q, *kv, *kf, *p;
    u16 *xh, *xl, *qh, *ql, *qfh, *qfl, *ph, *pl, *aoh, *aol, *ovh, *ovl;
    u16 *wqT16, *wkvaT16, *kcT16, *kf16, *latT16, *vcT16, *woT16;
    cudaGetSymbolAddress((void**)&q,  g_q);
    cudaGetSymbolAddress((void**)&kv, g_kv);
    cudaGetSymbolAddress((void**)&kf, g_kfull);
    cudaGetSymbolAddress((void**)&p,  g_p);
    cudaGetSymbolAddress((void**)&xh, g_xh);   cudaGetSymbolAddress((void**)&xl, g_xl);
    cudaGetSymbolAddress((void**)&qh, g_qh);   cudaGetSymbolAddress((void**)&ql, g_ql);
    cudaGetSymbolAddress((void**)&qfh, g_qfh); cudaGetSymbolAddress((void**)&qfl, g_qfl);
    cudaGetSymbolAddress((void**)&ph, g_ph);   cudaGetSymbolAddress((void**)&pl, g_pl);
    cudaGetSymbolAddress((void**)&aoh, g_aoh); cudaGetSymbolAddress((void**)&aol, g_aol);
    cudaGetSymbolAddress((void**)&ovh, g_ovh); cudaGetSymbolAddress((void**)&ovl, g_ovl);
    cudaGetSymbolAddress((void**)&wqT16, g_wqT16);
    cudaGetSymbolAddress((void**)&wkvaT16, g_wkvaT16);
    cudaGetSymbolAddress((void**)&kcT16, g_kcT16);
    cudaGetSymbolAddress((void**)&kf16, g_kf16);
    cudaGetSymbolAddress((void**)&latT16, g_latT16);
    cudaGetSymbolAddress((void**)&vcT16, g_vcT16);
    cudaGetSymbolAddress((void**)&woT16, g_woT16);

    const int SM_128 = 2 * (20480 + 128 * 80);  // 61440
    const int SM_64  = 2 * (20480 + 64 * 80);   // 51200
    cudaFuncSetAttribute(mma_gemm<128, 0>, cudaFuncAttributeMaxDynamicSharedMemorySize, SM_128);
    cudaFuncSetAttribute(mma_gemm<128, 1>, cudaFuncAttributeMaxDynamicSharedMemorySize, SM_128);
    cudaFuncSetAttribute(mma_gemm<128, 2>, cudaFuncAttributeMaxDynamicSharedMemorySize, SM_128);
    cudaFuncSetAttribute(mma_gemm<64, 0>,  cudaFuncAttributeMaxDynamicSharedMemorySize, SM_64);

    dim3 tb(32, 8);

    // [0] split x to fp16 hi/lo
    split_kernel<<<(S * HID) / 1024, 256>>>(x, xh, xl, (long long)S * HID);
    // [1..4] weight transposes -> single fp16 K-major
    transpose_half_kernel<<<dim3((H * QD) / 32, HID / 32, 1), tb>>>(w_q, wqT16, H * QD, HID, 0, 0);
    transpose_half_kernel<<<dim3(D / 32, HID / 32, 1), tb>>>(w_kv_a, wkvaT16, D, HID, 0, 0);
    transpose_half_kernel<<<dim3(KVR / 32, NOPE / 32, H), tb>>>(kc, kcT16, KVR, NOPE,
        (long long)NOPE * KVR, (long long)NOPE * KVR);
    transpose_half_kernel<<<dim3(VH / 32, KVR / 32, H), tb>>>(vc, vcT16, VH, KVR,
        (long long)KVR * VH, (long long)KVR * VH);

    // [5] q = x @ w_q  (fp32 for prep rope + fp16 split for stage 4; ncu -s 5 target)
    mma_gemm<128, 2><<<dim3((H * QD) / 128, S / 128, 1), 256, SM_128>>>(
        xh, xl, wqT16, q, qh, ql, HID, HID, HID, H * QD, 0, 0, 0, 1.0f, 0);

    // [6] w_o^T fp16
    transpose_half_kernel<<<dim3(HID / 32, (H * VH) / 32, 1), tb>>>(w_o, woT16, HID, H * VH, 0, 0);

    // [7] kv = x @ w_kv_a (fp32)
    mma_gemm<64, 0><<<dim3(D / 64, S / 128, 1), 256, SM_64>>>(
        xh, xl, wkvaT16, kv, nullptr, nullptr, HID, HID, HID, D, 0, 0, 0, 1.0f, 0);

    // [8] rmsnorm + rope (kf fp32 + fp16; qfull rope part fp16 split)
    prep_kernel<<<S, 256>>>(cosp, sinp, normw);

    // [9] latent^T fp16 [KVR, S]
    transpose_half_kernel<<<dim3(KVR / 32, S / 32, 1), tb>>>(kf, latT16, D, S, 0, 0);

    // [10] q_nope @ kc -> qfull[:, :512] fp16 split (per head)
    mma_gemm<128, 1><<<dim3(KVR / 128, S / 128, H), 256, SM_128>>>(
        qh, ql, kcT16, nullptr, qfh, qfl, NOPE, H * QD, NOPE, D,
        (long long)QD, (long long)KVR * NOPE, (long long)S * D, 1.0f, 0);

    // [11] scores = SCALE * qfull @ kfull^T  (causal tile skip, fp32)
    mma_gemm<128, 0><<<dim3(S / 128, S / 128, H), 256, SM_128>>>(
        qfh, qfl, kf16, p, nullptr, nullptr, D, D, D, S,
        (long long)S * D, 0LL, (long long)S * S, SCALE, 1);

    // [12] softmax -> P fp16 split (zero-fill to tile boundary only)
    softmax_kernel<<<dim3(S, H), 256>>>();

    // [13] ao = P @ latent  (K truncated at diagonal)
    mma_gemm<128, 1><<<dim3(KVR / 128, S / 128, H), 256, SM_128>>>(
        ph, pl, latT16, nullptr, aoh, aol, S, S, S, KVR,
        (long long)S * S, 0LL, (long long)S * KVR, 1.0f, 2);

    // [14] ov = ao @ vc  (per head)
    mma_gemm<128, 1><<<dim3(VH / 128, S / 128, H), 256, SM_128>>>(
        aoh, aol, vcT16, nullptr, ovh, ovl, KVR, KVR, KVR, H * VH,
        (long long)S * KVR, (long long)VH * KVR, (long long)VH, 1.0f, 0);

    // [15] out = ov @ w_o  (fp32 final)
    mma_gemm<128, 0><<<dim3(HID / 128, S / 128, 1), 256, SM_128>>>(
        ovh, ovl, woT16, out, nullptr, nullptr, H * VH, H * VH, H * VH, HID,
        0, 0, 0, 1.0f, 0);
}

// round 12
// speedup vs baseline: 3.8901x; 1.2553x over previous
#include <cuda_runtime.h>
#include <cuda_fp16.h>
#include <cstdint>
#include <cstring>

#define S    2048
#define HID  2048
#define H    16
#define NOPE 128
#define ROPE 64
#define QD   192   // NOPE+ROPE
#define KVR  512
#define D    576   // KVR+ROPE
#define VH   128
#define SCALE 0.07216878364870323f
#define EPS  1e-6f

typedef unsigned short u16;

// ---------------- scratch (device globals) ------------------------------------
__device__ float g_q[(long long)S * H * QD];        // fp32 (prep reads q_pe)
__device__ float g_kv[(long long)S * D];
__device__ float g_kfull[(long long)S * D];
__device__ float g_p[(long long)H * S * S];         // scores fp32
// fp16 split pairs (A operands of 2-term stages)
__device__ u16 g_qh[(long long)S * H * QD],   g_ql[(long long)S * H * QD];
__device__ u16 g_qfh[(long long)H * S * D],   g_qfl[(long long)H * S * D];
__device__ u16 g_ovh[(long long)S * H * VH],  g_ovl[(long long)S * H * VH];
// fp16 single
__device__ u16 g_x16[(long long)S * HID];           // x (A of q/kv, single)
__device__ u16 g_ph[(long long)H * S * S];          // P hi (A of 13, single)
__device__ u16 g_ao16[(long long)H * S * KVR];      // ao (A of 14, single)
// fp16 single B operands (K-major)
__device__ u16 g_wqT16[(long long)(H * QD) * HID];
__device__ u16 g_wkvaT16[(long long)D * HID];
__device__ u16 g_kcT16[(long long)H * KVR * NOPE];
__device__ u16 g_kf16[(long long)S * D];
__device__ u16 g_latT16[(long long)KVR * S];
__device__ u16 g_vcT16[(long long)H * VH * KVR];
__device__ u16 g_woT16[(long long)HID * (H * VH)];

// ---------------- helpers -----------------------------------------------------
__device__ __forceinline__ uint32_t smem_u32(const void* p) {
    uint32_t a;
    asm("{ .reg .u64 t; cvta.to.shared.u64 t, %1; cvt.u32.u64 %0, t; }" : "=r"(a) : "l"(p));
    return a;
}
__device__ __forceinline__ u16 h16_bits(float v) {
    __half b = __float2half_rn(v); u16 u; memcpy(&u, &b, 2); return u;
}
__device__ __forceinline__ float h16_val(u16 u) {
    __half b; memcpy(&b, &u, 2); return __half2float(b);
}
__device__ __forceinline__ void split_h_pack(float x, float y, uint32_t& h, uint32_t& l) {
    __half2 hv = __floats2half2_rn(x, y);
    __half2 lv = __floats2half2_rn(x - __half2float(__low2half(hv)),
                                   y - __half2float(__high2half(hv)));
    memcpy(&h, &hv, 4); memcpy(&l, &lv, 4);
}
__device__ __forceinline__ uint32_t h2_pack(float x, float y) {
    __half2 hv = __floats2half2_rn(x, y);
    uint32_t u; memcpy(&u, &hv, 4); return u;
}

#define CP_ASYNC16(dst, src) \
    asm volatile("cp.async.cg.shared.global [%0], [%1], 16;" :: "r"(dst), "l"(src))
#define CP_COMMIT() asm volatile("cp.async.commit_group;" ::: "memory")
#define CP_WAIT(n)  asm volatile("cp.async.wait_group %0;" :: "n"(n) : "memory")

#define LDMX4(r0, r1, r2, r3, addr) \
    asm volatile("ldmatrix.sync.aligned.m8n8.x4.shared.b16 {%0,%1,%2,%3}, [%4];" \
        : "=r"(r0), "=r"(r1), "=r"(r2), "=r"(r3) : "r"(addr))

#define MMA_F16(d, a, b0v, b1v) \
    asm volatile("mma.sync.aligned.m16n8k16.row.col.f32.f16.f16.f32 " \
        "{%0,%1,%2,%3}, {%4,%5,%6,%7}, {%8,%9}, {%0,%1,%2,%3};" \
        : "+f"((d)[0]), "+f"((d)[1]), "+f"((d)[2]), "+f"((d)[3]) \
        : "r"((a)[0]), "r"((a)[1]), "r"((a)[2]), "r"((a)[3]), "r"(b0v), "r"(b1v))

// ---------------- fp16 mma.sync GEMM -------------------------------------------
// C[M,N] = alpha * A[M,K] @ B[N,K]^T. B = fp16 single, K-major.
// MODE 0: A = fp16 hi/lo pair, 2 MMAs per frag. MODE 1: A = fp16 single, 1 MMA.
// Block tile 128 x NT x 32; 8 warps = 2(m) x 4(n).
// EPI: 0=fp32 C; 1=fp16 split (Ch,Cl); 2=fp32+fp16 split; 4=fp16 single (Ch).
// causal_mode: 0 none; 1 skip colbase>=rowbase+128; 2 kmax=rowbase+128.
template<int NT, int MODE, int EPI>
__global__ void __launch_bounds__(256)
mma_gemm(const u16* __restrict__ Agh, const u16* __restrict__ Agl,
         const u16* __restrict__ Bg,
         float* __restrict__ C, u16* __restrict__ Ch, u16* __restrict__ Cl,
         int K, int lda, int ldb, int ldc,
         long long sA, long long sB, long long sC, float alpha, int causal_mode)
{
    constexpr int WTN = NT / 4, NFRAG = WTN / 8, MFRAG = 4;
    constexpr int OFF_AL = 10240;
    constexpr int OFF_B = (MODE == 0) ? 20480 : 10240;
    constexpr int BUFB = OFF_B + NT * 80;
    constexpr int BC = (NT * 4) / 256;

    const int rowbase = blockIdx.y * 128;
    const int colbase = blockIdx.x * NT;
    if (causal_mode == 1 && colbase >= rowbase + 128) return;
    const int kmax = (causal_mode == 2) ? min(K, rowbase + 128) : K;
    const int nk = kmax >> 5;

    Agh += blockIdx.z * sA;
    if (MODE == 0) Agl += blockIdx.z * sA;
    Bg += blockIdx.z * sB;

    extern __shared__ char smem[];
    const uint32_t sb = smem_u32(smem);
    const int tid = threadIdx.x, wid = tid >> 5, lane = tid & 31;
    const int wm = wid >> 2, wn = wid & 3;
    const int lr = lane >> 2, lc = lane & 3;

    float acc[MFRAG][NFRAG][4];
#pragma unroll
    for (int i = 0; i < MFRAG; i++)
#pragma unroll
        for (int j = 0; j < NFRAG; j++)
#pragma unroll
            for (int q = 0; q < 4; q++) acc[i][j][q] = 0.f;

    auto issue_tile = [&](int kt, int buf) {
        const uint32_t base = sb + buf * BUFB;
        const int k0 = kt << 5;
#pragma unroll
        for (int i = 0; i < 2; i++) {
            int idx = tid + i * 256, r = idx >> 2, c = idx & 3;
            long long g = (long long)(rowbase + r) * lda + k0 + c * 8;
            uint32_t so = (uint32_t)(r * 80 + c * 16);
            CP_ASYNC16(base + so, Agh + g);
            if (MODE == 0) CP_ASYNC16(base + OFF_AL + so, Agl + g);
        }
#pragma unroll
        for (int i = 0; i < BC; i++) {
            int idx = tid + i * 256, r = idx >> 2, c = idx & 3;
            long long g = (long long)(colbase + r) * ldb + k0 + c * 8;
            uint32_t so = (uint32_t)(r * 80 + c * 16);
            CP_ASYNC16(base + OFF_B + so, Bg + g);
        }
        CP_COMMIT();
    };

    issue_tile(0, 0);

    for (int kt = 0; kt < nk; kt++) {
        CP_WAIT(0);
        __syncthreads();
        if (kt + 1 < nk) issue_tile(kt + 1, (kt + 1) & 1);   // overlaps with compute

        const uint32_t base = sb + (kt & 1) * BUFB;
        uint32_t bh[NFRAG][4];
#pragma unroll
        for (int nf = 0; nf < NFRAG; nf++) {
            int n = wn * WTN + nf * 8 + (lane & 7);
            uint32_t ad = base + OFF_B + n * 80 + (lane >> 3) * 16;
            LDMX4(bh[nf][0], bh[nf][1], bh[nf][2], bh[nf][3], ad);
        }
#pragma unroll
        for (int ks = 0; ks < 2; ks++) {
#pragma unroll
            for (int mf = 0; mf < MFRAG; mf++) {
                int r = wm * 64 + mf * 16 + (lane & 15);
                uint32_t ad = base + r * 80 + (lane >> 4) * 16 + ks * 32;
                uint32_t ah[4];
                LDMX4(ah[0], ah[1], ah[2], ah[3], ad);
#pragma unroll
                for (int nf = 0; nf < NFRAG; nf++)
                    MMA_F16(acc[mf][nf], ah, bh[nf][2 * ks], bh[nf][2 * ks + 1]);
                if (MODE == 0) {
                    uint32_t al[4];
                    LDMX4(al[0], al[1], al[2], al[3], ad + OFF_AL);
#pragma unroll
                    for (int nf = 0; nf < NFRAG; nf++)
                        MMA_F16(acc[mf][nf], al, bh[nf][2 * ks], bh[nf][2 * ks + 1]);
                }
            }
        }
    }

    // ---- epilogue
#pragma unroll
    for (int mf = 0; mf < MFRAG; mf++) {
        int r0 = rowbase + wm * 64 + mf * 16 + lr;
#pragma unroll
        for (int nf = 0; nf < NFRAG; nf++) {
            int c0 = colbase + wn * WTN + nf * 8 + lc * 2;
            float v00 = acc[mf][nf][0] * alpha, v01 = acc[mf][nf][1] * alpha;
            float v10 = acc[mf][nf][2] * alpha, v11 = acc[mf][nf][3] * alpha;
            long long o0 = (long long)r0 * ldc + c0 + blockIdx.z * sC;
            long long o1 = (long long)(r0 + 8) * ldc + c0 + blockIdx.z * sC;
            if (EPI == 0 || EPI == 2) {
                *(float2*)(C + o0) = make_float2(v00, v01);
                *(float2*)(C + o1) = make_float2(v10, v11);
            }
            if (EPI == 1 || EPI == 2) {
                uint32_t h0, l0, h1, l1;
                split_h_pack(v00, v01, h0, l0); split_h_pack(v10, v11, h1, l1);
                *(uint32_t*)(Ch + o0) = h0; *(uint32_t*)(Cl + o0) = l0;
                *(uint32_t*)(Ch + o1) = h1; *(uint32_t*)(Cl + o1) = l1;
            }
            if (EPI == 4) {
                *(uint32_t*)(Ch + o0) = h2_pack(v00, v01);
                *(uint32_t*)(Ch + o1) = h2_pack(v10, v11);
            }
        }
    }
}

// ---------------- fp32 -> fp16 single (elementwise) ----------------------------
__global__ void __launch_bounds__(256)
half_kernel(const float* __restrict__ in, u16* __restrict__ o, long long n)
{
    long long i = ((long long)blockIdx.x * 256 + threadIdx.x) * 4;
    if (i >= n) return;
    float4 v = *(const float4*)(in + i);
    *(uint32_t*)(o + i) = h2_pack(v.x, v.y);
    *(uint32_t*)(o + i + 2) = h2_pack(v.z, v.w);
}

// ---------------- fp32 transpose -> fp16 single --------------------------------
__global__ void __launch_bounds__(256)
transpose_half_kernel(const float* __restrict__ in, u16* __restrict__ out,
                      int ldin, int ldout, long long sIn, long long sOut)
{
    __shared__ float t[32][33];
    const float* ip = in + blockIdx.z * sIn;
    const int c0 = blockIdx.x * 32, r0 = blockIdx.y * 32;
#pragma unroll
    for (int i = 0; i < 4; i++) {
        int r = threadIdx.y + i * 8;
        t[r][threadIdx.x] = ip[(long long)(r0 + r) * ldin + c0 + threadIdx.x];
    }
    __syncthreads();
#pragma unroll
    for (int i = 0; i < 4; i++) {
        int c = threadIdx.y + i * 8;
        long long o = blockIdx.z * sOut + (long long)(c0 + c) * ldout + r0 + threadIdx.x;
        out[o] = h16_bits(t[threadIdx.x][c]);
    }
}

// ---------------- rmsnorm(latent) + RoPE ---------------------------------------
__global__ void __launch_bounds__(256)
prep_kernel(const float* __restrict__ cosp, const float* __restrict__ sinp,
            const float* __restrict__ normw)
{
    const int s = blockIdx.x;
    const int tid = threadIdx.x;
    const float* kv = g_kv + (long long)s * D;
    float* kf = g_kfull + (long long)s * D;

    float ss = 0.f;
    for (int i = tid; i < KVR; i += 256) { float v = kv[i]; ss += v * v; }
    __shared__ float red[32];
#pragma unroll
    for (int o = 16; o > 0; o >>= 1) ss += __shfl_xor_sync(0xffffffffu, ss, o);
    if ((tid & 31) == 0) red[tid >> 5] = ss;
    __syncthreads();
    if (tid < 32) {
        float v = (tid < 8) ? red[tid] : 0.f;
#pragma unroll
        for (int o = 16; o > 0; o >>= 1) v += __shfl_xor_sync(0xffffffffu, v, o);
        if (tid == 0) red[0] = v;
    }
    __syncthreads();
    const float r = rsqrtf(red[0] / (float)KVR + EPS);

    for (int i = tid; i < KVR; i += 256) {
        float v = kv[i] * r * normw[i];
        kf[i] = v;
        g_kf16[(long long)s * D + i] = h16_bits(v);
    }

    const float* cs = cosp + (long long)s * ROPE;
    const float* sn = sinp + (long long)s * ROPE;

    for (int i = tid; i < ROPE; i += 256) {
        float v = kv[KVR + i];
        float rot = (i < 32) ? -kv[KVR + i + 32] : kv[KVR + i - 32];
        float w = v * cs[i] + rot * sn[i];
        kf[KVR + i] = w;
        g_kf16[(long long)s * D + KVR + i] = h16_bits(w);
    }
    for (int idx = tid; idx < H * ROPE; idx += 256) {
        int h = idx >> 6, i = idx & 63;
        const float* qp = g_q + (long long)s * (H * QD) + h * QD + NOPE;
        float v = qp[i];
        float rot = (i < 32) ? -qp[i + 32] : qp[i - 32];
        float w = v * cs[i] + rot * sn[i];
        long long o = (long long)h * S * D + (long long)s * D + KVR + i;
        u16 hb = h16_bits(w);
        g_qfh[o] = hb;
        g_qfl[o] = h16_bits(w - h16_val(hb));
    }
}

// ---------------- causal row softmax (fp32 in -> fp16 single out) --------------
__global__ void __launch_bounds__(256)
softmax_kernel()
{
    const int s = blockIdx.x, h = blockIdx.y;
    const float* row = g_p + ((long long)h * S + s) * S;
    u16* ph = g_ph + ((long long)h * S + s) * S;
    __shared__ float sh[S];
    __shared__ float red[33];
    const int n = s + 1;
    const int nz = ((s >> 7) + 1) << 7;   // round_up(n,128)
    const int tid = threadIdx.x;

    float mx = -3.0e38f;
    for (int t = tid; t < n; t += 256) { float v = row[t]; sh[t] = v; mx = fmaxf(mx, v); }
#pragma unroll
    for (int o = 16; o > 0; o >>= 1) mx = fmaxf(mx, __shfl_xor_sync(0xffffffffu, mx, o));
    if ((tid & 31) == 0) red[tid >> 5] = mx;
    __syncthreads();
    if (tid < 32) {
        float v = (tid < 8) ? red[tid] : -3.0e38f;
#pragma unroll
        for (int o = 16; o > 0; o >>= 1) v = fmaxf(v, __shfl_xor_sync(0xffffffffu, v, o));
        if (tid == 0) red[32] = v;
    }
    __syncthreads();
    mx = red[32];

    float sum = 0.f;
    for (int t = tid; t < n; t += 256) { float e = expf(sh[t] - mx); sh[t] = e; sum += e; }
#pragma unroll
    for (int o = 16; o > 0; o >>= 1) sum += __shfl_xor_sync(0xffffffffu, sum, o);
    if ((tid & 31) == 0) red[tid >> 5] = sum;
    __syncthreads();
    if (tid < 32) {
        float v = (tid < 8) ? red[tid] : 0.f;
#pragma unroll
        for (int o = 16; o > 0; o >>= 1) v += __shfl_xor_sync(0xffffffffu, v, o);
        if (tid == 0) red[32] = v;
    }
    __syncthreads();
    const float inv = 1.0f / red[32];

    for (int t = tid; t < n; t += 256) ph[t] = h16_bits(sh[t] * inv);
    for (int t = n + tid; t < nz; t += 256) ph[t] = 0;
}

// ---------------- launch --------------------------------------------------------
extern "C" void kernel_launch(void* const* d_in, const int* in_sizes, int n_in,
                              void* d_out, int out_size)
{
    (void)in_sizes; (void)n_in; (void)out_size;
    const float* x      = (const float*)d_in[0];
    const float* cosp   = (const float*)d_in[1];
    const float* sinp   = (const float*)d_in[2];
    const float* w_q    = (const float*)d_in[3];
    const float* w_kv_a = (const float*)d_in[4];
    const float* normw  = (const float*)d_in[5];
    const float* kc     = (const float*)d_in[6];
    const float* vc     = (const float*)d_in[7];
    const float* w_o    = (const float*)d_in[8];
    float* out = (float*)d_out;

    float *q, *kv, *kf, *p;
    u16 *x16, *qh, *ql, *qfh, *qfl, *ph, *ao16, *ovh, *ovl;
    u16 *wqT16, *wkvaT16, *kcT16, *kf16, *latT16, *vcT16, *woT16;
    cudaGetSymbolAddress((void**)&q,  g_q);
    cudaGetSymbolAddress((void**)&kv, g_kv);
    cudaGetSymbolAddress((void**)&kf, g_kfull);
    cudaGetSymbolAddress((void**)&p,  g_p);
    cudaGetSymbolAddress((void**)&x16, g_x16);
    cudaGetSymbolAddress((void**)&qh, g_qh);   cudaGetSymbolAddress((void**)&ql, g_ql);
    cudaGetSymbolAddress((void**)&qfh, g_qfh); cudaGetSymbolAddress((void**)&qfl, g_qfl);
    cudaGetSymbolAddress((void**)&ph, g_ph);
    cudaGetSymbolAddress((void**)&ao16, g_ao16);
    cudaGetSymbolAddress((void**)&ovh, g_ovh); cudaGetSymbolAddress((void**)&ovl, g_ovl);
    cudaGetSymbolAddress((void**)&wqT16, g_wqT16);
    cudaGetSymbolAddress((void**)&wkvaT16, g_wkvaT16);
    cudaGetSymbolAddress((void**)&kcT16, g_kcT16);
    cudaGetSymbolAddress((void**)&kf16, g_kf16);
    cudaGetSymbolAddress((void**)&latT16, g_latT16);
    cudaGetSymbolAddress((void**)&vcT16, g_vcT16);
    cudaGetSymbolAddress((void**)&woT16, g_woT16);

    const int SM_M0_128 = 2 * (20480 + 128 * 80);  // 61440
    const int SM_M1_128 = 2 * (10240 + 128 * 80);  // 40960
    const int SM_M1_64  = 2 * (10240 + 64 * 80);   // 30720
    cudaFuncSetAttribute(mma_gemm<128, 0, 0>, cudaFuncAttributeMaxDynamicSharedMemorySize, SM_M0_128);
    cudaFuncSetAttribute(mma_gemm<128, 0, 1>, cudaFuncAttributeMaxDynamicSharedMemorySize, SM_M0_128);
    cudaFuncSetAttribute(mma_gemm<128, 1, 2>, cudaFuncAttributeMaxDynamicSharedMemorySize, SM_M1_128);
    cudaFuncSetAttribute(mma_gemm<64, 1, 0>,  cudaFuncAttributeMaxDynamicSharedMemorySize, SM_M1_64);
    cudaFuncSetAttribute(mma_gemm<128, 1, 4>, cudaFuncAttributeMaxDynamicSharedMemorySize, SM_M1_128);
    cudaFuncSetAttribute(mma_gemm<128, 1, 1>, cudaFuncAttributeMaxDynamicSharedMemorySize, SM_M1_128);

    dim3 tb(32, 8);

    // [0] x -> fp16 single
    half_kernel<<<(S * HID) / 1024, 256>>>(x, x16, (long long)S * HID);
    // [1..4] weight transposes -> single fp16 K-major
    transpose_half_kernel<<<dim3((H * QD) / 32, HID / 32, 1), tb>>>(w_q, wqT16, H * QD, HID, 0, 0);
    transpose_half_kernel<<<dim3(D / 32, HID / 32, 1), tb>>>(w_kv_a, wkvaT16, D, HID, 0, 0);
    transpose_half_kernel<<<dim3(KVR / 32, NOPE / 32, H), tb>>>(kc, kcT16, KVR, NOPE,
        (long long)NOPE * KVR, (long long)NOPE * KVR);
    transpose_half_kernel<<<dim3(VH / 32, KVR / 32, H), tb>>>(vc, vcT16, VH, KVR,
        (long long)KVR * VH, (long long)KVR * VH);

    // [5] q = x @ w_q  (single-A; fp32 q for prep + split qh/ql for 2-term stage 10)
    mma_gemm<128, 1, 2><<<dim3((H * QD) / 128, S / 128, 1), 256, SM_M1_128>>>(
        x16, nullptr, wqT16, q, qh, ql, HID, HID, HID, H * QD, 0, 0, 0, 1.0f, 0);

    // [6] w_o^T fp16
    transpose_half_kernel<<<dim3(HID / 32, (H * VH) / 32, 1), tb>>>(w_o, woT16, HID, H * VH, 0, 0);

    // [7] kv = x @ w_kv_a  (single-A, fp32 out)
    mma_gemm<64, 1, 0><<<dim3(D / 64, S / 128, 1), 256, SM_M1_64>>>(
        x16, nullptr, wkvaT16, kv, nullptr, nullptr, HID, HID, HID, D, 0, 0, 0, 1.0f, 0);

    // [8] rmsnorm + rope
    prep_kernel<<<S, 256>>>(cosp, sinp, normw);

    // [9] latent^T fp16 [KVR, S]
    transpose_half_kernel<<<dim3(KVR / 32, S / 32, 1), tb>>>(kf, latT16, D, S, 0, 0);

    // [10] q_nope @ kc -> qfull[:, :512] fp16 split (2-term A, per head)
    mma_gemm<128, 0, 1><<<dim3(KVR / 128, S / 128, H), 256, SM_M0_128>>>(
        qh, ql, kcT16, nullptr, qfh, qfl, NOPE, H * QD, NOPE, D,
        (long long)QD, (long long)KVR * NOPE, (long long)S * D, 1.0f, 0);

    // [11] scores = SCALE * qfull @ kfull^T  (2-term A, causal tile skip, fp32)
    mma_gemm<128, 0, 0><<<dim3(S / 128, S / 128, H), 256, SM_M0_128>>>(
        qfh, qfl, kf16, p, nullptr, nullptr, D, D, D, S,
        (long long)S * D, 0LL, (long long)S * S, SCALE, 1);

    // [12] softmax -> P fp16 single
    softmax_kernel<<<dim3(S, H), 256>>>();

    // [13] ao = P @ latent  (single-A, K truncated, fp16 single out)
    mma_gemm<128, 1, 4><<<dim3(KVR / 128, S / 128, H), 256, SM_M1_128>>>(
        ph, nullptr, latT16, nullptr, ao16, nullptr, S, S, S, KVR,
        (long long)S * S, 0LL, (long long)S * KVR, 1.0f, 2);

    // [14] ov = ao @ vc  (single-A, split out for 2-term stage 15)
    mma_gemm<128, 1, 1><<<dim3(VH / 128, S / 128, H), 256, SM_M1_128>>>(
        ao16, nullptr, vcT16, nullptr, ovh, ovl, KVR, KVR, KVR, H * VH,
        (long long)S * KVR, (long long)VH * KVR, (long long)VH, 1.0f, 0);

    // [15] out = ov @ w_o  (2-term A, fp32 final)
    mma_gemm<128, 0, 0><<<dim3(HID / 128, S / 128, 1), 256, SM_M0_128>>>(
        ovh, ovl, woT16, out, nullptr, nullptr, H * VH, H * VH, H * VH, HID,
        0, 0, 0, 1.0f, 0);
}

// round 14
// speedup vs baseline: 5.6636x; 1.4559x over previous
#include <cuda_runtime.h>
#include <cuda_fp16.h>
#include <cstdint>
#include <cstring>

#define S    2048
#define HID  2048
#define H    16
#define NOPE 128
#define ROPE 64
#define QD   192   // NOPE+ROPE
#define KVR  512
#define D    576   // KVR+ROPE
#define D2   192   // NOPE+ROPE (scoring dim, un-absorbed)
#define VH   128
#define SCALE 0.07216878364870323f
#define EPS  1e-6f

typedef unsigned short u16;

// ---------------- scratch (device globals) ------------------------------------
__device__ float g_kv[(long long)S * D];            // x @ w_kv_a (fp32)
__device__ float g_p[(long long)H * S * S];         // scores fp32
// fp16 split pairs (A of 2-term stages)
__device__ u16 g_qh[(long long)S * H * QD],  g_ql[(long long)S * H * QD];   // q (+roped q_pe)
__device__ u16 g_pvh[(long long)S * H * VH], g_pvl[(long long)S * H * VH];  // P@v
// fp16 single
__device__ u16 g_x16[(long long)S * HID];
__device__ u16 g_lat16[(long long)S * KVR];         // rmsnorm'd latent, dense [S,512]
__device__ u16 g_kc16[(long long)H * NOPE * KVR];   // kc fp16 (natural K-major)
__device__ u16 g_kf2[(long long)H * S * D2];        // [k_nope | k_pe] per head, ld=192
__device__ u16 g_vT16[(long long)H * VH * S];       // v^T per head [128, S]
__device__ u16 g_ph[(long long)H * S * S];          // softmax out (single)
// fp16 single B weights (K-major)
__device__ u16 g_wqT16[(long long)(H * QD) * HID];
__device__ u16 g_wkvaT16[(long long)D * HID];
__device__ u16 g_vcT16[(long long)H * VH * KVR];
__device__ u16 g_woT16[(long long)HID * (H * VH)];

// ---------------- helpers -----------------------------------------------------
__device__ __forceinline__ uint32_t smem_u32(const void* p) {
    uint32_t a;
    asm("{ .reg .u64 t; cvta.to.shared.u64 t, %1; cvt.u32.u64 %0, t; }" : "=r"(a) : "l"(p));
    return a;
}
__device__ __forceinline__ u16 h16_bits(float v) {
    __half b = __float2half_rn(v); u16 u; memcpy(&u, &b, 2); return u;
}
__device__ __forceinline__ float h16_val(u16 u) {
    __half b; memcpy(&b, &u, 2); return __half2float(b);
}
__device__ __forceinline__ void split_h_pack(float x, float y, uint32_t& h, uint32_t& l) {
    __half2 hv = __floats2half2_rn(x, y);
    __half2 lv = __floats2half2_rn(x - __half2float(__low2half(hv)),
                                   y - __half2float(__high2half(hv)));
    memcpy(&h, &hv, 4); memcpy(&l, &lv, 4);
}
__device__ __forceinline__ uint32_t h2_pack(float x, float y) {
    __half2 hv = __floats2half2_rn(x, y);
    uint32_t u; memcpy(&u, &hv, 4); return u;
}

#define CP_ASYNC16(dst, src) \
    asm volatile("cp.async.cg.shared.global [%0], [%1], 16;" :: "r"(dst), "l"(src))
#define CP_COMMIT() asm volatile("cp.async.commit_group;" ::: "memory")
#define CP_WAIT(n)  asm volatile("cp.async.wait_group %0;" :: "n"(n) : "memory")

#define LDMX4(r0, r1, r2, r3, addr) \
    asm volatile("ldmatrix.sync.aligned.m8n8.x4.shared.b16 {%0,%1,%2,%3}, [%4];" \
        : "=r"(r0), "=r"(r1), "=r"(r2), "=r"(r3) : "r"(addr))

#define MMA_F16(d, a, b0v, b1v) \
    asm volatile("mma.sync.aligned.m16n8k16.row.col.f32.f16.f16.f32 " \
        "{%0,%1,%2,%3}, {%4,%5,%6,%7}, {%8,%9}, {%0,%1,%2,%3};" \
        : "+f"((d)[0]), "+f"((d)[1]), "+f"((d)[2]), "+f"((d)[3]) \
        : "r"((a)[0]), "r"((a)[1]), "r"((a)[2]), "r"((a)[3]), "r"(b0v), "r"(b1v))

// ---------------- fp16 mma.sync GEMM -------------------------------------------
// C[M,N] = alpha * A[M,K] @ B[N,K]^T. B = fp16 single, K-major.
// MODE 0: A = fp16 hi/lo pair (2 MMAs). MODE 1: A = fp16 single (1 MMA).
// Block tile 128 x NT x 32; 8 warps = 2(m) x 4(n).
// EPI: 0=fp32 C; 1=fp16 split (Ch,Cl); 4=fp16 single (Ch).
// causal_mode: 0 none; 1 skip colbase>=rowbase+128; 2 kmax=rowbase+128.
template<int NT, int MODE, int EPI>
__global__ void __launch_bounds__(256)
mma_gemm(const u16* __restrict__ Agh, const u16* __restrict__ Agl,
         const u16* __restrict__ Bg,
         float* __restrict__ C, u16* __restrict__ Ch, u16* __restrict__ Cl,
         int K, int lda, int ldb, int ldc,
         long long sA, long long sB, long long sC, float alpha, int causal_mode)
{
    constexpr int WTN = NT / 4, NFRAG = WTN / 8, MFRAG = 4;
    constexpr int OFF_AL = 10240;
    constexpr int OFF_B = (MODE == 0) ? 20480 : 10240;
    constexpr int BUFB = OFF_B + NT * 80;
    constexpr int BC = (NT * 4) / 256;

    const int rowbase = blockIdx.y * 128;
    const int colbase = blockIdx.x * NT;
    if (causal_mode == 1 && colbase >= rowbase + 128) return;
    const int kmax = (causal_mode == 2) ? min(K, rowbase + 128) : K;
    const int nk = kmax >> 5;

    Agh += blockIdx.z * sA;
    if (MODE == 0) Agl += blockIdx.z * sA;
    Bg += blockIdx.z * sB;

    extern __shared__ char smem[];
    const uint32_t sb = smem_u32(smem);
    const int tid = threadIdx.x, wid = tid >> 5, lane = tid & 31;
    const int wm = wid >> 2, wn = wid & 3;
    const int lr = lane >> 2, lc = lane & 3;

    float acc[MFRAG][NFRAG][4];
#pragma unroll
    for (int i = 0; i < MFRAG; i++)
#pragma unroll
        for (int j = 0; j < NFRAG; j++)
#pragma unroll
            for (int q = 0; q < 4; q++) acc[i][j][q] = 0.f;

    auto issue_tile = [&](int kt, int buf) {
        const uint32_t base = sb + buf * BUFB;
        const int k0 = kt << 5;
#pragma unroll
        for (int i = 0; i < 2; i++) {
            int idx = tid + i * 256, r = idx >> 2, c = idx & 3;
            long long g = (long long)(rowbase + r) * lda + k0 + c * 8;
            uint32_t so = (uint32_t)(r * 80 + c * 16);
            CP_ASYNC16(base + so, Agh + g);
            if (MODE == 0) CP_ASYNC16(base + OFF_AL + so, Agl + g);
        }
#pragma unroll
        for (int i = 0; i < BC; i++) {
            int idx = tid + i * 256, r = idx >> 2, c = idx & 3;
            long long g = (long long)(colbase + r) * ldb + k0 + c * 8;
            uint32_t so = (uint32_t)(r * 80 + c * 16);
            CP_ASYNC16(base + OFF_B + so, Bg + g);
        }
        CP_COMMIT();
    };

    issue_tile(0, 0);

    for (int kt = 0; kt < nk; kt++) {
        CP_WAIT(0);
        __syncthreads();
        if (kt + 1 < nk) issue_tile(kt + 1, (kt + 1) & 1);   // overlaps with compute

        const uint32_t base = sb + (kt & 1) * BUFB;
        uint32_t bh[NFRAG][4];
#pragma unroll
        for (int nf = 0; nf < NFRAG; nf++) {
            int n = wn * WTN + nf * 8 + (lane & 7);
            uint32_t ad = base + OFF_B + n * 80 + (lane >> 3) * 16;
            LDMX4(bh[nf][0], bh[nf][1], bh[nf][2], bh[nf][3], ad);
        }
#pragma unroll
        for (int ks = 0; ks < 2; ks++) {
#pragma unroll
            for (int mf = 0; mf < MFRAG; mf++) {
                int r = wm * 64 + mf * 16 + (lane & 15);
                uint32_t ad = base + r * 80 + (lane >> 4) * 16 + ks * 32;
                uint32_t ah[4];
                LDMX4(ah[0], ah[1], ah[2], ah[3], ad);
#pragma unroll
                for (int nf = 0; nf < NFRAG; nf++)
                    MMA_F16(acc[mf][nf], ah, bh[nf][2 * ks], bh[nf][2 * ks + 1]);
                if (MODE == 0) {
                    uint32_t al[4];
                    LDMX4(al[0], al[1], al[2], al[3], ad + OFF_AL);
#pragma unroll
                    for (int nf = 0; nf < NFRAG; nf++)
                        MMA_F16(acc[mf][nf], al, bh[nf][2 * ks], bh[nf][2 * ks + 1]);
                }
            }
        }
    }

    // ---- epilogue
#pragma unroll
    for (int mf = 0; mf < MFRAG; mf++) {
        int r0 = rowbase + wm * 64 + mf * 16 + lr;
#pragma unroll
        for (int nf = 0; nf < NFRAG; nf++) {
            int c0 = colbase + wn * WTN + nf * 8 + lc * 2;
            float v00 = acc[mf][nf][0] * alpha, v01 = acc[mf][nf][1] * alpha;
            float v10 = acc[mf][nf][2] * alpha, v11 = acc[mf][nf][3] * alpha;
            long long o0 = (long long)r0 * ldc + c0 + blockIdx.z * sC;
            long long o1 = (long long)(r0 + 8) * ldc + c0 + blockIdx.z * sC;
            if (EPI == 0) {
                *(float2*)(C + o0) = make_float2(v00, v01);
                *(float2*)(C + o1) = make_float2(v10, v11);
            }
            if (EPI == 1) {
                uint32_t h0, l0, h1, l1;
                split_h_pack(v00, v01, h0, l0); split_h_pack(v10, v11, h1, l1);
                *(uint32_t*)(Ch + o0) = h0; *(uint32_t*)(Cl + o0) = l0;
                *(uint32_t*)(Ch + o1) = h1; *(uint32_t*)(Cl + o1) = l1;
            }
            if (EPI == 4) {
                *(uint32_t*)(Ch + o0) = h2_pack(v00, v01);
                *(uint32_t*)(Ch + o1) = h2_pack(v10, v11);
            }
        }
    }
}

// ---------------- fp32 -> fp16 single (elementwise) ----------------------------
__global__ void __launch_bounds__(256)
half_kernel(const float* __restrict__ in, u16* __restrict__ o, long long n)
{
    long long i = ((long long)blockIdx.x * 256 + threadIdx.x) * 4;
    if (i >= n) return;
    float4 v = *(const float4*)(in + i);
    *(uint32_t*)(o + i) = h2_pack(v.x, v.y);
    *(uint32_t*)(o + i + 2) = h2_pack(v.z, v.w);
}

// ---------------- fp32 transpose -> fp16 single --------------------------------
__global__ void __launch_bounds__(256)
transpose_half_kernel(const float* __restrict__ in, u16* __restrict__ out,
                      int ldin, int ldout, long long sIn, long long sOut)
{
    __shared__ float t[32][33];
    const float* ip = in + blockIdx.z * sIn;
    const int c0 = blockIdx.x * 32, r0 = blockIdx.y * 32;
#pragma unroll
    for (int i = 0; i < 4; i++) {
        int r = threadIdx.y + i * 8;
        t[r][threadIdx.x] = ip[(long long)(r0 + r) * ldin + c0 + threadIdx.x];
    }
    __syncthreads();
#pragma unroll
    for (int i = 0; i < 4; i++) {
        int c = threadIdx.y + i * 8;
        long long o = blockIdx.z * sOut + (long long)(c0 + c) * ldout + r0 + threadIdx.x;
        out[o] = h16_bits(t[threadIdx.x][c]);
    }
}

// ---------------- rmsnorm(latent) + RoPE ---------------------------------------
// lat16 <- rmsnorm(kv[:512]); kf2[h][s][128:192] <- rope(k_pe) (all heads);
// qh/ql[s, h*192+128 : +64] <- rope(q_pe) split (in place over q-GEMM output).
__global__ void __launch_bounds__(256)
prep_kernel(const float* __restrict__ cosp, const float* __restrict__ sinp,
            const float* __restrict__ normw)
{
    const int s = blockIdx.x;
    const int tid = threadIdx.x;
    const float* kv = g_kv + (long long)s * D;

    float ss = 0.f;
    for (int i = tid; i < KVR; i += 256) { float v = kv[i]; ss += v * v; }
    __shared__ float red[32];
#pragma unroll
    for (int o = 16; o > 0; o >>= 1) ss += __shfl_xor_sync(0xffffffffu, ss, o);
    if ((tid & 31) == 0) red[tid >> 5] = ss;
    __syncthreads();
    if (tid < 32) {
        float v = (tid < 8) ? red[tid] : 0.f;
#pragma unroll
        for (int o = 16; o > 0; o >>= 1) v += __shfl_xor_sync(0xffffffffu, v, o);
        if (tid == 0) red[0] = v;
    }
    __syncthreads();
    const float r = rsqrtf(red[0] / (float)KVR + EPS);

    for (int i = tid; i < KVR; i += 256)
        g_lat16[(long long)s * KVR + i] = h16_bits(kv[i] * r * normw[i]);

    const float* cs = cosp + (long long)s * ROPE;
    const float* sn = sinp + (long long)s * ROPE;

    __shared__ u16 kpe[ROPE];
    for (int i = tid; i < ROPE; i += 256) {
        float v = kv[KVR + i];
        float rot = (i < 32) ? -kv[KVR + i + 32] : kv[KVR + i - 32];
        kpe[i] = h16_bits(v * cs[i] + rot * sn[i]);
    }
    __syncthreads();
    // replicate roped k_pe into all H per-head kf2 rows
    for (int idx = tid; idx < H * ROPE; idx += 256) {
        int h = idx >> 6, i = idx & 63;
        g_kf2[(long long)h * S * D2 + (long long)s * D2 + NOPE + i] = kpe[i];
    }
    // rope q_pe (reconstruct fp32 from split, rope, write back split)
    for (int idx = tid; idx < H * ROPE; idx += 256) {
        int h = idx >> 6, i = idx & 63;
        long long base = (long long)s * (H * QD) + h * QD + NOPE;
        float v = h16_val(g_qh[base + i]) + h16_val(g_ql[base + i]);
        float ro = (i < 32)
            ? -(h16_val(g_qh[base + i + 32]) + h16_val(g_ql[base + i + 32]))
            :  (h16_val(g_qh[base + i - 32]) + h16_val(g_ql[base + i - 32]));
        float w = v * cs[i] + ro * sn[i];
        u16 hb = h16_bits(w);
        // defer write: use shared staging to avoid read/write race within block
        kpe[0] = kpe[0];  // no-op
        // store to registers then sync below
        g_kf2[0] = g_kf2[0]; // placeholder removed
        (void)hb;
    }
    // NOTE: the loop above must not write qh/ql while other threads still read.
    __syncthreads();
    for (int idx = tid; idx < H * ROPE; idx += 256) {
        int h = idx >> 6, i = idx & 63;
        long long base = (long long)s * (H * QD) + h * QD + NOPE;
        float v = h16_val(g_qh[base + i]) + h16_val(g_ql[base + i]);
        float ro = (i < 32)
            ? -(h16_val(g_qh[base + i + 32]) + h16_val(g_ql[base + i + 32]))
            :  (h16_val(g_qh[base + i - 32]) + h16_val(g_ql[base + i - 32]));
        float w = v * cs[i] + ro * sn[i];
        __shared__ float stage[H * ROPE];
        stage[idx] = w;
        __syncthreads();
        u16 hb = h16_bits(stage[idx]);
        g_qh[base + i] = hb;
        g_ql[base + i] = h16_bits(stage[idx] - h16_val(hb));
        __syncthreads();
    }
}

// ---------------- causal row softmax (fp32 in -> fp16 single out) --------------
__global__ void __launch_bounds__(256)
softmax_kernel()
{
    const int s = blockIdx.x, h = blockIdx.y;
    const float* row = g_p + ((long long)h * S + s) * S;
    u16* ph = g_ph + ((long long)h * S + s) * S;
    __shared__ float sh[S];
    __shared__ float red[33];
    const int n = s + 1;
    const int nz = ((s >> 7) + 1) << 7;   // round_up(n,128)
    const int tid = threadIdx.x;

    float mx = -3.0e38f;
    for (int t = tid; t < n; t += 256) { float v = row[t]; sh[t] = v; mx = fmaxf(mx, v); }
#pragma unroll
    for (int o = 16; o > 0; o >>= 1) mx = fmaxf(mx, __shfl_xor_sync(0xffffffffu, mx, o));
    if ((tid & 31) == 0) red[tid >> 5] = mx;
    __syncthreads();
    if (tid < 32) {
        float v = (tid < 8) ? red[tid] : -3.0e38f;
#pragma unroll
        for (int o = 16; o > 0; o >>= 1) v = fmaxf(v, __shfl_xor_sync(0xffffffffu, v, o));
        if (tid == 0) red[32] = v;
    }
    __syncthreads();
    mx = red[32];

    float sum = 0.f;
    for (int t = tid; t < n; t += 256) { float e = expf(sh[t] - mx); sh[t] = e; sum += e; }
#pragma unroll
    for (int o = 16; o > 0; o >>= 1) sum += __shfl_xor_sync(0xffffffffu, sum, o);
    if ((tid & 31) == 0) red[tid >> 5] = sum;
    __syncthreads();
    if (tid < 32) {
        float v = (tid < 8) ? red[tid] : 0.f;
#pragma unroll
        for (int o = 16; o > 0; o >>= 1) v += __shfl_xor_sync(0xffffffffu, v, o);
        if (tid == 0) red[32] = v;
    }
    __syncthreads();
    const float inv = 1.0f / red[32];

    for (int t = tid; t < n; t += 256) ph[t] = h16_bits(sh[t] * inv);
    for (int t = n + tid; t < nz; t += 256) ph[t] = 0;
}

// ---------------- launch --------------------------------------------------------
extern "C" void kernel_launch(void* const* d_in, const int* in_sizes, int n_in,
                              void* d_out, int out_size)
{
    (void)in_sizes; (void)n_in; (void)out_size;
    const float* x      = (const float*)d_in[0];
    const float* cosp   = (const float*)d_in[1];
    const float* sinp   = (const float*)d_in[2];
    const float* w_q    = (const float*)d_in[3];
    const float* w_kv_a = (const float*)d_in[4];
    const float* normw  = (const float*)d_in[5];
    const float* kc     = (const float*)d_in[6];
    const float* vc     = (const float*)d_in[7];
    const float* w_o    = (const float*)d_in[8];
    float* out = (float*)d_out;

    float *kv, *p;
    u16 *x16, *qh, *ql, *lat16, *kc16, *kf2, *vT16, *ph, *pvh, *pvl;
    u16 *wqT16, *wkvaT16, *vcT16, *woT16;
    cudaGetSymbolAddress((void**)&kv, g_kv);
    cudaGetSymbolAddress((void**)&p,  g_p);
    cudaGetSymbolAddress((void**)&x16, g_x16);
    cudaGetSymbolAddress((void**)&qh, g_qh);     cudaGetSymbolAddress((void**)&ql, g_ql);
    cudaGetSymbolAddress((void**)&lat16, g_lat16);
    cudaGetSymbolAddress((void**)&kc16, g_kc16);
    cudaGetSymbolAddress((void**)&kf2, g_kf2);
    cudaGetSymbolAddress((void**)&vT16, g_vT16);
    cudaGetSymbolAddress((void**)&ph, g_ph);
    cudaGetSymbolAddress((void**)&pvh, g_pvh);   cudaGetSymbolAddress((void**)&pvl, g_pvl);
    cudaGetSymbolAddress((void**)&wqT16, g_wqT16);
    cudaGetSymbolAddress((void**)&wkvaT16, g_wkvaT16);
    cudaGetSymbolAddress((void**)&vcT16, g_vcT16);
    cudaGetSymbolAddress((void**)&woT16, g_woT16);

    const int SM_M0_128 = 2 * (20480 + 128 * 80);  // 61440
    const int SM_M1_128 = 2 * (10240 + 128 * 80);  // 40960
    const int SM_M1_64  = 2 * (10240 + 64 * 80);   // 30720
    cudaFuncSetAttribute(mma_gemm<128, 0, 0>, cudaFuncAttributeMaxDynamicSharedMemorySize, SM_M0_128);
    cudaFuncSetAttribute(mma_gemm<128, 1, 1>, cudaFuncAttributeMaxDynamicSharedMemorySize, SM_M1_128);
    cudaFuncSetAttribute(mma_gemm<128, 1, 4>, cudaFuncAttributeMaxDynamicSharedMemorySize, SM_M1_128);
    cudaFuncSetAttribute(mma_gemm<64, 1, 0>,  cudaFuncAttributeMaxDynamicSharedMemorySize, SM_M1_64);

    dim3 tb(32, 8);

    // [0] x -> fp16
    half_kernel<<<(S * HID) / 1024, 256>>>(x, x16, (long long)S * HID);
    // [1..3] weight transposes -> fp16 K-major
    transpose_half_kernel<<<dim3((H * QD) / 32, HID / 32, 1), tb>>>(w_q, wqT16, H * QD, HID, 0, 0);
    transpose_half_kernel<<<dim3(D / 32, HID / 32, 1), tb>>>(w_kv_a, wkvaT16, D, HID, 0, 0);
    transpose_half_kernel<<<dim3(VH / 32, KVR / 32, H), tb>>>(vc, vcT16, VH, KVR,
        (long long)KVR * VH, (long long)KVR * VH);
    // [4] kc -> fp16 (natural layout is K-major [h][128,512])
    half_kernel<<<(H * NOPE * KVR) / 1024, 256>>>(kc, kc16, (long long)H * NOPE * KVR);

    // [5] q = x @ w_q  (single-A, split out; ncu -s 5 target)
    mma_gemm<128, 1, 1><<<dim3((H * QD) / 128, S / 128, 1), 256, SM_M1_128>>>(
        x16, nullptr, wqT16, nullptr, qh, ql, HID, HID, HID, H * QD, 0, 0, 0, 1.0f, 0);

    // [6] w_o^T fp16
    transpose_half_kernel<<<dim3(HID / 32, (H * VH) / 32, 1), tb>>>(w_o, woT16, HID, H * VH, 0, 0);

    // [7] kv = x @ w_kv_a  (single-A, fp32 out)
    mma_gemm<64, 1, 0><<<dim3(D / 64, S / 128, 1), 256, SM_M1_64>>>(
        x16, nullptr, wkvaT16, kv, nullptr, nullptr, HID, HID, HID, D, 0, 0, 0, 1.0f, 0);

    // [8] rmsnorm + rope (lat16; k_pe -> kf2 all heads; q_pe roped in-place in qh/ql)
    prep_kernel<<<S, 256>>>(cosp, sinp, normw);

    // [9] k_nope[h] = latent @ kc[h]^T -> kf2[h][:, 0:128]  (M=S, N=128, K=512)
    mma_gemm<128, 1, 4><<<dim3(1, S / 128, H), 256, SM_M1_128>>>(
        lat16, nullptr, kc16, nullptr, kf2, nullptr, KVR, KVR, KVR, D2,
        0LL, (long long)NOPE * KVR, (long long)S * D2, 1.0f, 0);

    // [10] vT[h] = vc[h]^T @ latent^T -> [128, S]  (M=128, N=S, K=512)
    mma_gemm<128, 1, 4><<<dim3(S / 128, 1, H), 256, SM_M1_128>>>(
        vcT16, nullptr, lat16, nullptr, vT16, nullptr, KVR, KVR, KVR, S,
        (long long)VH * KVR, 0LL, (long long)VH * S, 1.0f, 0);

    // [11] scores = SCALE * q[h] @ kf2[h]^T over 192 dims  (2-term A, causal skip)
    mma_gemm<128, 0, 0><<<dim3(S / 128, S / 128, H), 256, SM_M0_128>>>(
        qh, ql, kf2, p, nullptr, nullptr, D2, H * QD, D2, S,
        (long long)QD, (long long)S * D2, (long long)S * S, SCALE, 1);

    // [12] softmax -> P fp16 single
    softmax_kernel<<<dim3(S, H), 256>>>();

    // [13] pv = P @ v  (single-A, K truncated at diagonal, split out into [S, H*VH])
    mma_gemm<128, 1, 1><<<dim3(1, S / 128, H), 256, SM_M1_128>>>(
        ph, nullptr, vT16, nullptr, pvh, pvl, S, S, S, H * VH,
        (long long)S * S, (long long)VH * S, (long long)VH, 1.0f, 2);

    // [14] out = pv @ w_o  (2-term A, fp32 final)
    mma_gemm<128, 0, 0><<<dim3(HID / 128, S / 128, 1), 256, SM_M0_128>>>(
        pvh, pvl, woT16, out, nullptr, nullptr, H * VH, H * VH, H * VH, HID,
        0, 0, 0, 1.0f, 0);
}

// round 15
// speedup vs baseline: 6.2681x; 1.1067x over previous
#include <cuda_runtime.h>
#include <cuda_fp16.h>
#include <cstdint>
#include <cstring>

#define S    2048
#define HID  2048
#define H    16
#define NOPE 128
#define ROPE 64
#define QD   192   // NOPE+ROPE
#define KVR  512
#define D    576   // KVR+ROPE
#define D2   192   // NOPE+ROPE (scoring dim, un-absorbed)
#define VH   128
#define SCALE 0.07216878364870323f
#define EPS  1e-6f

typedef unsigned short u16;

// ---------------- scratch (device globals) ------------------------------------
__device__ float g_kv[(long long)S * D];            // x @ w_kv_a (fp32)
__device__ float g_p[(long long)H * S * S];         // scores fp32
// fp16 split pairs (A of 2-term stages)
__device__ u16 g_qh[(long long)S * H * QD],  g_ql[(long long)S * H * QD];   // q (+roped q_pe)
// fp16 single
__device__ u16 g_x16[(long long)S * HID];
__device__ u16 g_lat16[(long long)S * KVR];         // rmsnorm'd latent, dense [S,512]
__device__ u16 g_kc16[(long long)H * NOPE * KVR];   // kc fp16 (natural K-major)
__device__ u16 g_kf2[(long long)H * S * D2];        // [k_nope | k_pe] per head, ld=192
__device__ u16 g_vT16[(long long)H * VH * S];       // v^T per head [128, S]
__device__ u16 g_ph[(long long)H * S * S];          // softmax out (single)
__device__ u16 g_pv16[(long long)S * H * VH];       // P@v (single, A of out-proj)
// fp16 single B weights (K-major)
__device__ u16 g_wqT16[(long long)(H * QD) * HID];
__device__ u16 g_wkvaT16[(long long)D * HID];
__device__ u16 g_vcT16[(long long)H * VH * KVR];
__device__ u16 g_woT16[(long long)HID * (H * VH)];

// ---------------- helpers -----------------------------------------------------
__device__ __forceinline__ uint32_t smem_u32(const void* p) {
    uint32_t a;
    asm("{ .reg .u64 t; cvta.to.shared.u64 t, %1; cvt.u32.u64 %0, t; }" : "=r"(a) : "l"(p));
    return a;
}
__device__ __forceinline__ u16 h16_bits(float v) {
    __half b = __float2half_rn(v); u16 u; memcpy(&u, &b, 2); return u;
}
__device__ __forceinline__ float h16_val(u16 u) {
    __half b; memcpy(&b, &u, 2); return __half2float(b);
}
__device__ __forceinline__ void split_h_pack(float x, float y, uint32_t& h, uint32_t& l) {
    __half2 hv = __floats2half2_rn(x, y);
    __half2 lv = __floats2half2_rn(x - __half2float(__low2half(hv)),
                                   y - __half2float(__high2half(hv)));
    memcpy(&h, &hv, 4); memcpy(&l, &lv, 4);
}
__device__ __forceinline__ uint32_t h2_pack(float x, float y) {
    __half2 hv = __floats2half2_rn(x, y);
    uint32_t u; memcpy(&u, &hv, 4); return u;
}

#define CP_ASYNC16(dst, src) \
    asm volatile("cp.async.cg.shared.global [%0], [%1], 16;" :: "r"(dst), "l"(src))
#define CP_COMMIT() asm volatile("cp.async.commit_group;" ::: "memory")
#define CP_WAIT(n)  asm volatile("cp.async.wait_group %0;" :: "n"(n) : "memory")

#define LDMX4(r0, r1, r2, r3, addr) \
    asm volatile("ldmatrix.sync.aligned.m8n8.x4.shared.b16 {%0,%1,%2,%3}, [%4];" \
        : "=r"(r0), "=r"(r1), "=r"(r2), "=r"(r3) : "r"(addr))

#define MMA_F16(d, a, b0v, b1v) \
    asm volatile("mma.sync.aligned.m16n8k16.row.col.f32.f16.f16.f32 " \
        "{%0,%1,%2,%3}, {%4,%5,%6,%7}, {%8,%9}, {%0,%1,%2,%3};" \
        : "+f"((d)[0]), "+f"((d)[1]), "+f"((d)[2]), "+f"((d)[3]) \
        : "r"((a)[0]), "r"((a)[1]), "r"((a)[2]), "r"((a)[3]), "r"(b0v), "r"(b1v))

// ---------------- fp16 mma.sync GEMM -------------------------------------------
// C[M,N] = alpha * A[M,K] @ B[N,K]^T. B = fp16 single, K-major.
// MODE 0: A = fp16 hi/lo pair (2 MMAs). MODE 1: A = fp16 single (1 MMA).
// Block tile 128 x NT x 32; 8 warps = 2(m) x 4(n).
// EPI: 0=fp32 C; 1=fp16 split (Ch,Cl); 4=fp16 single (Ch).
// causal_mode: 0 none; 1 skip colbase>=rowbase+128; 2 kmax=rowbase+128.
template<int NT, int MODE, int EPI>
__global__ void __launch_bounds__(256)
mma_gemm(const u16* __restrict__ Agh, const u16* __restrict__ Agl,
         const u16* __restrict__ Bg,
         float* __restrict__ C, u16* __restrict__ Ch, u16* __restrict__ Cl,
         int K, int lda, int ldb, int ldc,
         long long sA, long long sB, long long sC, float alpha, int causal_mode)
{
    constexpr int WTN = NT / 4, NFRAG = WTN / 8, MFRAG = 4;
    constexpr int OFF_AL = 10240;
    constexpr int OFF_B = (MODE == 0) ? 20480 : 10240;
    constexpr int BUFB = OFF_B + NT * 80;
    constexpr int BC = (NT * 4) / 256;

    const int rowbase = blockIdx.y * 128;
    const int colbase = blockIdx.x * NT;
    if (causal_mode == 1 && colbase >= rowbase + 128) return;
    const int kmax = (causal_mode == 2) ? min(K, rowbase + 128) : K;
    const int nk = kmax >> 5;

    Agh += blockIdx.z * sA;
    if (MODE == 0) Agl += blockIdx.z * sA;
    Bg += blockIdx.z * sB;

    extern __shared__ char smem[];
    const uint32_t sb = smem_u32(smem);
    const int tid = threadIdx.x, wid = tid >> 5, lane = tid & 31;
    const int wm = wid >> 2, wn = wid & 3;
    const int lr = lane >> 2, lc = lane & 3;

    float acc[MFRAG][NFRAG][4];
#pragma unroll
    for (int i = 0; i < MFRAG; i++)
#pragma unroll
        for (int j = 0; j < NFRAG; j++)
#pragma unroll
            for (int q = 0; q < 4; q++) acc[i][j][q] = 0.f;

    auto issue_tile = [&](int kt, int buf) {
        const uint32_t base = sb + buf * BUFB;
        const int k0 = kt << 5;
#pragma unroll
        for (int i = 0; i < 2; i++) {
            int idx = tid + i * 256, r = idx >> 2, c = idx & 3;
            long long g = (long long)(rowbase + r) * lda + k0 + c * 8;
            uint32_t so = (uint32_t)(r * 80 + c * 16);
            CP_ASYNC16(base + so, Agh + g);
            if (MODE == 0) CP_ASYNC16(base + OFF_AL + so, Agl + g);
        }
#pragma unroll
        for (int i = 0; i < BC; i++) {
            int idx = tid + i * 256, r = idx >> 2, c = idx & 3;
            long long g = (long long)(colbase + r) * ldb + k0 + c * 8;
            uint32_t so = (uint32_t)(r * 80 + c * 16);
            CP_ASYNC16(base + OFF_B + so, Bg + g);
        }
        CP_COMMIT();
    };

    issue_tile(0, 0);

    for (int kt = 0; kt < nk; kt++) {
        CP_WAIT(0);
        __syncthreads();
        if (kt + 1 < nk) issue_tile(kt + 1, (kt + 1) & 1);   // overlaps with compute

        const uint32_t base = sb + (kt & 1) * BUFB;
        uint32_t bh[NFRAG][4];
#pragma unroll
        for (int nf = 0; nf < NFRAG; nf++) {
            int n = wn * WTN + nf * 8 + (lane & 7);
            uint32_t ad = base + OFF_B + n * 80 + (lane >> 3) * 16;
            LDMX4(bh[nf][0], bh[nf][1], bh[nf][2], bh[nf][3], ad);
        }
#pragma unroll
        for (int ks = 0; ks < 2; ks++) {
#pragma unroll
            for (int mf = 0; mf < MFRAG; mf++) {
                int r = wm * 64 + mf * 16 + (lane & 15);
                uint32_t ad = base + r * 80 + (lane >> 4) * 16 + ks * 32;
                uint32_t ah[4];
                LDMX4(ah[0], ah[1], ah[2], ah[3], ad);
#pragma unroll
                for (int nf = 0; nf < NFRAG; nf++)
                    MMA_F16(acc[mf][nf], ah, bh[nf][2 * ks], bh[nf][2 * ks + 1]);
                if (MODE == 0) {
                    uint32_t al[4];
                    LDMX4(al[0], al[1], al[2], al[3], ad + OFF_AL);
#pragma unroll
                    for (int nf = 0; nf < NFRAG; nf++)
                        MMA_F16(acc[mf][nf], al, bh[nf][2 * ks], bh[nf][2 * ks + 1]);
                }
            }
        }
    }

    // ---- epilogue
#pragma unroll
    for (int mf = 0; mf < MFRAG; mf++) {
        int r0 = rowbase + wm * 64 + mf * 16 + lr;
#pragma unroll
        for (int nf = 0; nf < NFRAG; nf++) {
            int c0 = colbase + wn * WTN + nf * 8 + lc * 2;
            float v00 = acc[mf][nf][0] * alpha, v01 = acc[mf][nf][1] * alpha;
            float v10 = acc[mf][nf][2] * alpha, v11 = acc[mf][nf][3] * alpha;
            long long o0 = (long long)r0 * ldc + c0 + blockIdx.z * sC;
            long long o1 = (long long)(r0 + 8) * ldc + c0 + blockIdx.z * sC;
            if (EPI == 0) {
                *(float2*)(C + o0) = make_float2(v00, v01);
                *(float2*)(C + o1) = make_float2(v10, v11);
            }
            if (EPI == 1) {
                uint32_t h0, l0, h1, l1;
                split_h_pack(v00, v01, h0, l0); split_h_pack(v10, v11, h1, l1);
                *(uint32_t*)(Ch + o0) = h0; *(uint32_t*)(Cl + o0) = l0;
                *(uint32_t*)(Ch + o1) = h1; *(uint32_t*)(Cl + o1) = l1;
            }
            if (EPI == 4) {
                *(uint32_t*)(Ch + o0) = h2_pack(v00, v01);
                *(uint32_t*)(Ch + o1) = h2_pack(v10, v11);
            }
        }
    }
}

// ---------------- fp32 -> fp16 single (elementwise) ----------------------------
__global__ void __launch_bounds__(256)
half_kernel(const float* __restrict__ in, u16* __restrict__ o, long long n)
{
    long long i = ((long long)blockIdx.x * 256 + threadIdx.x) * 4;
    if (i >= n) return;
    float4 v = *(const float4*)(in + i);
    *(uint32_t*)(o + i) = h2_pack(v.x, v.y);
    *(uint32_t*)(o + i + 2) = h2_pack(v.z, v.w);
}

// ---------------- fp32 transpose -> fp16 single --------------------------------
__global__ void __launch_bounds__(256)
transpose_half_kernel(const float* __restrict__ in, u16* __restrict__ out,
                      int ldin, int ldout, long long sIn, long long sOut)
{
    __shared__ float t[32][33];
    const float* ip = in + blockIdx.z * sIn;
    const int c0 = blockIdx.x * 32, r0 = blockIdx.y * 32;
#pragma unroll
    for (int i = 0; i < 4; i++) {
        int r = threadIdx.y + i * 8;
        t[r][threadIdx.x] = ip[(long long)(r0 + r) * ldin + c0 + threadIdx.x];
    }
    __syncthreads();
#pragma unroll
    for (int i = 0; i < 4; i++) {
        int c = threadIdx.y + i * 8;
        long long o = blockIdx.z * sOut + (long long)(c0 + c) * ldout + r0 + threadIdx.x;
        out[o] = h16_bits(t[threadIdx.x][c]);
    }
}

// ---------------- rmsnorm(latent) + RoPE ---------------------------------------
// lat16 <- rmsnorm(kv[:512]); kf2[h][s][128:192] <- rope(k_pe) (all heads);
// qh/ql rope section updated in place (register-staged read -> barrier -> write).
__global__ void __launch_bounds__(256)
prep_kernel(const float* __restrict__ cosp, const float* __restrict__ sinp,
            const float* __restrict__ normw)
{
    const int s = blockIdx.x;
    const int tid = threadIdx.x;
    const float* kv = g_kv + (long long)s * D;

    float ss = 0.f;
    for (int i = tid; i < KVR; i += 256) { float v = kv[i]; ss += v * v; }
    __shared__ float red[32];
#pragma unroll
    for (int o = 16; o > 0; o >>= 1) ss += __shfl_xor_sync(0xffffffffu, ss, o);
    if ((tid & 31) == 0) red[tid >> 5] = ss;
    __syncthreads();
    if (tid < 32) {
        float v = (tid < 8) ? red[tid] : 0.f;
#pragma unroll
        for (int o = 16; o > 0; o >>= 1) v += __shfl_xor_sync(0xffffffffu, v, o);
        if (tid == 0) red[0] = v;
    }
    __syncthreads();
    const float r = rsqrtf(red[0] / (float)KVR + EPS);

    for (int i = tid; i < KVR; i += 256)
        g_lat16[(long long)s * KVR + i] = h16_bits(kv[i] * r * normw[i]);

    const float* cs = cosp + (long long)s * ROPE;
    const float* sn = sinp + (long long)s * ROPE;

    __shared__ u16 kpe[ROPE];
    for (int i = tid; i < ROPE; i += 256) {
        float v = kv[KVR + i];
        float rot = (i < 32) ? -kv[KVR + i + 32] : kv[KVR + i - 32];
        kpe[i] = h16_bits(v * cs[i] + rot * sn[i]);
    }
    __syncthreads();
    // replicate roped k_pe into all H per-head kf2 rows
    for (int idx = tid; idx < H * ROPE; idx += 256) {
        int h = idx >> 6, i = idx & 63;
        g_kf2[(long long)h * S * D2 + (long long)s * D2 + NOPE + i] = kpe[i];
    }

    // rope q_pe in place: read all (uniform trip count), barrier, then write
    float wv[(H * ROPE) / 256];
#pragma unroll
    for (int it = 0; it < (H * ROPE) / 256; it++) {
        int idx = tid + it * 256;
        int h = idx >> 6, i = idx & 63;
        long long base = (long long)s * (H * QD) + h * QD + NOPE;
        float v = h16_val(g_qh[base + i]) + h16_val(g_ql[base + i]);
        float ro = (i < 32)
            ? -(h16_val(g_qh[base + i + 32]) + h16_val(g_ql[base + i + 32]))
            :  (h16_val(g_qh[base + i - 32]) + h16_val(g_ql[base + i - 32]));
        wv[it] = v * cs[i] + ro * sn[i];
    }
    __syncthreads();
#pragma unroll
    for (int it = 0; it < (H * ROPE) / 256; it++) {
        int idx = tid + it * 256;
        int h = idx >> 6, i = idx & 63;
        long long base = (long long)s * (H * QD) + h * QD + NOPE;
        u16 hb = h16_bits(wv[it]);
        g_qh[base + i] = hb;
        g_ql[base + i] = h16_bits(wv[it] - h16_val(hb));
    }
}

// ---------------- causal row softmax (fp32 in -> fp16 single out) --------------
__global__ void __launch_bounds__(256)
softmax_kernel()
{
    const int s = blockIdx.x, h = blockIdx.y;
    const float* row = g_p + ((long long)h * S + s) * S;
    u16* ph = g_ph + ((long long)h * S + s) * S;
    __shared__ float sh[S];
    __shared__ float red[33];
    const int n = s + 1;
    const int nz = ((s >> 7) + 1) << 7;   // round_up(n,128)
    const int tid = threadIdx.x;

    float mx = -3.0e38f;
    for (int t = tid; t < n; t += 256) { float v = row[t]; sh[t] = v; mx = fmaxf(mx, v); }
#pragma unroll
    for (int o = 16; o > 0; o >>= 1) mx = fmaxf(mx, __shfl_xor_sync(0xffffffffu, mx, o));
    if ((tid & 31) == 0) red[tid >> 5] = mx;
    __syncthreads();
    if (tid < 32) {
        float v = (tid < 8) ? red[tid] : -3.0e38f;
#pragma unroll
        for (int o = 16; o > 0; o >>= 1) v = fmaxf(v, __shfl_xor_sync(0xffffffffu, v, o));
        if (tid == 0) red[32] = v;
    }
    __syncthreads();
    mx = red[32];

    float sum = 0.f;
    for (int t = tid; t < n; t += 256) { float e = expf(sh[t] - mx); sh[t] = e; sum += e; }
#pragma unroll
    for (int o = 16; o > 0; o >>= 1) sum += __shfl_xor_sync(0xffffffffu, sum, o);
    if ((tid & 31) == 0) red[tid >> 5] = sum;
    __syncthreads();
    if (tid < 32) {
        float v = (tid < 8) ? red[tid] : 0.f;
#pragma unroll
        for (int o = 16; o > 0; o >>= 1) v += __shfl_xor_sync(0xffffffffu, v, o);
        if (tid == 0) red[32] = v;
    }
    __syncthreads();
    const float inv = 1.0f / red[32];

    for (int t = tid; t < n; t += 256) ph[t] = h16_bits(sh[t] * inv);
    for (int t = n + tid; t < nz; t += 256) ph[t] = 0;
}

// ---------------- launch --------------------------------------------------------
extern "C" void kernel_launch(void* const* d_in, const int* in_sizes, int n_in,
                              void* d_out, int out_size)
{
    (void)in_sizes; (void)n_in; (void)out_size;
    const float* x      = (const float*)d_in[0];
    const float* cosp   = (const float*)d_in[1];
    const float* sinp   = (const float*)d_in[2];
    const float* w_q    = (const float*)d_in[3];
    const float* w_kv_a = (const float*)d_in[4];
    const float* normw  = (const float*)d_in[5];
    const float* kc     = (const float*)d_in[6];
    const float* vc     = (const float*)d_in[7];
    const float* w_o    = (const float*)d_in[8];
    float* out = (float*)d_out;

    float *kv, *p;
    u16 *x16, *qh, *ql, *lat16, *kc16, *kf2, *vT16, *ph, *pv16;
    u16 *wqT16, *wkvaT16, *vcT16, *woT16;
    cudaGetSymbolAddress((void**)&kv, g_kv);
    cudaGetSymbolAddress((void**)&p,  g_p);
    cudaGetSymbolAddress((void**)&x16, g_x16);
    cudaGetSymbolAddress((void**)&qh, g_qh);     cudaGetSymbolAddress((void**)&ql, g_ql);
    cudaGetSymbolAddress((void**)&lat16, g_lat16);
    cudaGetSymbolAddress((void**)&kc16, g_kc16);
    cudaGetSymbolAddress((void**)&kf2, g_kf2);
    cudaGetSymbolAddress((void**)&vT16, g_vT16);
    cudaGetSymbolAddress((void**)&ph, g_ph);
    cudaGetSymbolAddress((void**)&pv16, g_pv16);
    cudaGetSymbolAddress((void**)&wqT16, g_wqT16);
    cudaGetSymbolAddress((void**)&wkvaT16, g_wkvaT16);
    cudaGetSymbolAddress((void**)&vcT16, g_vcT16);
    cudaGetSymbolAddress((void**)&woT16, g_woT16);

    const int SM_M0_128 = 2 * (20480 + 128 * 80);  // 61440
    const int SM_M1_128 = 2 * (10240 + 128 * 80);  // 40960
    const int SM_M1_64  = 2 * (10240 + 64 * 80);   // 30720
    cudaFuncSetAttribute(mma_gemm<128, 0, 0>, cudaFuncAttributeMaxDynamicSharedMemorySize, SM_M0_128);
    cudaFuncSetAttribute(mma_gemm<128, 1, 0>, cudaFuncAttributeMaxDynamicSharedMemorySize, SM_M1_128);
    cudaFuncSetAttribute(mma_gemm<128, 1, 1>, cudaFuncAttributeMaxDynamicSharedMemorySize, SM_M1_128);
    cudaFuncSetAttribute(mma_gemm<128, 1, 4>, cudaFuncAttributeMaxDynamicSharedMemorySize, SM_M1_128);
    cudaFuncSetAttribute(mma_gemm<64, 1, 0>,  cudaFuncAttributeMaxDynamicSharedMemorySize, SM_M1_64);

    dim3 tb(32, 8);

    // [0] x -> fp16
    half_kernel<<<(S * HID) / 1024, 256>>>(x, x16, (long long)S * HID);
    // [1..3] weight transposes -> fp16 K-major
    transpose_half_kernel<<<dim3((H * QD) / 32, HID / 32, 1), tb>>>(w_q, wqT16, H * QD, HID, 0, 0);
    transpose_half_kernel<<<dim3(D / 32, HID / 32, 1), tb>>>(w_kv_a, wkvaT16, D, HID, 0, 0);
    transpose_half_kernel<<<dim3(VH / 32, KVR / 32, H), tb>>>(vc, vcT16, VH, KVR,
        (long long)KVR * VH, (long long)KVR * VH);
    // [4] kc -> fp16 (natural layout is K-major [h][128,512])
    half_kernel<<<(H * NOPE * KVR) / 1024, 256>>>(kc, kc16, (long long)H * NOPE * KVR);

    // [5] q = x @ w_q  (single-A, split out; ncu -s 5 target)
    mma_gemm<128, 1, 1><<<dim3((H * QD) / 128, S / 128, 1), 256, SM_M1_128>>>(
        x16, nullptr, wqT16, nullptr, qh, ql, HID, HID, HID, H * QD, 0, 0, 0, 1.0f, 0);

    // [6] w_o^T fp16
    transpose_half_kernel<<<dim3(HID / 32, (H * VH) / 32, 1), tb>>>(w_o, woT16, HID, H * VH, 0, 0);

    // [7] kv = x @ w_kv_a  (single-A, fp32 out)
    mma_gemm<64, 1, 0><<<dim3(D / 64, S / 128, 1), 256, SM_M1_64>>>(
        x16, nullptr, wkvaT16, kv, nullptr, nullptr, HID, HID, HID, D, 0, 0, 0, 1.0f, 0);

    // [8] rmsnorm + rope
    prep_kernel<<<S, 256>>>(cosp, sinp, normw);

    // [9] k_nope[h] = latent @ kc[h]^T -> kf2[h][:, 0:128]  (M=S, N=128, K=512)
    mma_gemm<128, 1, 4><<<dim3(1, S / 128, H), 256, SM_M1_128>>>(
        lat16, nullptr, kc16, nullptr, kf2, nullptr, KVR, KVR, KVR, D2,
        0LL, (long long)NOPE * KVR, (long long)S * D2, 1.0f, 0);

    // [10] vT[h] = vc[h]^T @ latent^T -> [128, S]  (M=128, N=S, K=512)
    mma_gemm<128, 1, 4><<<dim3(S / 128, 1, H), 256, SM_M1_128>>>(
        vcT16, nullptr, lat16, nullptr, vT16, nullptr, KVR, KVR, KVR, S,
        (long long)VH * KVR, 0LL, (long long)VH * S, 1.0f, 0);

    // [11] scores = SCALE * q[h] @ kf2[h]^T over 192 dims  (2-term A, causal skip)
    mma_gemm<128, 0, 0><<<dim3(S / 128, S / 128, H), 256, SM_M0_128>>>(
        qh, ql, kf2, p, nullptr, nullptr, D2, H * QD, D2, S,
        (long long)QD, (long long)S * D2, (long long)S * S, SCALE, 1);

    // [12] softmax -> P fp16 single
    softmax_kernel<<<dim3(S, H), 256>>>();

    // [13] pv = P @ v  (single-A, K truncated, fp16 single out into [S, H*VH])
    mma_gemm<128, 1, 4><<<dim3(1, S / 128, H), 256, SM_M1_128>>>(
        ph, nullptr, vT16, nullptr, pv16, nullptr, S, S, S, H * VH,
        (long long)S * S, (long long)VH * S, (long long)VH, 1.0f, 2);

    // [14] out = pv @ w_o  (single-A, fp32 final)
    mma_gemm<128, 1, 0><<<dim3(HID / 128, S / 128, 1), 256, SM_M1_128>>>(
        pv16, nullptr, woT16, out, nullptr, nullptr, H * VH, H * VH, H * VH, HID,
        0, 0, 0, 1.0f, 0);
}

// round 16
// speedup vs baseline: 6.4441x; 1.0281x over previous
#include <cuda_runtime.h>
#include <cuda_fp16.h>
#include <cstdint>
#include <cstring>

#define S    2048
#define HID  2048
#define H    16
#define NOPE 128
#define ROPE 64
#define QD   192   // NOPE+ROPE
#define KVR  512
#define D    576   // KVR+ROPE
#define D2   192   // NOPE+ROPE (scoring dim, un-absorbed)
#define VH   128
#define SCALE 0.07216878364870323f
#define EPS  1e-6f

typedef unsigned short u16;

// ---------------- scratch (device globals) ------------------------------------
__device__ float g_kv[(long long)S * D];            // x @ w_kv_a (fp32)
__device__ float g_p[(long long)H * S * S];         // scores fp32
// fp16 split pairs (A of 2-term stages)
__device__ u16 g_qh[(long long)S * H * QD],  g_ql[(long long)S * H * QD];   // q (+roped q_pe)
// fp16 single
__device__ u16 g_x16[(long long)S * HID];
__device__ u16 g_lat16[(long long)S * KVR];         // rmsnorm'd latent, dense [S,512]
__device__ u16 g_kc16[(long long)H * NOPE * KVR];   // kc fp16 (natural K-major)
__device__ u16 g_kf2[(long long)H * S * D2];        // [k_nope | k_pe] per head, ld=192
__device__ u16 g_vT16[(long long)H * VH * S];       // v^T per head [128, S]
__device__ u16 g_ph[(long long)H * S * S];          // softmax out (single)
__device__ u16 g_pv16[(long long)S * H * VH];       // P@v (single, A of out-proj)
// fp16 single B weights (K-major)
__device__ u16 g_wqT16[(long long)(H * QD) * HID];
__device__ u16 g_wkvaT16[(long long)D * HID];
__device__ u16 g_vcT16[(long long)H * VH * KVR];
__device__ u16 g_woT16[(long long)HID * (H * VH)];

// ---------------- helpers -----------------------------------------------------
__device__ __forceinline__ uint32_t smem_u32(const void* p) {
    uint32_t a;
    asm("{ .reg .u64 t; cvta.to.shared.u64 t, %1; cvt.u32.u64 %0, t; }" : "=r"(a) : "l"(p));
    return a;
}
__device__ __forceinline__ u16 h16_bits(float v) {
    __half b = __float2half_rn(v); u16 u; memcpy(&u, &b, 2); return u;
}
__device__ __forceinline__ float h16_val(u16 u) {
    __half b; memcpy(&b, &u, 2); return __half2float(b);
}
__device__ __forceinline__ void split_h_pack(float x, float y, uint32_t& h, uint32_t& l) {
    __half2 hv = __floats2half2_rn(x, y);
    __half2 lv = __floats2half2_rn(x - __half2float(__low2half(hv)),
                                   y - __half2float(__high2half(hv)));
    memcpy(&h, &hv, 4); memcpy(&l, &lv, 4);
}
__device__ __forceinline__ uint32_t h2_pack(float x, float y) {
    __half2 hv = __floats2half2_rn(x, y);
    uint32_t u; memcpy(&u, &hv, 4); return u;
}

#define CP_ASYNC16(dst, src) \
    asm volatile("cp.async.cg.shared.global [%0], [%1], 16;" :: "r"(dst), "l"(src))
#define CP_COMMIT() asm volatile("cp.async.commit_group;" ::: "memory")
#define CP_WAIT(n)  asm volatile("cp.async.wait_group %0;" :: "n"(n) : "memory")

#define LDMX4(r0, r1, r2, r3, addr) \
    asm volatile("ldmatrix.sync.aligned.m8n8.x4.shared.b16 {%0,%1,%2,%3}, [%4];" \
        : "=r"(r0), "=r"(r1), "=r"(r2), "=r"(r3) : "r"(addr))

#define MMA_F16(d, a, b0v, b1v) \
    asm volatile("mma.sync.aligned.m16n8k16.row.col.f32.f16.f16.f32 " \
        "{%0,%1,%2,%3}, {%4,%5,%6,%7}, {%8,%9}, {%0,%1,%2,%3};" \
        : "+f"((d)[0]), "+f"((d)[1]), "+f"((d)[2]), "+f"((d)[3]) \
        : "r"((a)[0]), "r"((a)[1]), "r"((a)[2]), "r"((a)[3]), "r"(b0v), "r"(b1v))

// ---------------- fp16 mma.sync GEMM -------------------------------------------
// C[M,N] = alpha * A[M,K] @ B[N,K]^T. B = fp16 single, K-major.
// MODE 0: A = fp16 hi/lo pair (2 MMAs). MODE 1: A = fp16 single (1 MMA).
// Block tile 128 x NT x 32; 8 warps = 2(m) x 4(n).
// EPI: 0=fp32 C; 1=fp16 split (Ch,Cl); 4=fp16 single (Ch).
// causal_mode: 0 none; 1 skip colbase>=rowbase+128; 2 kmax=rowbase+128.
template<int NT, int MODE, int EPI>
__global__ void __launch_bounds__(256)
mma_gemm(const u16* __restrict__ Agh, const u16* __restrict__ Agl,
         const u16* __restrict__ Bg,
         float* __restrict__ C, u16* __restrict__ Ch, u16* __restrict__ Cl,
         int K, int lda, int ldb, int ldc,
         long long sA, long long sB, long long sC, float alpha, int causal_mode)
{
    constexpr int WTN = NT / 4, NFRAG = WTN / 8, MFRAG = 4;
    constexpr int OFF_AL = 10240;
    constexpr int OFF_B = (MODE == 0) ? 20480 : 10240;
    constexpr int BUFB = OFF_B + NT * 80;
    constexpr int BC = (NT * 4) / 256;

    const int rowbase = blockIdx.y * 128;
    const int colbase = blockIdx.x * NT;
    if (causal_mode == 1 && colbase >= rowbase + 128) return;
    const int kmax = (causal_mode == 2) ? min(K, rowbase + 128) : K;
    const int nk = kmax >> 5;

    Agh += blockIdx.z * sA;
    if (MODE == 0) Agl += blockIdx.z * sA;
    Bg += blockIdx.z * sB;

    extern __shared__ char smem[];
    const uint32_t sb = smem_u32(smem);
    const int tid = threadIdx.x, wid = tid >> 5, lane = tid & 31;
    const int wm = wid >> 2, wn = wid & 3;
    const int lr = lane >> 2, lc = lane & 3;

    float acc[MFRAG][NFRAG][4];
#pragma unroll
    for (int i = 0; i < MFRAG; i++)
#pragma unroll
        for (int j = 0; j < NFRAG; j++)
#pragma unroll
            for (int q = 0; q < 4; q++) acc[i][j][q] = 0.f;

    auto issue_tile = [&](int kt, int buf) {
        const uint32_t base = sb + buf * BUFB;
        const int k0 = kt << 5;
#pragma unroll
        for (int i = 0; i < 2; i++) {
            int idx = tid + i * 256, r = idx >> 2, c = idx & 3;
            long long g = (long long)(rowbase + r) * lda + k0 + c * 8;
            uint32_t so = (uint32_t)(r * 80 + c * 16);
            CP_ASYNC16(base + so, Agh + g);
            if (MODE == 0) CP_ASYNC16(base + OFF_AL + so, Agl + g);
        }
#pragma unroll
        for (int i = 0; i < BC; i++) {
            int idx = tid + i * 256, r = idx >> 2, c = idx & 3;
            long long g = (long long)(colbase + r) * ldb + k0 + c * 8;
            uint32_t so = (uint32_t)(r * 80 + c * 16);
            CP_ASYNC16(base + OFF_B + so, Bg + g);
        }
        CP_COMMIT();
    };

    issue_tile(0, 0);

    for (int kt = 0; kt < nk; kt++) {
        CP_WAIT(0);
        __syncthreads();
        if (kt + 1 < nk) issue_tile(kt + 1, (kt + 1) & 1);   // overlaps with compute

        const uint32_t base = sb + (kt & 1) * BUFB;
        uint32_t bh[NFRAG][4];
#pragma unroll
        for (int nf = 0; nf < NFRAG; nf++) {
            int n = wn * WTN + nf * 8 + (lane & 7);
            uint32_t ad = base + OFF_B + n * 80 + (lane >> 3) * 16;
            LDMX4(bh[nf][0], bh[nf][1], bh[nf][2], bh[nf][3], ad);
        }
#pragma unroll
        for (int ks = 0; ks < 2; ks++) {
#pragma unroll
            for (int mf = 0; mf < MFRAG; mf++) {
                int r = wm * 64 + mf * 16 + (lane & 15);
                uint32_t ad = base + r * 80 + (lane >> 4) * 16 + ks * 32;
                uint32_t ah[4];
                LDMX4(ah[0], ah[1], ah[2], ah[3], ad);
#pragma unroll
                for (int nf = 0; nf < NFRAG; nf++)
                    MMA_F16(acc[mf][nf], ah, bh[nf][2 * ks], bh[nf][2 * ks + 1]);
                if (MODE == 0) {
                    uint32_t al[4];
                    LDMX4(al[0], al[1], al[2], al[3], ad + OFF_AL);
#pragma unroll
                    for (int nf = 0; nf < NFRAG; nf++)
                        MMA_F16(acc[mf][nf], al, bh[nf][2 * ks], bh[nf][2 * ks + 1]);
                }
            }
        }
    }

    // ---- epilogue
#pragma unroll
    for (int mf = 0; mf < MFRAG; mf++) {
        int r0 = rowbase + wm * 64 + mf * 16 + lr;
#pragma unroll
        for (int nf = 0; nf < NFRAG; nf++) {
            int c0 = colbase + wn * WTN + nf * 8 + lc * 2;
            float v00 = acc[mf][nf][0] * alpha, v01 = acc[mf][nf][1] * alpha;
            float v10 = acc[mf][nf][2] * alpha, v11 = acc[mf][nf][3] * alpha;
            long long o0 = (long long)r0 * ldc + c0 + blockIdx.z * sC;
            long long o1 = (long long)(r0 + 8) * ldc + c0 + blockIdx.z * sC;
            if (EPI == 0) {
                *(float2*)(C + o0) = make_float2(v00, v01);
                *(float2*)(C + o1) = make_float2(v10, v11);
            }
            if (EPI == 1) {
                uint32_t h0, l0, h1, l1;
                split_h_pack(v00, v01, h0, l0); split_h_pack(v10, v11, h1, l1);
                *(uint32_t*)(Ch + o0) = h0; *(uint32_t*)(Cl + o0) = l0;
                *(uint32_t*)(Ch + o1) = h1; *(uint32_t*)(Cl + o1) = l1;
            }
            if (EPI == 4) {
                *(uint32_t*)(Ch + o0) = h2_pack(v00, v01);
                *(uint32_t*)(Ch + o1) = h2_pack(v10, v11);
            }
        }
    }
}

// ---------------- fp32 -> fp16 single (elementwise) ----------------------------
__global__ void __launch_bounds__(256)
half_kernel(const float* __restrict__ in, u16* __restrict__ o, long long n)
{
    long long i = ((long long)blockIdx.x * 256 + threadIdx.x) * 4;
    if (i >= n) return;
    float4 v = *(const float4*)(in + i);
    *(uint32_t*)(o + i) = h2_pack(v.x, v.y);
    *(uint32_t*)(o + i + 2) = h2_pack(v.z, v.w);
}

// ---------------- fp32 transpose -> fp16 single --------------------------------
__global__ void __launch_bounds__(256)
transpose_half_kernel(const float* __restrict__ in, u16* __restrict__ out,
                      int ldin, int ldout, long long sIn, long long sOut)
{
    __shared__ float t[32][33];
    const float* ip = in + blockIdx.z * sIn;
    const int c0 = blockIdx.x * 32, r0 = blockIdx.y * 32;
#pragma unroll
    for (int i = 0; i < 4; i++) {
        int r = threadIdx.y + i * 8;
        t[r][threadIdx.x] = ip[(long long)(r0 + r) * ldin + c0 + threadIdx.x];
    }
    __syncthreads();
#pragma unroll
    for (int i = 0; i < 4; i++) {
        int c = threadIdx.y + i * 8;
        long long o = blockIdx.z * sOut + (long long)(c0 + c) * ldout + r0 + threadIdx.x;
        out[o] = h16_bits(t[threadIdx.x][c]);
    }
}

// ---------------- rmsnorm(latent) + RoPE ---------------------------------------
__global__ void __launch_bounds__(256)
prep_kernel(const float* __restrict__ cosp, const float* __restrict__ sinp,
            const float* __restrict__ normw)
{
    const int s = blockIdx.x;
    const int tid = threadIdx.x;
    const float* kv = g_kv + (long long)s * D;

    float ss = 0.f;
    for (int i = tid; i < KVR; i += 256) { float v = kv[i]; ss += v * v; }
    __shared__ float red[32];
#pragma unroll
    for (int o = 16; o > 0; o >>= 1) ss += __shfl_xor_sync(0xffffffffu, ss, o);
    if ((tid & 31) == 0) red[tid >> 5] = ss;
    __syncthreads();
    if (tid < 32) {
        float v = (tid < 8) ? red[tid] : 0.f;
#pragma unroll
        for (int o = 16; o > 0; o >>= 1) v += __shfl_xor_sync(0xffffffffu, v, o);
        if (tid == 0) red[0] = v;
    }
    __syncthreads();
    const float r = rsqrtf(red[0] / (float)KVR + EPS);

    for (int i = tid; i < KVR; i += 256)
        g_lat16[(long long)s * KVR + i] = h16_bits(kv[i] * r * normw[i]);

    const float* cs = cosp + (long long)s * ROPE;
    const float* sn = sinp + (long long)s * ROPE;

    __shared__ u16 kpe[ROPE];
    for (int i = tid; i < ROPE; i += 256) {
        float v = kv[KVR + i];
        float rot = (i < 32) ? -kv[KVR + i + 32] : kv[KVR + i - 32];
        kpe[i] = h16_bits(v * cs[i] + rot * sn[i]);
    }
    __syncthreads();
    // replicate roped k_pe into all H per-head kf2 rows
    for (int idx = tid; idx < H * ROPE; idx += 256) {
        int h = idx >> 6, i = idx & 63;
        g_kf2[(long long)h * S * D2 + (long long)s * D2 + NOPE + i] = kpe[i];
    }

    // rope q_pe in place: read all (uniform trip count), barrier, then write
    float wv[(H * ROPE) / 256];
#pragma unroll
    for (int it = 0; it < (H * ROPE) / 256; it++) {
        int idx = tid + it * 256;
        int h = idx >> 6, i = idx & 63;
        long long base = (long long)s * (H * QD) + h * QD + NOPE;
        float v = h16_val(g_qh[base + i]) + h16_val(g_ql[base + i]);
        float ro = (i < 32)
            ? -(h16_val(g_qh[base + i + 32]) + h16_val(g_ql[base + i + 32]))
            :  (h16_val(g_qh[base + i - 32]) + h16_val(g_ql[base + i - 32]));
        wv[it] = v * cs[i] + ro * sn[i];
    }
    __syncthreads();
#pragma unroll
    for (int it = 0; it < (H * ROPE) / 256; it++) {
        int idx = tid + it * 256;
        int h = idx >> 6, i = idx & 63;
        long long base = (long long)s * (H * QD) + h * QD + NOPE;
        u16 hb = h16_bits(wv[it]);
        g_qh[base + i] = hb;
        g_ql[base + i] = h16_bits(wv[it] - h16_val(hb));
    }
}

// ---------------- causal row softmax (fp32 in -> fp16 single out) --------------
__global__ void __launch_bounds__(256)
softmax_kernel()
{
    const int s = blockIdx.x, h = blockIdx.y;
    const float* row = g_p + ((long long)h * S + s) * S;
    u16* ph = g_ph + ((long long)h * S + s) * S;
    __shared__ float sh[S];
    __shared__ float red[33];
    const int n = s + 1;
    const int nz = ((s >> 7) + 1) << 7;   // round_up(n,128)
    const int tid = threadIdx.x;

    float mx = -3.0e38f;
    for (int t = tid; t < n; t += 256) { float v = row[t]; sh[t] = v; mx = fmaxf(mx, v); }
#pragma unroll
    for (int o = 16; o > 0; o >>= 1) mx = fmaxf(mx, __shfl_xor_sync(0xffffffffu, mx, o));
    if ((tid & 31) == 0) red[tid >> 5] = mx;
    __syncthreads();
    if (tid < 32) {
        float v = (tid < 8) ? red[tid] : -3.0e38f;
#pragma unroll
        for (int o = 16; o > 0; o >>= 1) v = fmaxf(v, __shfl_xor_sync(0xffffffffu, v, o));
        if (tid == 0) red[32] = v;
    }
    __syncthreads();
    mx = red[32];

    float sum = 0.f;
    for (int t = tid; t < n; t += 256) { float e = expf(sh[t] - mx); sh[t] = e; sum += e; }
#pragma unroll
    for (int o = 16; o > 0; o >>= 1) sum += __shfl_xor_sync(0xffffffffu, sum, o);
    if ((tid & 31) == 0) red[tid >> 5] = sum;
    __syncthreads();
    if (tid < 32) {
        float v = (tid < 8) ? red[tid] : 0.f;
#pragma unroll
        for (int o = 16; o > 0; o >>= 1) v += __shfl_xor_sync(0xffffffffu, v, o);
        if (tid == 0) red[32] = v;
    }
    __syncthreads();
    const float inv = 1.0f / red[32];

    for (int t = tid; t < n; t += 256) ph[t] = h16_bits(sh[t] * inv);
    for (int t = n + tid; t < nz; t += 256) ph[t] = 0;
}

// ---------------- stream/event helpers (created once, outside capture) ---------
static cudaStream_t make_stream() {
    cudaStream_t s; cudaStreamCreateWithFlags(&s, cudaStreamNonBlocking); return s;
}
static cudaEvent_t make_event() {
    cudaEvent_t e; cudaEventCreateWithFlags(&e, cudaEventDisableTiming); return e;
}

// ---------------- launch --------------------------------------------------------
extern "C" void kernel_launch(void* const* d_in, const int* in_sizes, int n_in,
                              void* d_out, int out_size)
{
    (void)in_sizes; (void)n_in; (void)out_size;
    const float* x      = (const float*)d_in[0];
    const float* cosp   = (const float*)d_in[1];
    const float* sinp   = (const float*)d_in[2];
    const float* w_q    = (const float*)d_in[3];
    const float* w_kv_a = (const float*)d_in[4];
    const float* normw  = (const float*)d_in[5];
    const float* kc     = (const float*)d_in[6];
    const float* vc     = (const float*)d_in[7];
    const float* w_o    = (const float*)d_in[8];
    float* out = (float*)d_out;

    float *kv, *p;
    u16 *x16, *qh, *ql, *lat16, *kc16, *kf2, *vT16, *ph, *pv16;
    u16 *wqT16, *wkvaT16, *vcT16, *woT16;
    cudaGetSymbolAddress((void**)&kv, g_kv);
    cudaGetSymbolAddress((void**)&p,  g_p);
    cudaGetSymbolAddress((void**)&x16, g_x16);
    cudaGetSymbolAddress((void**)&qh, g_qh);     cudaGetSymbolAddress((void**)&ql, g_ql);
    cudaGetSymbolAddress((void**)&lat16, g_lat16);
    cudaGetSymbolAddress((void**)&kc16, g_kc16);
    cudaGetSymbolAddress((void**)&kf2, g_kf2);
    cudaGetSymbolAddress((void**)&vT16, g_vT16);
    cudaGetSymbolAddress((void**)&ph, g_ph);
    cudaGetSymbolAddress((void**)&pv16, g_pv16);
    cudaGetSymbolAddress((void**)&wqT16, g_wqT16);
    cudaGetSymbolAddress((void**)&wkvaT16, g_wkvaT16);
    cudaGetSymbolAddress((void**)&vcT16, g_vcT16);
    cudaGetSymbolAddress((void**)&woT16, g_woT16);

    const int SM_M0_128 = 2 * (20480 + 128 * 80);  // 61440
    const int SM_M1_128 = 2 * (10240 + 128 * 80);  // 40960
    const int SM_M1_64  = 2 * (10240 + 64 * 80);   // 30720
    cudaFuncSetAttribute(mma_gemm<128, 0, 0>, cudaFuncAttributeMaxDynamicSharedMemorySize, SM_M0_128);
    cudaFuncSetAttribute(mma_gemm<128, 1, 0>, cudaFuncAttributeMaxDynamicSharedMemorySize, SM_M1_128);
    cudaFuncSetAttribute(mma_gemm<128, 1, 1>, cudaFuncAttributeMaxDynamicSharedMemorySize, SM_M1_128);
    cudaFuncSetAttribute(mma_gemm<128, 1, 4>, cudaFuncAttributeMaxDynamicSharedMemorySize, SM_M1_128);
    cudaFuncSetAttribute(mma_gemm<64, 1, 0>,  cudaFuncAttributeMaxDynamicSharedMemorySize, SM_M1_64);

    // streams/events created once on the first (uncaptured) correctness call;
    // reused inside capture — fork/join edges become graph dependencies.
    static cudaStream_t s1 = make_stream();
    static cudaStream_t s2 = make_stream();
    static cudaEvent_t eA = make_event();   // fork at entry
    static cudaEvent_t e2 = make_event();   // wkvaT done
    static cudaEvent_t e3 = make_event();   // all side-stream weight prep done
    static cudaEvent_t eP = make_event();   // prep done (for vT fork)
    static cudaEvent_t eV = make_event();   // vT done

    dim3 tb(32, 8);

    // ---- fork: side stream does the weight conversions not needed by q-GEMM
    cudaEventRecord(eA, 0);
    cudaStreamWaitEvent(s1, eA, 0);
    transpose_half_kernel<<<dim3(D / 32, HID / 32, 1), tb, 0, s1>>>(
        w_kv_a, wkvaT16, D, HID, 0, 0);
    cudaEventRecord(e2, s1);
    transpose_half_kernel<<<dim3(VH / 32, KVR / 32, H), tb, 0, s1>>>(
        vc, vcT16, VH, KVR, (long long)KVR * VH, (long long)KVR * VH);
    half_kernel<<<(H * NOPE * KVR) / 1024, 256, 0, s1>>>(kc, kc16, (long long)H * NOPE * KVR);
    transpose_half_kernel<<<dim3(HID / 32, (H * VH) / 32, 1), tb, 0, s1>>>(
        w_o, woT16, HID, H * VH, 0, 0);
    cudaEventRecord(e3, s1);

    // ---- main stream: x conversion + q projection (overlaps side stream)
    half_kernel<<<(S * HID) / 1024, 256>>>(x, x16, (long long)S * HID);
    transpose_half_kernel<<<dim3((H * QD) / 32, HID / 32, 1), tb>>>(w_q, wqT16, H * QD, HID, 0, 0);
    mma_gemm<128, 1, 1><<<dim3((H * QD) / 128, S / 128, 1), 256, SM_M1_128>>>(
        x16, nullptr, wqT16, nullptr, qh, ql, HID, HID, HID, H * QD, 0, 0, 0, 1.0f, 0);

    // kv needs wkvaT
    cudaStreamWaitEvent(0, e2, 0);
    mma_gemm<64, 1, 0><<<dim3(D / 64, S / 128, 1), 256, SM_M1_64>>>(
        x16, nullptr, wkvaT16, kv, nullptr, nullptr, HID, HID, HID, D, 0, 0, 0, 1.0f, 0);

    // rmsnorm + rope (needs kv + q)
    prep_kernel<<<S, 256>>>(cosp, sinp, normw);
    cudaEventRecord(eP, 0);

    // join remaining weight prep (kc16 for k_nope, vcT for vT, woT for out)
    cudaStreamWaitEvent(0, e3, 0);

    // vT on s2, concurrent with k_nope on main
    cudaStreamWaitEvent(s2, eP, 0);
    cudaStreamWaitEvent(s2, e3, 0);
    mma_gemm<128, 1, 4><<<dim3(S / 128, 1, H), 256, SM_M1_128, s2>>>(
        vcT16, nullptr, lat16, nullptr, vT16, nullptr, KVR, KVR, KVR, S,
        (long long)VH * KVR, 0LL, (long long)VH * S, 1.0f, 0);
    cudaEventRecord(eV, s2);

    // k_nope[h] = latent @ kc[h]^T -> kf2[h][:, 0:128]
    mma_gemm<128, 1, 4><<<dim3(1, S / 128, H), 256, SM_M1_128>>>(
        lat16, nullptr, kc16, nullptr, kf2, nullptr, KVR, KVR, KVR, D2,
        0LL, (long long)NOPE * KVR, (long long)S * D2, 1.0f, 0);

    // scores = SCALE * q[h] @ kf2[h]^T over 192 dims  (2-term A, causal skip)
    mma_gemm<128, 0, 0><<<dim3(S / 128, S / 128, H), 256, SM_M0_128>>>(
        qh, ql, kf2, p, nullptr, nullptr, D2, H * QD, D2, S,
        (long long)QD, (long long)S * D2, (long long)S * S, SCALE, 1);

    // softmax -> P fp16 single
    softmax_kernel<<<dim3(S, H), 256>>>();

    // PV needs vT
    cudaStreamWaitEvent(0, eV, 0);
    mma_gemm<128, 1, 4><<<dim3(1, S / 128, H), 256, SM_M1_128>>>(
        ph, nullptr, vT16, nullptr, pv16, nullptr, S, S, S, H * VH,
        (long long)S * S, (long long)VH * S, (long long)VH, 1.0f, 2);

    // out = pv @ w_o  (single-A, fp32 final)
    mma_gemm<128, 1, 0><<<dim3(HID / 128, S / 128, 1), 256, SM_M1_128>>>(
        pv16, nullptr, woT16, out, nullptr, nullptr, H * VH, H * VH, H * VH, HID,
        0, 0, 0, 1.0f, 0);
}

// round 17
// speedup vs baseline: 8.8309x; 1.3704x over previous
#include <cuda_runtime.h>
#include <cuda_fp16.h>
#include <cstdint>
#include <cstring>

#define S    2048
#define HID  2048
#define H    16
#define NOPE 128
#define ROPE 64
#define QD   192   // NOPE+ROPE
#define KVR  512
#define D    576   // KVR+ROPE
#define D2   192   // NOPE+ROPE (scoring dim, un-absorbed)
#define VH   128
#define SCALE 0.07216878364870323f
#define EPS  1e-6f

typedef unsigned short u16;

// ---------------- scratch (device globals) ------------------------------------
__device__ float g_kv[(long long)S * D];            // x @ w_kv_a (fp32)
// fp16 split pairs (A of 2-term stages)
__device__ u16 g_qh[(long long)S * H * QD],  g_ql[(long long)S * H * QD];   // q (+roped q_pe)
// fp16 single
__device__ u16 g_x16[(long long)S * HID];
__device__ u16 g_lat16[(long long)S * KVR];         // rmsnorm'd latent, dense [S,512]
__device__ u16 g_kc16[(long long)H * NOPE * KVR];   // kc fp16 (natural K-major)
__device__ u16 g_kf2[(long long)H * S * D2];        // [k_nope | k_pe] per head, ld=192
__device__ u16 g_vT16[(long long)H * VH * S];       // v^T per head [128, S]
__device__ u16 g_pv16[(long long)S * H * VH];       // P@v (single, A of out-proj)
// fp16 single B weights (K-major)
__device__ u16 g_wqT16[(long long)(H * QD) * HID];
__device__ u16 g_wkvaT16[(long long)D * HID];
__device__ u16 g_vcT16[(long long)H * VH * KVR];
__device__ u16 g_woT16[(long long)HID * (H * VH)];

// ---------------- helpers -----------------------------------------------------
__device__ __forceinline__ uint32_t smem_u32(const void* p) {
    uint32_t a;
    asm("{ .reg .u64 t; cvta.to.shared.u64 t, %1; cvt.u32.u64 %0, t; }" : "=r"(a) : "l"(p));
    return a;
}
__device__ __forceinline__ u16 h16_bits(float v) {
    __half b = __float2half_rn(v); u16 u; memcpy(&u, &b, 2); return u;
}
__device__ __forceinline__ float h16_val(u16 u) {
    __half b; memcpy(&b, &u, 2); return __half2float(b);
}
__device__ __forceinline__ void split_h_pack(float x, float y, uint32_t& h, uint32_t& l) {
    __half2 hv = __floats2half2_rn(x, y);
    __half2 lv = __floats2half2_rn(x - __half2float(__low2half(hv)),
                                   y - __half2float(__high2half(hv)));
    memcpy(&h, &hv, 4); memcpy(&l, &lv, 4);
}
__device__ __forceinline__ uint32_t h2_pack(float x, float y) {
    __half2 hv = __floats2half2_rn(x, y);
    uint32_t u; memcpy(&u, &hv, 4); return u;
}

#define CP_ASYNC16(dst, src) \
    asm volatile("cp.async.cg.shared.global [%0], [%1], 16;" :: "r"(dst), "l"(src))
#define CP_COMMIT() asm volatile("cp.async.commit_group;" ::: "memory")
#define CP_WAIT(n)  asm volatile("cp.async.wait_group %0;" :: "n"(n) : "memory")

#define LDMX4(r0, r1, r2, r3, addr) \
    asm volatile("ldmatrix.sync.aligned.m8n8.x4.shared.b16 {%0,%1,%2,%3}, [%4];" \
        : "=r"(r0), "=r"(r1), "=r"(r2), "=r"(r3) : "r"(addr))

#define MMA_F16(d, a, b0v, b1v) \
    asm volatile("mma.sync.aligned.m16n8k16.row.col.f32.f16.f16.f32 " \
        "{%0,%1,%2,%3}, {%4,%5,%6,%7}, {%8,%9}, {%0,%1,%2,%3};" \
        : "+f"((d)[0]), "+f"((d)[1]), "+f"((d)[2]), "+f"((d)[3]) \
        : "r"((a)[0]), "r"((a)[1]), "r"((a)[2]), "r"((a)[3]), "r"(b0v), "r"(b1v))

// ---------------- fp16 mma.sync GEMM (unchanged engine) ------------------------
template<int NT, int MODE, int EPI>
__global__ void __launch_bounds__(256)
mma_gemm(const u16* __restrict__ Agh, const u16* __restrict__ Agl,
         const u16* __restrict__ Bg,
         float* __restrict__ C, u16* __restrict__ Ch, u16* __restrict__ Cl,
         int K, int lda, int ldb, int ldc,
         long long sA, long long sB, long long sC, float alpha, int causal_mode)
{
    constexpr int WTN = NT / 4, NFRAG = WTN / 8, MFRAG = 4;
    constexpr int OFF_AL = 10240;
    constexpr int OFF_B = (MODE == 0) ? 20480 : 10240;
    constexpr int BUFB = OFF_B + NT * 80;
    constexpr int BC = (NT * 4) / 256;

    const int rowbase = blockIdx.y * 128;
    const int colbase = blockIdx.x * NT;
    if (causal_mode == 1 && colbase >= rowbase + 128) return;
    const int kmax = (causal_mode == 2) ? min(K, rowbase + 128) : K;
    const int nk = kmax >> 5;

    Agh += blockIdx.z * sA;
    if (MODE == 0) Agl += blockIdx.z * sA;
    Bg += blockIdx.z * sB;

    extern __shared__ char smem[];
    const uint32_t sb = smem_u32(smem);
    const int tid = threadIdx.x, wid = tid >> 5, lane = tid & 31;
    const int wm = wid >> 2, wn = wid & 3;
    const int lr = lane >> 2, lc = lane & 3;

    float acc[MFRAG][NFRAG][4];
#pragma unroll
    for (int i = 0; i < MFRAG; i++)
#pragma unroll
        for (int j = 0; j < NFRAG; j++)
#pragma unroll
            for (int q = 0; q < 4; q++) acc[i][j][q] = 0.f;

    auto issue_tile = [&](int kt, int buf) {
        const uint32_t base = sb + buf * BUFB;
        const int k0 = kt << 5;
#pragma unroll
        for (int i = 0; i < 2; i++) {
            int idx = tid + i * 256, r = idx >> 2, c = idx & 3;
            long long g = (long long)(rowbase + r) * lda + k0 + c * 8;
            uint32_t so = (uint32_t)(r * 80 + c * 16);
            CP_ASYNC16(base + so, Agh + g);
            if (MODE == 0) CP_ASYNC16(base + OFF_AL + so, Agl + g);
        }
#pragma unroll
        for (int i = 0; i < BC; i++) {
            int idx = tid + i * 256, r = idx >> 2, c = idx & 3;
            long long g = (long long)(colbase + r) * ldb + k0 + c * 8;
            uint32_t so = (uint32_t)(r * 80 + c * 16);
            CP_ASYNC16(base + OFF_B + so, Bg + g);
        }
        CP_COMMIT();
    };

    issue_tile(0, 0);

    for (int kt = 0; kt < nk; kt++) {
        CP_WAIT(0);
        __syncthreads();
        if (kt + 1 < nk) issue_tile(kt + 1, (kt + 1) & 1);

        const uint32_t base = sb + (kt & 1) * BUFB;
        uint32_t bh[NFRAG][4];
#pragma unroll
        for (int nf = 0; nf < NFRAG; nf++) {
            int n = wn * WTN + nf * 8 + (lane & 7);
            uint32_t ad = base + OFF_B + n * 80 + (lane >> 3) * 16;
            LDMX4(bh[nf][0], bh[nf][1], bh[nf][2], bh[nf][3], ad);
        }
#pragma unroll
        for (int ks = 0; ks < 2; ks++) {
#pragma unroll
            for (int mf = 0; mf < MFRAG; mf++) {
                int r = wm * 64 + mf * 16 + (lane & 15);
                uint32_t ad = base + r * 80 + (lane >> 4) * 16 + ks * 32;
                uint32_t ah[4];
                LDMX4(ah[0], ah[1], ah[2], ah[3], ad);
#pragma unroll
                for (int nf = 0; nf < NFRAG; nf++)
                    MMA_F16(acc[mf][nf], ah, bh[nf][2 * ks], bh[nf][2 * ks + 1]);
                if (MODE == 0) {
                    uint32_t al[4];
                    LDMX4(al[0], al[1], al[2], al[3], ad + OFF_AL);
#pragma unroll
                    for (int nf = 0; nf < NFRAG; nf++)
                        MMA_F16(acc[mf][nf], al, bh[nf][2 * ks], bh[nf][2 * ks + 1]);
                }
            }
        }
    }

#pragma unroll
    for (int mf = 0; mf < MFRAG; mf++) {
        int r0 = rowbase + wm * 64 + mf * 16 + lr;
#pragma unroll
        for (int nf = 0; nf < NFRAG; nf++) {
            int c0 = colbase + wn * WTN + nf * 8 + lc * 2;
            float v00 = acc[mf][nf][0] * alpha, v01 = acc[mf][nf][1] * alpha;
            float v10 = acc[mf][nf][2] * alpha, v11 = acc[mf][nf][3] * alpha;
            long long o0 = (long long)r0 * ldc + c0 + blockIdx.z * sC;
            long long o1 = (long long)(r0 + 8) * ldc + c0 + blockIdx.z * sC;
            if (EPI == 0) {
                *(float2*)(C + o0) = make_float2(v00, v01);
                *(float2*)(C + o1) = make_float2(v10, v11);
            }
            if (EPI == 1) {
                uint32_t h0, l0, h1, l1;
                split_h_pack(v00, v01, h0, l0); split_h_pack(v10, v11, h1, l1);
                *(uint32_t*)(Ch + o0) = h0; *(uint32_t*)(Cl + o0) = l0;
                *(uint32_t*)(Ch + o1) = h1; *(uint32_t*)(Cl + o1) = l1;
            }
            if (EPI == 4) {
                *(uint32_t*)(Ch + o0) = h2_pack(v00, v01);
                *(uint32_t*)(Ch + o1) = h2_pack(v10, v11);
            }
        }
    }
}

// ---------------- fused flash attention ----------------------------------------
// Per CTA: one head, 128 q rows. Iterates 64-wide kv tiles to the diagonal.
// scores: 2-term A (q hi/lo from smem) vs K tile; online softmax in registers;
// PV accumulated in registers; writes pv16 [S, H*VH] fp16 single.
#define QSTR 400          // 192 fp16 = 384B + 16B pad (conflict-free ldmatrix)
#define VSTR 144          // 64 fp16 = 128B + 16B pad
#define SM_QH 0
#define SM_QL 51200
#define SM_K  102400
#define KBUF  25600       // 64 * 400
#define SM_V  153600
#define VBUF  18432       // 128 * 144
#define SM_FUSED (153600 + 2 * 18432)   // 190464

__global__ void __launch_bounds__(256)
fused_attn_kernel()
{
    const int h = blockIdx.x;
    const int qt = (gridDim.y - 1) - blockIdx.y;    // longest tiles first
    const int rowbase = qt * 128;
    const int nkv = (rowbase >> 6) + 2;
    extern __shared__ char smem[];
    const uint32_t sb = smem_u32(smem);
    const int tid = threadIdx.x, wid = tid >> 5, lane = tid & 31;
    const int lc = lane & 3;

    const u16* kf2 = g_kf2 + (long long)h * S * D2;
    const u16* vT  = g_vT16 + (long long)h * VH * S;

    // Q tile hi/lo: 128 rows x 192 fp16 (24 x 16B chunks per row)
    for (int i = tid; i < 128 * 24; i += 256) {
        int r = i / 24, c = i % 24;
        long long g = (long long)(rowbase + r) * (H * QD) + h * QD + c * 8;
        CP_ASYNC16(sb + SM_QH + r * QSTR + c * 16, g_qh + g);
        CP_ASYNC16(sb + SM_QL + r * QSTR + c * 16, g_ql + g);
    }
    CP_COMMIT();

    auto issue_kv = [&](int j, int buf) {
        const uint32_t kb = sb + SM_K + buf * KBUF;
        const uint32_t vb = sb + SM_V + buf * VBUF;
        for (int i = tid; i < 64 * 24; i += 256) {
            int r = i / 24, c = i % 24;
            CP_ASYNC16(kb + r * QSTR + c * 16,
                       kf2 + (long long)(j * 64 + r) * D2 + c * 8);
        }
        for (int i = tid; i < 128 * 8; i += 256) {
            int r = i >> 3, c = i & 7;
            CP_ASYNC16(vb + r * VSTR + c * 16,
                       vT + (long long)r * S + j * 64 + c * 8);
        }
        CP_COMMIT();
    };
    issue_kv(0, 0);

    float m0 = -1e30f, m1 = -1e30f, l0 = 0.f, l1 = 0.f;
    float o[16][4];
#pragma unroll
    for (int i = 0; i < 16; i++) { o[i][0] = o[i][1] = o[i][2] = o[i][3] = 0.f; }

    const int r0g = rowbase + wid * 16 + (lane >> 2);
    const int r1g = r0g + 8;

    for (int j = 0; j < nkv; j++) {
        CP_WAIT(0);
        __syncthreads();
        if (j + 1 < nkv) issue_kv(j + 1, (j + 1) & 1);
        const uint32_t kb = sb + SM_K + (j & 1) * KBUF;
        const uint32_t vb = sb + SM_V + (j & 1) * VBUF;

        // ---- scores S = q @ k^T (2-term A), acc s[8][4]
        float s[8][4];
#pragma unroll
        for (int i = 0; i < 8; i++) s[i][0] = s[i][1] = s[i][2] = s[i][3] = 0.f;

#pragma unroll
        for (int kc = 0; kc < 6; kc++) {
            uint32_t bh[8][4];
#pragma unroll
            for (int nf = 0; nf < 8; nf++) {
                int n = nf * 8 + (lane & 7);
                LDMX4(bh[nf][0], bh[nf][1], bh[nf][2], bh[nf][3],
                      kb + n * QSTR + kc * 64 + (lane >> 3) * 16);
            }
#pragma unroll
            for (int ks = 0; ks < 2; ks++) {
                int r = wid * 16 + (lane & 15);
                uint32_t ad = sb + SM_QH + r * QSTR + kc * 64 + ks * 32 + (lane >> 4) * 16;
                uint32_t ah[4], al[4];
                LDMX4(ah[0], ah[1], ah[2], ah[3], ad);
                LDMX4(al[0], al[1], al[2], al[3], ad + (SM_QL - SM_QH));
#pragma unroll
                for (int nf = 0; nf < 8; nf++) {
                    MMA_F16(s[nf], ah, bh[nf][2 * ks], bh[nf][2 * ks + 1]);
                    MMA_F16(s[nf], al, bh[nf][2 * ks], bh[nf][2 * ks + 1]);
                }
            }
        }

        // ---- scale + causal mask + tile row max
        const int kvb = j * 64;
        float tm0 = -1e30f, tm1 = -1e30f;
#pragma unroll
        for (int nf = 0; nf < 8; nf++) {
            int c0 = kvb + nf * 8 + lc * 2;
            float v0 = s[nf][0] * SCALE; if (c0 > r0g)     v0 = -1e30f;
            float v1 = s[nf][1] * SCALE; if (c0 + 1 > r0g) v1 = -1e30f;
            float v2 = s[nf][2] * SCALE; if (c0 > r1g)     v2 = -1e30f;
            float v3 = s[nf][3] * SCALE; if (c0 + 1 > r1g) v3 = -1e30f;
            s[nf][0] = v0; s[nf][1] = v1; s[nf][2] = v2; s[nf][3] = v3;
            tm0 = fmaxf(tm0, fmaxf(v0, v1));
            tm1 = fmaxf(tm1, fmaxf(v2, v3));
        }
        tm0 = fmaxf(tm0, __shfl_xor_sync(0xffffffffu, tm0, 1));
        tm0 = fmaxf(tm0, __shfl_xor_sync(0xffffffffu, tm0, 2));
        tm1 = fmaxf(tm1, __shfl_xor_sync(0xffffffffu, tm1, 1));
        tm1 = fmaxf(tm1, __shfl_xor_sync(0xffffffffu, tm1, 2));

        const float mn0 = fmaxf(m0, tm0), mn1 = fmaxf(m1, tm1);
        const float f0 = __expf(m0 - mn0), f1 = __expf(m1 - mn1);
        m0 = mn0; m1 = mn1;
        l0 *= f0; l1 *= f1;
#pragma unroll
        for (int of = 0; of < 16; of++) {
            o[of][0] *= f0; o[of][1] *= f0; o[of][2] *= f1; o[of][3] *= f1;
        }
#pragma unroll
        for (int nf = 0; nf < 8; nf++) {
            float p0 = __expf(s[nf][0] - mn0), p1 = __expf(s[nf][1] - mn0);
            float p2 = __expf(s[nf][2] - mn1), p3 = __expf(s[nf][3] - mn1);
            l0 += p0 + p1; l1 += p2 + p3;
            s[nf][0] = p0; s[nf][1] = p1; s[nf][2] = p2; s[nf][3] = p3;
        }
        // C-accumulator layout repacks directly into A m16k16 fragments
        uint32_t pf[4][4];
#pragma unroll
        for (int t = 0; t < 4; t++) {
            pf[t][0] = h2_pack(s[2 * t][0],     s[2 * t][1]);
            pf[t][1] = h2_pack(s[2 * t][2],     s[2 * t][3]);
            pf[t][2] = h2_pack(s[2 * t + 1][0], s[2 * t + 1][1]);
            pf[t][3] = h2_pack(s[2 * t + 1][2], s[2 * t + 1][3]);
        }

        // ---- PV: o += P @ V  (V^T tile in smem, K-major over kv)
#pragma unroll
        for (int og = 0; og < 4; og++) {
            uint32_t bv[4][8];
#pragma unroll
            for (int k = 0; k < 4; k++) {
                int n = (og * 4 + k) * 8 + (lane & 7);
                LDMX4(bv[k][0], bv[k][1], bv[k][2], bv[k][3],
                      vb + n * VSTR + (lane >> 3) * 16);
                LDMX4(bv[k][4], bv[k][5], bv[k][6], bv[k][7],
                      vb + n * VSTR + 64 + (lane >> 3) * 16);
            }
#pragma unroll
            for (int t = 0; t < 4; t++)
#pragma unroll
                for (int k = 0; k < 4; k++)
                    MMA_F16(o[og * 4 + k], pf[t], bv[k][2 * t], bv[k][2 * t + 1]);
        }
    }

    // ---- finalize: divide by row sums, write pv16
    l0 += __shfl_xor_sync(0xffffffffu, l0, 1);
    l0 += __shfl_xor_sync(0xffffffffu, l0, 2);
    l1 += __shfl_xor_sync(0xffffffffu, l1, 1);
    l1 += __shfl_xor_sync(0xffffffffu, l1, 2);
    const float i0 = 1.f / l0, i1 = 1.f / l1;
#pragma unroll
    for (int of = 0; of < 16; of++) {
        long long c = h * VH + of * 8 + lc * 2;
        *(uint32_t*)(g_pv16 + (long long)r0g * (H * VH) + c) =
            h2_pack(o[of][0] * i0, o[of][1] * i0);
        *(uint32_t*)(g_pv16 + (long long)r1g * (H * VH) + c) =
            h2_pack(o[of][2] * i1, o[of][3] * i1);
    }
}

// ---------------- fp32 -> fp16 single (elementwise) ----------------------------
__global__ void __launch_bounds__(256)
half_kernel(const float* __restrict__ in, u16* __restrict__ o, long long n)
{
    long long i = ((long long)blockIdx.x * 256 + threadIdx.x) * 4;
    if (i >= n) return;
    float4 v = *(const float4*)(in + i);
    *(uint32_t*)(o + i) = h2_pack(v.x, v.y);
    *(uint32_t*)(o + i + 2) = h2_pack(v.z, v.w);
}

// ---------------- fp32 transpose -> fp16 single --------------------------------
__global__ void __launch_bounds__(256)
transpose_half_kernel(const float* __restrict__ in, u16* __restrict__ out,
                      int ldin, int ldout, long long sIn, long long sOut)
{
    __shared__ float t[32][33];
    const float* ip = in + blockIdx.z * sIn;
    const int c0 = blockIdx.x * 32, r0 = blockIdx.y * 32;
#pragma unroll
    for (int i = 0; i < 4; i++) {
        int r = threadIdx.y + i * 8;
        t[r][threadIdx.x] = ip[(long long)(r0 + r) * ldin + c0 + threadIdx.x];
    }
    __syncthreads();
#pragma unroll
    for (int i = 0; i < 4; i++) {
        int c = threadIdx.y + i * 8;
        long long o = blockIdx.z * sOut + (long long)(c0 + c) * ldout + r0 + threadIdx.x;
        out[o] = h16_bits(t[threadIdx.x][c]);
    }
}

// ---------------- rmsnorm(latent) + RoPE ---------------------------------------
__global__ void __launch_bounds__(256)
prep_kernel(const float* __restrict__ cosp, const float* __restrict__ sinp,
            const float* __restrict__ normw)
{
    const int s = blockIdx.x;
    const int tid = threadIdx.x;
    const float* kv = g_kv + (long long)s * D;

    float ss = 0.f;
    for (int i = tid; i < KVR; i += 256) { float v = kv[i]; ss += v * v; }
    __shared__ float red[32];
#pragma unroll
    for (int o = 16; o > 0; o >>= 1) ss += __shfl_xor_sync(0xffffffffu, ss, o);
    if ((tid & 31) == 0) red[tid >> 5] = ss;
    __syncthreads();
    if (tid < 32) {
        float v = (tid < 8) ? red[tid] : 0.f;
#pragma unroll
        for (int o = 16; o > 0; o >>= 1) v += __shfl_xor_sync(0xffffffffu, v, o);
        if (tid == 0) red[0] = v;
    }
    __syncthreads();
    const float r = rsqrtf(red[0] / (float)KVR + EPS);

    for (int i = tid; i < KVR; i += 256)
        g_lat16[(long long)s * KVR + i] = h16_bits(kv[i] * r * normw[i]);

    const float* cs = cosp + (long long)s * ROPE;
    const float* sn = sinp + (long long)s * ROPE;

    __shared__ u16 kpe[ROPE];
    for (int i = tid; i < ROPE; i += 256) {
        float v = kv[KVR + i];
        float rot = (i < 32) ? -kv[KVR + i + 32] : kv[KVR + i - 32];
        kpe[i] = h16_bits(v * cs[i] + rot * sn[i]);
    }
    __syncthreads();
    for (int idx = tid; idx < H * ROPE; idx += 256) {
        int h = idx >> 6, i = idx & 63;
        g_kf2[(long long)h * S * D2 + (long long)s * D2 + NOPE + i] = kpe[i];
    }

    float wv[(H * ROPE) / 256];
#pragma unroll
    for (int it = 0; it < (H * ROPE) / 256; it++) {
        int idx = tid + it * 256;
        int h = idx >> 6, i = idx & 63;
        long long base = (long long)s * (H * QD) + h * QD + NOPE;
        float v = h16_val(g_qh[base + i]) + h16_val(g_ql[base + i]);
        float ro = (i < 32)
            ? -(h16_val(g_qh[base + i + 32]) + h16_val(g_ql[base + i + 32]))
            :  (h16_val(g_qh[base + i - 32]) + h16_val(g_ql[base + i - 32]));
        wv[it] = v * cs[i] + ro * sn[i];
    }
    __syncthreads();
#pragma unroll
    for (int it = 0; it < (H * ROPE) / 256; it++) {
        int idx = tid + it * 256;
        int h = idx >> 6, i = idx & 63;
        long long base = (long long)s * (H * QD) + h * QD + NOPE;
        u16 hb = h16_bits(wv[it]);
        g_qh[base + i] = hb;
        g_ql[base + i] = h16_bits(wv[it] - h16_val(hb));
    }
}

// ---------------- stream/event helpers (created once, outside capture) ---------
static cudaStream_t make_stream() {
    cudaStream_t s; cudaStreamCreateWithFlags(&s, cudaStreamNonBlocking); return s;
}
static cudaEvent_t make_event() {
    cudaEvent_t e; cudaEventCreateWithFlags(&e, cudaEventDisableTiming); return e;
}

// ---------------- launch --------------------------------------------------------
extern "C" void kernel_launch(void* const* d_in, const int* in_sizes, int n_in,
                              void* d_out, int out_size)
{
    (void)in_sizes; (void)n_in; (void)out_size;
    const float* x      = (const float*)d_in[0];
    const float* cosp   = (const float*)d_in[1];
    const float* sinp   = (const float*)d_in[2];
    const float* w_q    = (const float*)d_in[3];
    const float* w_kv_a = (const float*)d_in[4];
    const float* normw  = (const float*)d_in[5];
    const float* kc     = (const float*)d_in[6];
    const float* vc     = (const float*)d_in[7];
    const float* w_o    = (const float*)d_in[8];
    float* out = (float*)d_out;

    float *kv;
    u16 *x16, *qh, *ql, *lat16, *kc16, *kf2, *vT16, *pv16;
    u16 *wqT16, *wkvaT16, *vcT16, *woT16;
    cudaGetSymbolAddress((void**)&kv, g_kv);
    cudaGetSymbolAddress((void**)&x16, g_x16);
    cudaGetSymbolAddress((void**)&qh, g_qh);     cudaGetSymbolAddress((void**)&ql, g_ql);
    cudaGetSymbolAddress((void**)&lat16, g_lat16);
    cudaGetSymbolAddress((void**)&kc16, g_kc16);
    cudaGetSymbolAddress((void**)&kf2, g_kf2);
    cudaGetSymbolAddress((void**)&vT16, g_vT16);
    cudaGetSymbolAddress((void**)&pv16, g_pv16);
    cudaGetSymbolAddress((void**)&wqT16, g_wqT16);
    cudaGetSymbolAddress((void**)&wkvaT16, g_wkvaT16);
    cudaGetSymbolAddress((void**)&vcT16, g_vcT16);
    cudaGetSymbolAddress((void**)&woT16, g_woT16);

    const int SM_M1_128 = 2 * (10240 + 128 * 80);  // 40960
    const int SM_M1_64  = 2 * (10240 + 64 * 80);   // 30720
    cudaFuncSetAttribute(mma_gemm<128, 1, 0>, cudaFuncAttributeMaxDynamicSharedMemorySize, SM_M1_128);
    cudaFuncSetAttribute(mma_gemm<128, 1, 1>, cudaFuncAttributeMaxDynamicSharedMemorySize, SM_M1_128);
    cudaFuncSetAttribute(mma_gemm<128, 1, 4>, cudaFuncAttributeMaxDynamicSharedMemorySize, SM_M1_128);
    cudaFuncSetAttribute(mma_gemm<64, 1, 0>,  cudaFuncAttributeMaxDynamicSharedMemorySize, SM_M1_64);
    cudaFuncSetAttribute(fused_attn_kernel,   cudaFuncAttributeMaxDynamicSharedMemorySize, SM_FUSED);

    static cudaStream_t s1 = make_stream();
    static cudaStream_t s2 = make_stream();
    static cudaEvent_t eA = make_event();
    static cudaEvent_t e2 = make_event();
    static cudaEvent_t e3 = make_event();
    static cudaEvent_t eP = make_event();
    static cudaEvent_t eV = make_event();

    dim3 tb(32, 8);

    // ---- fork: side stream weight prep
    cudaEventRecord(eA, 0);
    cudaStreamWaitEvent(s1, eA, 0);
    transpose_half_kernel<<<dim3(D / 32, HID / 32, 1), tb, 0, s1>>>(
        w_kv_a, wkvaT16, D, HID, 0, 0);
    cudaEventRecord(e2, s1);
    transpose_half_kernel<<<dim3(VH / 32, KVR / 32, H), tb, 0, s1>>>(
        vc, vcT16, VH, KVR, (long long)KVR * VH, (long long)KVR * VH);
    half_kernel<<<(H * NOPE * KVR) / 1024, 256, 0, s1>>>(kc, kc16, (long long)H * NOPE * KVR);
    transpose_half_kernel<<<dim3(HID / 32, (H * VH) / 32, 1), tb, 0, s1>>>(
        w_o, woT16, HID, H * VH, 0, 0);
    cudaEventRecord(e3, s1);

    // ---- main: x conversion + q projection
    half_kernel<<<(S * HID) / 1024, 256>>>(x, x16, (long long)S * HID);
    transpose_half_kernel<<<dim3((H * QD) / 32, HID / 32, 1), tb>>>(w_q, wqT16, H * QD, HID, 0, 0);
    mma_gemm<128, 1, 1><<<dim3((H * QD) / 128, S / 128, 1), 256, SM_M1_128>>>(
        x16, nullptr, wqT16, nullptr, qh, ql, HID, HID, HID, H * QD, 0, 0, 0, 1.0f, 0);

    cudaStreamWaitEvent(0, e2, 0);
    mma_gemm<64, 1, 0><<<dim3(D / 64, S / 128, 1), 256, SM_M1_64>>>(
        x16, nullptr, wkvaT16, kv, nullptr, nullptr, HID, HID, HID, D, 0, 0, 0, 1.0f, 0);

    prep_kernel<<<S, 256>>>(cosp, sinp, normw);
    cudaEventRecord(eP, 0);

    cudaStreamWaitEvent(0, e3, 0);

    // vT on s2, concurrent with k_nope on main
    cudaStreamWaitEvent(s2, eP, 0);
    cudaStreamWaitEvent(s2, e3, 0);
    mma_gemm<128, 1, 4><<<dim3(S / 128, 1, H), 256, SM_M1_128, s2>>>(
        vcT16, nullptr, lat16, nullptr, vT16, nullptr, KVR, KVR, KVR, S,
        (long long)VH * KVR, 0LL, (long long)VH * S, 1.0f, 0);
    cudaEventRecord(eV, s2);

    // k_nope[h] = latent @ kc[h]^T -> kf2[h][:, 0:128]
    mma_gemm<128, 1, 4><<<dim3(1, S / 128, H), 256, SM_M1_128>>>(
        lat16, nullptr, kc16, nullptr, kf2, nullptr, KVR, KVR, KVR, D2,
        0LL, (long long)NOPE * KVR, (long long)S * D2, 1.0f, 0);

    // fused flash attention (needs kf2, vT, qh/ql)
    cudaStreamWaitEvent(0, eV, 0);
    fused_attn_kernel<<<dim3(H, S / 128), 256, SM_FUSED>>>();

    // out = pv @ w_o  (single-A, fp32 final)
    mma_gemm<128, 1, 0><<<dim3(HID / 128, S / 128, 1), 256, SM_M1_128>>>(
        pv16, nullptr, woT16, out, nullptr, nullptr, H * VH, H * VH, H * VH, HID,
        0, 0, 0, 1.0f, 0);
}